// round 10
// baseline (speedup 1.0000x reference)
#include <cuda_runtime.h>
#include <cuda_fp16.h>
#include <math.h>
#include <stdint.h>

#define LL 160
#define BB 16
#define EE 512
#define CC 256
#define HH 512
#define DM 128
#define DO 512
#define TOK (BB*LL)
#define CP 258
#define W1C 1028
#define KC (3*EE)            /* 1536 */
#define SPB 9
#define GRID_PAIRS (BB*SPB)  /* 144 */
#define NKT (KC/16)          /* 96 */
#define NCB 80               /* conv blocks = stats partial rows */

__device__ __half g_whfrag[NKT*32*32*4];
__device__ float g_W1T[CP*256];
__device__ float g_y[TOK*CC];
__device__ float g_ssum[NCB*256];
__device__ float g_ssq[NCB*256];
__device__ float g_u[TOK*DM];
__device__ float g_v[TOK*DM];
__device__ float g_hw[BB*DM];
__device__ float g_part[BB*SPB*DM];

__device__ __forceinline__ float lrelu(float x){ return x > 0.f ? x : 0.1f*x; }

__device__ __forceinline__ uint32_t h2pack(float lo, float hi){
    __half2 h = __floats2half2_rn(lo, hi);
    return *(uint32_t*)&h;
}
__device__ __forceinline__ void mma_f16(float& d0, float& d1, float& d2, float& d3,
                                        uint32_t a0, uint32_t a1, uint32_t a2, uint32_t a3,
                                        uint32_t b0, uint32_t b1){
    asm volatile("mma.sync.aligned.m16n8k16.row.col.f32.f16.f16.f32 "
                 "{%0,%1,%2,%3},{%4,%5,%6,%7},{%8,%9},{%0,%1,%2,%3};"
                 : "+f"(d0), "+f"(d1), "+f"(d2), "+f"(d3)
                 : "r"(a0), "r"(a1), "r"(a2), "r"(a3), "r"(b0), "r"(b1));
}

/* ---------------- 1. prep (+ fused h-projection in blocks 0..15) ------------ */
__global__ void k_prep(const float* __restrict__ conv_w, const float* __restrict__ W1,
                       const float* __restrict__ h){
    __shared__ float hs[HH];
    __shared__ float hp[256];
    int tid = threadIdx.x;
    int idx = blockIdx.x*256 + tid;
    if (idx < KC*CC){
        int k = idx >> 8, n = idx & 255;
        int e = k & 511, kk = k >> 9;
        float v = conv_w[n*KC + e*3 + kk];
        int kt = k >> 4, r = k & 15;
        int nt = n >> 3, gg = n & 7, c = (r & 7) >> 1;
        int lane = gg*4 + c;
        int hsl = ((r >> 3) << 1) | (r & 1);
        g_whfrag[(((kt*32 + nt)*32 + lane) << 2) + hsl] = __float2half(v);
    }
    if (idx < CP*256){
        int k = idx >> 8, n = idx & 255;
        g_W1T[idx] = (n < DM) ? W1[n*W1C + k] : W1[(n-DM)*W1C + CP + k];
    }
    if (blockIdx.x < BB){
        int b = blockIdx.x;
        for (int i = tid; i < HH; i += 256) hs[i] = h[b*HH + i];
        __syncthreads();
        int d = tid & 127, half = tid >> 7;
        const float* w = W1 + d*W1C + 2*CP + half*256;
        float acc = 0.f;
        #pragma unroll 8
        for (int c = 0; c < 256; c++) acc += hs[half*256 + c]*w[c];
        hp[tid] = acc;
        __syncthreads();
        if (tid < 128) g_hw[b*DM + tid] = hp[tid] + hp[tid + 128];
    }
}

/* ---------------- 2. conv1d fp16 mma GEMM, M=32/block, fused BN partials ----
   grid (5, BB); xh: 34 rows x 260 u32; wfr: 3072 uint2; stats via shfl.     */
#define DYN_CONV (34*260*4 + 3072*8)
__global__ void __launch_bounds__(256,1) k_conv(const float* __restrict__ x,
                                                const float* __restrict__ conv_b){
    extern __shared__ float csm[];
    uint32_t* xh32 = (uint32_t*)csm;
    uint2*    wfr  = (uint2*)(csm + 34*260);
    int l0 = blockIdx.x*32, b = blockIdx.y;
    int tid = threadIdx.x, w = tid >> 5, t = tid & 31;
    int g = t >> 2, c = t & 3;

    for (int idx = tid; idx < 34*256; idx += 256){
        int r = idx >> 8, i = idx & 255;
        int l = l0 + r - 1;
        uint32_t pv = 0u;
        if (l >= 0 && l < LL){
            const float2 xv = *(const float2*)(x + (l*BB + b)*EE + 2*i);
            pv = h2pack(xv.x, xv.y);
        }
        xh32[r*260 + i] = pv;
    }

    float d[2][4][4];
    #pragma unroll
    for (int mt = 0; mt < 2; mt++)
        #pragma unroll
        for (int j = 0; j < 4; j++){
            d[mt][j][0]=0.f; d[mt][j][1]=0.f; d[mt][j][2]=0.f; d[mt][j][3]=0.f;
        }

    const uint2* gsrc = (const uint2*)g_whfrag;
    for (int cc = 0; cc < 32; cc++){
        __syncthreads();
        const uint2* src = gsrc + cc*3072;
        #pragma unroll
        for (int q = 0; q < 12; q++) wfr[tid + q*256] = src[tid + q*256];
        __syncthreads();
        #pragma unroll
        for (int kt = 0; kt < 3; kt++){
            int k = cc*48 + kt*16;
            int kk = k >> 9, e2 = (k & 511) >> 1;
            uint32_t a[2][4];
            #pragma unroll
            for (int mt = 0; mt < 2; mt++){
                const uint32_t* r0 = xh32 + (mt*16 + g + kk)*260 + e2 + c;
                const uint32_t* r1 = xh32 + (mt*16 + g + 8 + kk)*260 + e2 + c;
                a[mt][0] = r0[0]; a[mt][1] = r1[0]; a[mt][2] = r0[4]; a[mt][3] = r1[4];
            }
            const uint2* wk = wfr + (kt*32 + w*4)*32 + t;
            #pragma unroll
            for (int j = 0; j < 4; j++){
                uint2 bb = wk[j*32];
                mma_f16(d[0][j][0], d[0][j][1], d[0][j][2], d[0][j][3],
                        a[0][0], a[0][1], a[0][2], a[0][3], bb.x, bb.y);
                mma_f16(d[1][j][0], d[1][j][1], d[1][j][2], d[1][j][3],
                        a[1][0], a[1][1], a[1][2], a[1][3], bb.x, bb.y);
            }
        }
    }

    /* epilogue: write y, accumulate per-channel partial sums over 32 tokens */
    float s[4][2], sq[4][2];
    #pragma unroll
    for (int j = 0; j < 4; j++){ s[j][0]=0.f; s[j][1]=0.f; sq[j][0]=0.f; sq[j][1]=0.f; }
    #pragma unroll
    for (int mt = 0; mt < 2; mt++){
        #pragma unroll
        for (int j = 0; j < 4; j++){
            int n = w*32 + j*8 + 2*c;
            float bx = conv_b[n], by = conv_b[n+1];
            float y0 = lrelu(d[mt][j][0] + bx);
            float y1 = lrelu(d[mt][j][1] + by);
            float y2 = lrelu(d[mt][j][2] + bx);
            float y3 = lrelu(d[mt][j][3] + by);
            int trow = (b*LL + l0 + mt*16 + g)*CC;
            g_y[trow + n]            = y0;
            g_y[trow + n + 1]        = y1;
            g_y[trow + 8*CC + n]     = y2;
            g_y[trow + 8*CC + n + 1] = y3;
            s[j][0]  += y0 + y2;         s[j][1]  += y1 + y3;
            sq[j][0] += y0*y0 + y2*y2;   sq[j][1] += y1*y1 + y3*y3;
        }
    }
    #pragma unroll
    for (int j = 0; j < 4; j++)
        #pragma unroll
        for (int r = 0; r < 2; r++){
            #pragma unroll
            for (int m = 4; m < 32; m <<= 1){
                s[j][r]  += __shfl_xor_sync(0xffffffffu, s[j][r],  m);
                sq[j][r] += __shfl_xor_sync(0xffffffffu, sq[j][r], m);
            }
        }
    if (t < 4){
        int blk = blockIdx.y*5 + blockIdx.x;
        #pragma unroll
        for (int j = 0; j < 4; j++){
            int n = w*32 + j*8 + 2*c;
            g_ssum[blk*256 + n]     = s[j][0];
            g_ssum[blk*256 + n + 1] = s[j][1];
            g_ssq[blk*256 + n]      = sq[j][0];
            g_ssq[blk*256 + n + 1]  = sq[j][1];
        }
    }
}

/* ---------------- 3. uv projection, fused BN finalize, 32 tokens/block ------ */
__global__ void __launch_bounds__(256,1) k_uv(const float* __restrict__ bn_g,
                                              const float* __restrict__ bn_b){
    __shared__ float sc_s[256], sh_s[256];
    __shared__ float xf[32*260];
    int t0 = blockIdx.x*32;
    int b = t0 / LL;
    int tid = threadIdx.x;

    {   /* finalize BN stats (redundant per block; partials are L2-resident) */
        float a = 0.f, q = 0.f;
        #pragma unroll 8
        for (int r = 0; r < NCB; r++){
            a += g_ssum[r*256 + tid];
            q += g_ssq[r*256 + tid];
        }
        float mu = a/(float)TOK;
        float var = q/(float)TOK - mu*mu;
        float sc = bn_g[tid]*rsqrtf(var + 1e-5f);
        sc_s[tid] = sc;
        sh_s[tid] = bn_b[tid] - mu*sc;
    }
    __syncthreads();

    for (int idx = tid; idx < 32*CC; idx += 256){
        int tok = idx >> 8, c = idx & 255;
        xf[tok*260 + c] = g_y[(t0+tok)*CC + c]*sc_s[c] + sh_s[c];
    }
    if (tid < 64){
        int tok = tid >> 1;
        float fi = (float)(t0 + tok - b*LL);
        float sL = sqrtf(160.f);
        float cv = (tid & 1) ? (fmodf(fi, sL) - 2.f)*0.5f : (fi/sL - 2.f)*0.5f;
        xf[tok*260 + 256 + (tid & 1)] = cv;
    }
    __syncthreads();

    int n = tid;
    float acc[32];
    #pragma unroll
    for (int i = 0; i < 32; i++) acc[i] = 0.f;
    #pragma unroll 2
    for (int k = 0; k < CP; k++){
        float w = g_W1T[k*256 + n];
        #pragma unroll
        for (int tok = 0; tok < 32; tok++) acc[tok] += xf[tok*260 + k]*w;
    }
    if (n < DM){
        #pragma unroll
        for (int tok = 0; tok < 32; tok++) g_u[(t0+tok)*DM + n] = acc[tok];
    } else {
        float hw = g_hw[b*DM + n - DM];
        #pragma unroll
        for (int tok = 0; tok < 32; tok++) g_v[(t0+tok)*DM + n - DM] = acc[tok] + hw;
    }
}

/* ---------------- 4. pair MLP (unchanged from R9; now the profiled launch) -- */
#define SM_U     24576
#define SM_V     (SM_U + 16*132)
#define SM_B1    (SM_V + 16*132)
#define SM_BIAS  (SM_B1 + 128)
#define SM_TOTF  (SM_BIAS + 384)
#define DYN_SMEM (SM_TOTF*4)

__global__ void __launch_bounds__(256,1) k_pairs_mma(
        const float* __restrict__ W2, const float* __restrict__ W3, const float* __restrict__ W4,
        const float* __restrict__ b1, const float* __restrict__ b2,
        const float* __restrict__ b3, const float* __restrict__ b4){
    extern __shared__ float smf[];
    float* u_s    = smf + SM_U;
    float* v_s    = smf + SM_V;
    float* b1_s   = smf + SM_B1;
    float* bias_s = smf + SM_BIAS;
    float* part_s = smf + SM_U;
    uint2* wfrag  = (uint2*)smf;

    int tid = threadIdx.x, w = tid >> 5, t = tid & 31;
    int g = t >> 2, c = t & 3;

    for (int l = 0; l < 3; l++){
        const float* W = (l == 0) ? W2 : (l == 1) ? W3 : W4;
        for (int idx = tid; idx < 4096; idx += 256){
            int lane = idx & 31, nt = (idx >> 5) & 15, kt = idx >> 9;
            int gg = lane >> 2, cc = lane & 3;
            const float* Wr = W + (nt*8 + gg)*DM + kt*16 + 2*cc;
            uint2 fr;
            fr.x = h2pack(Wr[0], Wr[1]);
            fr.y = h2pack(Wr[8], Wr[9]);
            wfrag[l*4096 + idx] = fr;
        }
    }
    for (int i = tid; i < 128; i += 256){
        b1_s[i]          = b1[i];
        bias_s[i]        = b2[i];
        bias_s[128 + i]  = b3[i];
        bias_s[256 + i]  = b4[i];
    }

    int cta = blockIdx.x;
    int b = cta / SPB, s = cta % SPB;
    int t0 = s*11 + (s > 0 ? 1 : 0);
    int t1 = t0 + 11 + (s == 0 ? 1 : 0);

    uint32_t a[2][8][4];
    uint32_t an[2][4][4];
    float    d[2][8][4];
    float    acc32[16][2];
    #pragma unroll
    for (int nt = 0; nt < 16; nt++){ acc32[nt][0] = 0.f; acc32[nt][1] = 0.f; }

    for (int tt = t0; tt < t1; tt++){
        int lt0 = (tt / 10)*16, m0 = (tt % 10)*16;
        __syncthreads();
        for (int idx = tid; idx < 16*DM; idx += 256){
            int mi = idx >> 7, k = idx & 127;
            u_s[mi*132 + k] = g_u[(b*LL + m0 + mi)*DM + k];
        }
        for (int idx = tid; idx < 16*DM; idx += 256){
            int li = idx >> 7, k = idx & 127;
            v_s[li*132 + k] = g_v[(b*LL + lt0 + li)*DM + k];
        }
        __syncthreads();

        #pragma unroll
        for (int f = 0; f < 2; f++){
            const float* vrow = v_s + (w + 8*f)*132;
            #pragma unroll
            for (int kt = 0; kt < 8; kt++){
                int k = kt*16 + 2*c;
                const float* vr = vrow + k;
                const float* br = b1_s + k;
                float vb0 = vr[0] + br[0], vb1 = vr[1] + br[1];
                float vb8 = vr[8] + br[8], vb9 = vr[9] + br[9];
                const float* ug = u_s + g*132 + k;
                const float* uh = u_s + (g+8)*132 + k;
                a[f][kt][0] = h2pack(lrelu(ug[0] + vb0), lrelu(ug[1] + vb1));
                a[f][kt][1] = h2pack(lrelu(uh[0] + vb0), lrelu(uh[1] + vb1));
                a[f][kt][2] = h2pack(lrelu(ug[8] + vb8), lrelu(ug[9] + vb9));
                a[f][kt][3] = h2pack(lrelu(uh[8] + vb8), lrelu(uh[9] + vb9));
            }
        }

        #pragma unroll 1
        for (int l = 0; l < 3; l++){
            #pragma unroll
            for (int h = 0; h < 2; h++){
                #pragma unroll
                for (int ntl = 0; ntl < 8; ntl++){
                    d[0][ntl][0]=0.f; d[0][ntl][1]=0.f; d[0][ntl][2]=0.f; d[0][ntl][3]=0.f;
                    d[1][ntl][0]=0.f; d[1][ntl][1]=0.f; d[1][ntl][2]=0.f; d[1][ntl][3]=0.f;
                }
                const uint2* wl = wfrag + l*4096 + h*256 + t;
                #pragma unroll
                for (int kt = 0; kt < 8; kt++){
                    const uint2* wk = wl + kt*512;
                    #pragma unroll
                    for (int ntl = 0; ntl < 8; ntl++){
                        uint2 bb = wk[ntl*32];
                        mma_f16(d[0][ntl][0], d[0][ntl][1], d[0][ntl][2], d[0][ntl][3],
                                a[0][kt][0], a[0][kt][1], a[0][kt][2], a[0][kt][3], bb.x, bb.y);
                        mma_f16(d[1][ntl][0], d[1][ntl][1], d[1][ntl][2], d[1][ntl][3],
                                a[1][kt][0], a[1][kt][1], a[1][kt][2], a[1][kt][3], bb.x, bb.y);
                    }
                }
                if (l < 2){
                    const float* bl = bias_s + l*128 + h*64;
                    #pragma unroll
                    for (int f = 0; f < 2; f++){
                        #pragma unroll
                        for (int ktl = 0; ktl < 4; ktl++){
                            float bx0 = bl[ktl*16 + 2*c],     by0 = bl[ktl*16 + 2*c + 1];
                            float bx8 = bl[ktl*16 + 2*c + 8], by8 = bl[ktl*16 + 2*c + 9];
                            uint32_t u0 = h2pack(lrelu(d[f][2*ktl][0]   + bx0), lrelu(d[f][2*ktl][1]   + by0));
                            uint32_t u1 = h2pack(lrelu(d[f][2*ktl][2]   + bx0), lrelu(d[f][2*ktl][3]   + by0));
                            uint32_t u2 = h2pack(lrelu(d[f][2*ktl+1][0] + bx8), lrelu(d[f][2*ktl+1][1] + by8));
                            uint32_t u3 = h2pack(lrelu(d[f][2*ktl+1][2] + bx8), lrelu(d[f][2*ktl+1][3] + by8));
                            if (h == 0){
                                an[f][ktl][0]=u0; an[f][ktl][1]=u1; an[f][ktl][2]=u2; an[f][ktl][3]=u3;
                            } else {
                                a[f][4+ktl][0]=u0; a[f][4+ktl][1]=u1; a[f][4+ktl][2]=u2; a[f][4+ktl][3]=u3;
                            }
                        }
                    }
                    if (h == 1){
                        #pragma unroll
                        for (int f = 0; f < 2; f++)
                            #pragma unroll
                            for (int ktl = 0; ktl < 4; ktl++){
                                a[f][ktl][0]=an[f][ktl][0]; a[f][ktl][1]=an[f][ktl][1];
                                a[f][ktl][2]=an[f][ktl][2]; a[f][ktl][3]=an[f][ktl][3];
                            }
                    }
                } else {
                    const float* bl = bias_s + 256 + h*64;
                    #pragma unroll
                    for (int ntl = 0; ntl < 8; ntl++){
                        int nt = 8*h + ntl;
                        float bx = bl[ntl*8 + 2*c], by = bl[ntl*8 + 2*c + 1];
                        acc32[nt][0] += lrelu(d[0][ntl][0] + bx) + lrelu(d[0][ntl][2] + bx)
                                      + lrelu(d[1][ntl][0] + bx) + lrelu(d[1][ntl][2] + bx);
                        acc32[nt][1] += lrelu(d[0][ntl][1] + by) + lrelu(d[0][ntl][3] + by)
                                      + lrelu(d[1][ntl][1] + by) + lrelu(d[1][ntl][3] + by);
                    }
                }
            }
        }
    }

    __syncthreads();

    #pragma unroll
    for (int nt = 0; nt < 16; nt++){
        #pragma unroll
        for (int r = 0; r < 2; r++){
            float v = acc32[nt][r];
            v += __shfl_xor_sync(0xffffffffu, v, 4);
            v += __shfl_xor_sync(0xffffffffu, v, 8);
            v += __shfl_xor_sync(0xffffffffu, v, 16);
            acc32[nt][r] = v;
        }
    }
    if (g == 0){
        #pragma unroll
        for (int nt = 0; nt < 16; nt++){
            part_s[w*128 + nt*8 + 2*c]     = acc32[nt][0];
            part_s[w*128 + nt*8 + 2*c + 1] = acc32[nt][1];
        }
    }
    __syncthreads();
    if (tid < 128){
        float r = 0.f;
        #pragma unroll
        for (int ww = 0; ww < 8; ww++) r += part_s[ww*128 + tid];
        g_part[(b*SPB + s)*DM + tid] = r;
    }
}

/* ---------------- 5. final reduction + 2-layer head ---------------- */
__global__ void k_tail(const float* __restrict__ W5, const float* __restrict__ b5,
                       const float* __restrict__ W6, const float* __restrict__ b6,
                       float* __restrict__ out){
    __shared__ float s_s[DM], s5[DM];
    int b = blockIdx.x, tid = threadIdx.x;
    if (tid < DM){
        float a = 0.f;
        #pragma unroll
        for (int t = 0; t < SPB; t++) a += g_part[(b*SPB + t)*DM + tid];
        s_s[tid] = a;
    }
    __syncthreads();
    if (tid < DM){
        float a = 0.f;
        const float* w = W5 + tid*DM;
        #pragma unroll 8
        for (int k = 0; k < DM; k++) a += s_s[k]*w[k];
        s5[tid] = lrelu(a + b5[tid]);
    }
    __syncthreads();
    {
        float a = 0.f;
        const float* w = W6 + tid*DM;
        #pragma unroll 8
        for (int k = 0; k < DM; k++) a += s5[k]*w[k];
        out[b*DO + tid] = lrelu(a + b6[tid]);
    }
}

extern "C" void kernel_launch(void* const* d_in, const int* in_sizes, int n_in,
                              void* d_out, int out_size){
    const float* x      = (const float*)d_in[0];
    const float* h      = (const float*)d_in[1];
    const float* conv_w = (const float*)d_in[2];
    const float* conv_b = (const float*)d_in[3];
    const float* bn_g   = (const float*)d_in[4];
    const float* bn_b   = (const float*)d_in[5];
    const float* W1     = (const float*)d_in[6];
    const float* b1     = (const float*)d_in[7];
    const float* W2     = (const float*)d_in[8];
    const float* b2     = (const float*)d_in[9];
    const float* W3     = (const float*)d_in[10];
    const float* b3     = (const float*)d_in[11];
    const float* W4     = (const float*)d_in[12];
    const float* b4     = (const float*)d_in[13];
    const float* W5     = (const float*)d_in[14];
    const float* b5     = (const float*)d_in[15];
    const float* W6     = (const float*)d_in[16];
    const float* b6     = (const float*)d_in[17];
    float* out = (float*)d_out;

    cudaFuncSetAttribute(k_conv, cudaFuncAttributeMaxDynamicSharedMemorySize, DYN_CONV);
    cudaFuncSetAttribute(k_pairs_mma, cudaFuncAttributeMaxDynamicSharedMemorySize, DYN_SMEM);

    k_prep<<<(KC*CC + 255)/256, 256>>>(conv_w, W1, h);              /* 1 */
    k_conv<<<dim3(5, BB), 256, DYN_CONV>>>(x, conv_b);              /* 2 */
    k_uv<<<TOK/32, 256>>>(bn_g, bn_b);                              /* 3 */
    k_pairs_mma<<<GRID_PAIRS, 256, DYN_SMEM>>>(W2, W3, W4, b1, b2, b3, b4);  /* 4: profiled */
    k_tail<<<BB, 512>>>(W5, b5, W6, b6, out);                       /* 5 */
}

// round 11
// speedup vs baseline: 1.0129x; 1.0129x over previous
#include <cuda_runtime.h>
#include <cuda_fp16.h>
#include <math.h>
#include <stdint.h>

#define LL 160
#define BB 16
#define EE 512
#define CC 256
#define HH 512
#define DM 128
#define DO 512
#define TOK (BB*LL)
#define CP 258
#define W1C 1028
#define KC (3*EE)            /* 1536 */
#define SPB 9
#define GRID_PAIRS (BB*SPB)  /* 144 */
#define NKT (KC/16)          /* 96 */
#define NCB 160              /* conv blocks = stats partial rows */

__device__ __half  g_whfrag[NKT*32*32*4];
__device__ float    g_W1T[CP*256];
__device__ float    g_y[TOK*CC];
__device__ float    g_ssum[NCB*256];
__device__ float    g_ssq[NCB*256];
__device__ uint32_t g_uh[TOK*64];   /* u as half2 pairs (features 2p,2p+1) */
__device__ uint32_t g_vh[TOK*64];
__device__ float    g_hw[BB*DM];
__device__ float    g_part[BB*SPB*DM];

__device__ __forceinline__ float lrelu(float x){ return fmaxf(x, 0.1f*x); }

__device__ __forceinline__ uint32_t h2pack(float lo, float hi){
    __half2 h = __floats2half2_rn(lo, hi);
    return *(uint32_t*)&h;
}
__device__ __forceinline__ uint32_t hadd2_(uint32_t a, uint32_t b){
    uint32_t d; asm("add.f16x2 %0,%1,%2;" : "=r"(d) : "r"(a), "r"(b)); return d;
}
__device__ __forceinline__ uint32_t lrelu2_(uint32_t x){
    uint32_t t, d;
    asm("mul.f16x2 %0,%1,%2;" : "=r"(t) : "r"(x), "r"(0x2E662E66u));  /* 0.1 in fp16 */
    asm("max.f16x2 %0,%1,%2;" : "=r"(d) : "r"(x), "r"(t));
    return d;
}
__device__ __forceinline__ void mma_f16(float& d0, float& d1, float& d2, float& d3,
                                        uint32_t a0, uint32_t a1, uint32_t a2, uint32_t a3,
                                        uint32_t b0, uint32_t b1){
    asm volatile("mma.sync.aligned.m16n8k16.row.col.f32.f16.f16.f32 "
                 "{%0,%1,%2,%3},{%4,%5,%6,%7},{%8,%9},{%0,%1,%2,%3};"
                 : "+f"(d0), "+f"(d1), "+f"(d2), "+f"(d3)
                 : "r"(a0), "r"(a1), "r"(a2), "r"(a3), "r"(b0), "r"(b1));
}

/* ---------------- 1. prep (+ fused h-projection in blocks 0..15) ------------ */
__global__ void k_prep(const float* __restrict__ conv_w, const float* __restrict__ W1,
                       const float* __restrict__ h){
    __shared__ float hs[HH];
    __shared__ float hp[256];
    int tid = threadIdx.x;
    int idx = blockIdx.x*256 + tid;
    if (idx < KC*CC){
        int k = idx >> 8, n = idx & 255;
        int e = k & 511, kk = k >> 9;
        float v = conv_w[n*KC + e*3 + kk];
        int kt = k >> 4, r = k & 15;
        int nt = n >> 3, gg = n & 7, c = (r & 7) >> 1;
        int lane = gg*4 + c;
        int hsl = ((r >> 3) << 1) | (r & 1);
        g_whfrag[(((kt*32 + nt)*32 + lane) << 2) + hsl] = __float2half(v);
    }
    if (idx < CP*256){
        int k = idx >> 8, n = idx & 255;
        g_W1T[idx] = (n < DM) ? W1[n*W1C + k] : W1[(n-DM)*W1C + CP + k];
    }
    if (blockIdx.x < BB){
        int b = blockIdx.x;
        for (int i = tid; i < HH; i += 256) hs[i] = h[b*HH + i];
        __syncthreads();
        int d = tid & 127, half = tid >> 7;
        const float* w = W1 + d*W1C + 2*CP + half*256;
        float acc = 0.f;
        #pragma unroll 8
        for (int c = 0; c < 256; c++) acc += hs[half*256 + c]*w[c];
        hp[tid] = acc;
        __syncthreads();
        if (tid < 128) g_hw[b*DM + tid] = hp[tid] + hp[tid + 128];
    }
}

/* ---------------- 2. conv1d fp16 mma GEMM, M=16/block (160 blocks),
                      fused BN partial stats ---------------- */
__global__ void __launch_bounds__(256,1) k_conv(const float* __restrict__ x,
                                                const float* __restrict__ conv_b){
    __shared__ uint32_t xh32[18*260];
    __shared__ uint2 wfr[3*32*32];
    int l0 = blockIdx.x*16, b = blockIdx.y;
    int tid = threadIdx.x, w = tid >> 5, t = tid & 31;
    int g = t >> 2, c = t & 3;

    for (int idx = tid; idx < 18*256; idx += 256){
        int r = idx >> 8, i = idx & 255;
        int l = l0 + r - 1;
        uint32_t pv = 0u;
        if (l >= 0 && l < LL){
            const float2 xv = *(const float2*)(x + (l*BB + b)*EE + 2*i);
            pv = h2pack(xv.x, xv.y);
        }
        xh32[r*260 + i] = pv;
    }

    float d[4][4];
    #pragma unroll
    for (int j = 0; j < 4; j++){ d[j][0]=0.f; d[j][1]=0.f; d[j][2]=0.f; d[j][3]=0.f; }

    const uint2* gsrc = (const uint2*)g_whfrag;
    for (int cc = 0; cc < 32; cc++){
        __syncthreads();
        const uint2* src = gsrc + cc*3072;
        #pragma unroll
        for (int q = 0; q < 12; q++) wfr[tid + q*256] = src[tid + q*256];
        __syncthreads();
        #pragma unroll
        for (int kt = 0; kt < 3; kt++){
            int k = cc*48 + kt*16;
            int kk = k >> 9, e2 = (k & 511) >> 1;
            const uint32_t* r0 = xh32 + (g + kk)*260 + e2 + c;
            const uint32_t* r1 = xh32 + (g + 8 + kk)*260 + e2 + c;
            uint32_t a0 = r0[0], a1 = r1[0], a2 = r0[4], a3 = r1[4];
            const uint2* wk = wfr + (kt*32 + w*4)*32 + t;
            #pragma unroll
            for (int j = 0; j < 4; j++){
                uint2 bb = wk[j*32];
                mma_f16(d[j][0], d[j][1], d[j][2], d[j][3], a0, a1, a2, a3, bb.x, bb.y);
            }
        }
    }

    float s[4][2], sq[4][2];
    #pragma unroll
    for (int j = 0; j < 4; j++){ s[j][0]=0.f; s[j][1]=0.f; sq[j][0]=0.f; sq[j][1]=0.f; }
    #pragma unroll
    for (int j = 0; j < 4; j++){
        int n = w*32 + j*8 + 2*c;
        float bx = conv_b[n], by = conv_b[n+1];
        float y0 = lrelu(d[j][0] + bx);
        float y1 = lrelu(d[j][1] + by);
        float y2 = lrelu(d[j][2] + bx);
        float y3 = lrelu(d[j][3] + by);
        int trow = (b*LL + l0 + g)*CC;
        g_y[trow + n]            = y0;
        g_y[trow + n + 1]        = y1;
        g_y[trow + 8*CC + n]     = y2;
        g_y[trow + 8*CC + n + 1] = y3;
        s[j][0]  += y0 + y2;         s[j][1]  += y1 + y3;
        sq[j][0] += y0*y0 + y2*y2;   sq[j][1] += y1*y1 + y3*y3;
    }
    #pragma unroll
    for (int j = 0; j < 4; j++)
        #pragma unroll
        for (int r = 0; r < 2; r++){
            #pragma unroll
            for (int m = 4; m < 32; m <<= 1){
                s[j][r]  += __shfl_xor_sync(0xffffffffu, s[j][r],  m);
                sq[j][r] += __shfl_xor_sync(0xffffffffu, sq[j][r], m);
            }
        }
    if (t < 4){
        int blk = blockIdx.y*10 + blockIdx.x;
        #pragma unroll
        for (int j = 0; j < 4; j++){
            int n = w*32 + j*8 + 2*c;
            g_ssum[blk*256 + n]     = s[j][0];
            g_ssum[blk*256 + n + 1] = s[j][1];
            g_ssq[blk*256 + n]      = sq[j][0];
            g_ssq[blk*256 + n + 1]  = sq[j][1];
        }
    }
}

/* ---------------- 3. uv projection, fused BN finalize, half2 output --------- */
__global__ void __launch_bounds__(256,1) k_uv(const float* __restrict__ bn_g,
                                              const float* __restrict__ bn_b){
    __shared__ float sc_s[256], sh_s[256];
    __shared__ float xf[32*260];
    int t0 = blockIdx.x*32;
    int b = t0 / LL;
    int tid = threadIdx.x;

    {
        float a = 0.f, q = 0.f;
        #pragma unroll 8
        for (int r = 0; r < NCB; r++){
            a += g_ssum[r*256 + tid];
            q += g_ssq[r*256 + tid];
        }
        float mu = a/(float)TOK;
        float var = q/(float)TOK - mu*mu;
        float sc = bn_g[tid]*rsqrtf(var + 1e-5f);
        sc_s[tid] = sc;
        sh_s[tid] = bn_b[tid] - mu*sc;
    }
    __syncthreads();

    for (int idx = tid; idx < 32*CC; idx += 256){
        int tok = idx >> 8, c = idx & 255;
        xf[tok*260 + c] = g_y[(t0+tok)*CC + c]*sc_s[c] + sh_s[c];
    }
    if (tid < 64){
        int tok = tid >> 1;
        float fi = (float)(t0 + tok - b*LL);
        float sL = sqrtf(160.f);
        float cv = (tid & 1) ? (fmodf(fi, sL) - 2.f)*0.5f : (fi/sL - 2.f)*0.5f;
        xf[tok*260 + 256 + (tid & 1)] = cv;
    }
    __syncthreads();

    int n = tid;
    float acc[32];
    #pragma unroll
    for (int i = 0; i < 32; i++) acc[i] = 0.f;
    #pragma unroll 2
    for (int k = 0; k < CP; k++){
        float w = g_W1T[k*256 + n];
        #pragma unroll
        for (int tok = 0; tok < 32; tok++) acc[tok] += xf[tok*260 + k]*w;
    }
    float hw = (n >= DM) ? g_hw[b*DM + n - DM] : 0.f;
    #pragma unroll
    for (int tok = 0; tok < 32; tok++){
        float val = acc[tok] + ((n >= DM) ? hw : 0.f);
        float other = __shfl_xor_sync(0xffffffffu, val, 1);
        if ((tid & 1) == 0){
            uint32_t p = h2pack(val, other);
            if (n < DM) g_uh[(t0+tok)*64 + (n >> 1)] = p;
            else        g_vh[(t0+tok)*64 + ((n - DM) >> 1)] = p;
        }
    }
}

/* ---------------- 4. pair MLP: half2 epilogues, 256-pair tiles -------------- */
/* u32-offset layout in dynamic smem */
#define OFF_WF   0
#define OFF_U2   24576
#define OFF_V2   (OFF_U2 + 16*68)
#define OFF_B12  (OFF_V2 + 16*68)
#define OFF_BI2  (OFF_B12 + 64)
#define OFF_BIF  (OFF_BI2 + 128)
#define SM_TOTU  (OFF_BIF + 128)
#define DYN_SMEM (SM_TOTU*4)

__global__ void __launch_bounds__(256,1) k_pairs_mma(
        const float* __restrict__ W2, const float* __restrict__ W3, const float* __restrict__ W4,
        const float* __restrict__ b1, const float* __restrict__ b2,
        const float* __restrict__ b3, const float* __restrict__ b4){
    extern __shared__ uint32_t smu[];
    uint2*    wfrag   = (uint2*)smu;
    uint32_t* u2_s    = smu + OFF_U2;   /* [16][68] half2 */
    uint32_t* v2_s    = smu + OFF_V2;
    uint32_t* b12_s   = smu + OFF_B12;  /* b1 half2 [64] */
    uint32_t* bias2_s = smu + OFF_BI2;  /* b2,b3 half2 [2][64] */
    float*    biasf_s = (float*)(smu + OFF_BIF);  /* b4 [128] */
    float*    part_s  = (float*)(smu + OFF_U2);   /* alias after tile loop */

    int tid = threadIdx.x, w = tid >> 5, t = tid & 31;
    int g = t >> 2, c = t & 3;

    for (int l = 0; l < 3; l++){
        const float* W = (l == 0) ? W2 : (l == 1) ? W3 : W4;
        for (int idx = tid; idx < 4096; idx += 256){
            int lane = idx & 31, nt = (idx >> 5) & 15, kt = idx >> 9;
            int gg = lane >> 2, cc = lane & 3;
            const float* Wr = W + (nt*8 + gg)*DM + kt*16 + 2*cc;
            uint2 fr;
            fr.x = h2pack(Wr[0], Wr[1]);
            fr.y = h2pack(Wr[8], Wr[9]);
            wfrag[l*4096 + idx] = fr;
        }
    }
    if (tid < 64){
        b12_s[tid]        = h2pack(b1[2*tid], b1[2*tid+1]);
        bias2_s[tid]      = h2pack(b2[2*tid], b2[2*tid+1]);
        bias2_s[64 + tid] = h2pack(b3[2*tid], b3[2*tid+1]);
    }
    if (tid < 128) biasf_s[tid] = b4[tid];

    int cta = blockIdx.x;
    int b = cta / SPB, s = cta % SPB;
    int t0 = s*11 + (s > 0 ? 1 : 0);
    int t1 = t0 + 11 + (s == 0 ? 1 : 0);

    uint32_t a[2][8][4];
    uint32_t an[2][4][4];
    float    d[2][8][4];
    float    acc32[16][2];
    #pragma unroll
    for (int nt = 0; nt < 16; nt++){ acc32[nt][0] = 0.f; acc32[nt][1] = 0.f; }

    for (int tt = t0; tt < t1; tt++){
        int lt0 = (tt / 10)*16, m0 = (tt % 10)*16;
        __syncthreads();
        for (int idx = tid; idx < 1024; idx += 256){
            int mi = idx >> 6, p = idx & 63;
            u2_s[mi*68 + p] = g_uh[(b*LL + m0 + mi)*64 + p];
        }
        for (int idx = tid; idx < 1024; idx += 256){
            int li = idx >> 6, p = idx & 63;
            v2_s[li*68 + p] = g_vh[(b*LL + lt0 + li)*64 + p];
        }
        __syncthreads();

        /* layer-1 activations, all half2 */
        #pragma unroll
        for (int kt = 0; kt < 8; kt++){
            int i0 = kt*8 + c;
            uint32_t bh0 = b12_s[i0], bh8 = b12_s[i0 + 4];
            #pragma unroll
            for (int f = 0; f < 2; f++){
                const uint32_t* vrow = v2_s + (w + 8*f)*68;
                uint32_t vb0 = hadd2_(vrow[i0], bh0);
                uint32_t vb8 = hadd2_(vrow[i0 + 4], bh8);
                a[f][kt][0] = lrelu2_(hadd2_(u2_s[g*68 + i0], vb0));
                a[f][kt][1] = lrelu2_(hadd2_(u2_s[(g+8)*68 + i0], vb0));
                a[f][kt][2] = lrelu2_(hadd2_(u2_s[g*68 + i0 + 4], vb8));
                a[f][kt][3] = lrelu2_(hadd2_(u2_s[(g+8)*68 + i0 + 4], vb8));
            }
        }

        #pragma unroll 1
        for (int l = 0; l < 3; l++){
            #pragma unroll
            for (int h = 0; h < 2; h++){
                #pragma unroll
                for (int ntl = 0; ntl < 8; ntl++){
                    d[0][ntl][0]=0.f; d[0][ntl][1]=0.f; d[0][ntl][2]=0.f; d[0][ntl][3]=0.f;
                    d[1][ntl][0]=0.f; d[1][ntl][1]=0.f; d[1][ntl][2]=0.f; d[1][ntl][3]=0.f;
                }
                const uint2* wl = wfrag + l*4096 + h*256 + t;
                #pragma unroll
                for (int kt = 0; kt < 8; kt++){
                    const uint2* wk = wl + kt*512;
                    #pragma unroll
                    for (int ntl = 0; ntl < 8; ntl++){
                        uint2 bb = wk[ntl*32];
                        mma_f16(d[0][ntl][0], d[0][ntl][1], d[0][ntl][2], d[0][ntl][3],
                                a[0][kt][0], a[0][kt][1], a[0][kt][2], a[0][kt][3], bb.x, bb.y);
                        mma_f16(d[1][ntl][0], d[1][ntl][1], d[1][ntl][2], d[1][ntl][3],
                                a[1][kt][0], a[1][kt][1], a[1][kt][2], a[1][kt][3], bb.x, bb.y);
                    }
                }
                if (l < 2){
                    const uint32_t* bl2 = bias2_s + l*64;
                    #pragma unroll
                    for (int f = 0; f < 2; f++){
                        #pragma unroll
                        for (int ktl = 0; ktl < 4; ktl++){
                            int i0g = (h*4 + ktl)*8 + c;
                            uint32_t bb0 = bl2[i0g], bb8 = bl2[i0g + 4];
                            uint32_t u0 = lrelu2_(hadd2_(h2pack(d[f][2*ktl][0],   d[f][2*ktl][1]),   bb0));
                            uint32_t u1 = lrelu2_(hadd2_(h2pack(d[f][2*ktl][2],   d[f][2*ktl][3]),   bb0));
                            uint32_t u2 = lrelu2_(hadd2_(h2pack(d[f][2*ktl+1][0], d[f][2*ktl+1][1]), bb8));
                            uint32_t u3 = lrelu2_(hadd2_(h2pack(d[f][2*ktl+1][2], d[f][2*ktl+1][3]), bb8));
                            if (h == 0){
                                an[f][ktl][0]=u0; an[f][ktl][1]=u1; an[f][ktl][2]=u2; an[f][ktl][3]=u3;
                            } else {
                                a[f][4+ktl][0]=u0; a[f][4+ktl][1]=u1; a[f][4+ktl][2]=u2; a[f][4+ktl][3]=u3;
                            }
                        }
                    }
                    if (h == 1){
                        #pragma unroll
                        for (int f = 0; f < 2; f++)
                            #pragma unroll
                            for (int ktl = 0; ktl < 4; ktl++){
                                a[f][ktl][0]=an[f][ktl][0]; a[f][ktl][1]=an[f][ktl][1];
                                a[f][ktl][2]=an[f][ktl][2]; a[f][ktl][3]=an[f][ktl][3];
                            }
                    }
                } else {
                    const float* bl = biasf_s + h*64;
                    #pragma unroll
                    for (int ntl = 0; ntl < 8; ntl++){
                        int nt = 8*h + ntl;
                        float bx = bl[ntl*8 + 2*c], by = bl[ntl*8 + 2*c + 1];
                        acc32[nt][0] += lrelu(d[0][ntl][0] + bx) + lrelu(d[0][ntl][2] + bx)
                                      + lrelu(d[1][ntl][0] + bx) + lrelu(d[1][ntl][2] + bx);
                        acc32[nt][1] += lrelu(d[0][ntl][1] + by) + lrelu(d[0][ntl][3] + by)
                                      + lrelu(d[1][ntl][1] + by) + lrelu(d[1][ntl][3] + by);
                    }
                }
            }
        }
    }

    __syncthreads();   /* fence before part_s aliases u2_s */

    #pragma unroll
    for (int nt = 0; nt < 16; nt++){
        #pragma unroll
        for (int r = 0; r < 2; r++){
            float v = acc32[nt][r];
            v += __shfl_xor_sync(0xffffffffu, v, 4);
            v += __shfl_xor_sync(0xffffffffu, v, 8);
            v += __shfl_xor_sync(0xffffffffu, v, 16);
            acc32[nt][r] = v;
        }
    }
    if (g == 0){
        #pragma unroll
        for (int nt = 0; nt < 16; nt++){
            part_s[w*128 + nt*8 + 2*c]     = acc32[nt][0];
            part_s[w*128 + nt*8 + 2*c + 1] = acc32[nt][1];
        }
    }
    __syncthreads();
    if (tid < 128){
        float r = 0.f;
        #pragma unroll
        for (int ww = 0; ww < 8; ww++) r += part_s[ww*128 + tid];
        g_part[(b*SPB + s)*DM + tid] = r;
    }
}

/* ---------------- 5. final reduction + 2-layer head ---------------- */
__global__ void k_tail(const float* __restrict__ W5, const float* __restrict__ b5,
                       const float* __restrict__ W6, const float* __restrict__ b6,
                       float* __restrict__ out){
    __shared__ float s_s[DM], s5[DM];
    int b = blockIdx.x, tid = threadIdx.x;
    if (tid < DM){
        float a = 0.f;
        #pragma unroll
        for (int t = 0; t < SPB; t++) a += g_part[(b*SPB + t)*DM + tid];
        s_s[tid] = a;
    }
    __syncthreads();
    if (tid < DM){
        float a = 0.f;
        const float* w = W5 + tid*DM;
        #pragma unroll 8
        for (int k = 0; k < DM; k++) a += s_s[k]*w[k];
        s5[tid] = lrelu(a + b5[tid]);
    }
    __syncthreads();
    {
        float a = 0.f;
        const float* w = W6 + tid*DM;
        #pragma unroll 8
        for (int k = 0; k < DM; k++) a += s5[k]*w[k];
        out[b*DO + tid] = lrelu(a + b6[tid]);
    }
}

extern "C" void kernel_launch(void* const* d_in, const int* in_sizes, int n_in,
                              void* d_out, int out_size){
    const float* x      = (const float*)d_in[0];
    const float* h      = (const float*)d_in[1];
    const float* conv_w = (const float*)d_in[2];
    const float* conv_b = (const float*)d_in[3];
    const float* bn_g   = (const float*)d_in[4];
    const float* bn_b   = (const float*)d_in[5];
    const float* W1     = (const float*)d_in[6];
    const float* b1     = (const float*)d_in[7];
    const float* W2     = (const float*)d_in[8];
    const float* b2     = (const float*)d_in[9];
    const float* W3     = (const float*)d_in[10];
    const float* b3     = (const float*)d_in[11];
    const float* W4     = (const float*)d_in[12];
    const float* b4     = (const float*)d_in[13];
    const float* W5     = (const float*)d_in[14];
    const float* b5     = (const float*)d_in[15];
    const float* W6     = (const float*)d_in[16];
    const float* b6     = (const float*)d_in[17];
    float* out = (float*)d_out;

    cudaFuncSetAttribute(k_pairs_mma, cudaFuncAttributeMaxDynamicSharedMemorySize, DYN_SMEM);

    k_prep<<<(KC*CC + 255)/256, 256>>>(conv_w, W1, h);              /* 1 */
    k_conv<<<dim3(10, BB), 256>>>(x, conv_b);                       /* 2 */
    k_uv<<<TOK/32, 256>>>(bn_g, bn_b);                              /* 3 */
    k_pairs_mma<<<GRID_PAIRS, 256, DYN_SMEM>>>(W2, W3, W4, b1, b2, b3, b4);  /* 4: profiled */
    k_tail<<<BB, 512>>>(W5, b5, W6, b6, out);                       /* 5 */
}

// round 12
// speedup vs baseline: 1.0695x; 1.0559x over previous
#include <cuda_runtime.h>
#include <cuda_fp16.h>
#include <math.h>
#include <stdint.h>

#define LL 160
#define BB 16
#define EE 512
#define CC 256
#define HH 512
#define DM 128
#define DO 512
#define TOK (BB*LL)
#define CP 258
#define W1C 1028
#define KC (3*EE)            /* 1536 */
#define SPB 9
#define GRID_PAIRS (BB*SPB)  /* 144 */
#define NKT (KC/16)          /* 96 */
#define NCB 160              /* conv blocks = stats partial rows */

__device__ __half   g_whfrag[NKT*32*32*4];
__device__ float    g_W1T[CP*256];
__device__ float    g_y[TOK*CC];
__device__ float    g_ssum[NCB*256];
__device__ float    g_ssq[NCB*256];
__device__ float    g_scale[CC];
__device__ float    g_shift[CC];
__device__ uint32_t g_uh[TOK*64];   /* u as half2 pairs */
__device__ uint32_t g_vh[TOK*64];
__device__ float    g_hw[BB*DM];
__device__ float    g_part[BB*SPB*DM];

__device__ __forceinline__ float lrelu(float x){ return fmaxf(x, 0.1f*x); }

__device__ __forceinline__ uint32_t h2pack(float lo, float hi){
    __half2 h = __floats2half2_rn(lo, hi);
    return *(uint32_t*)&h;
}
__device__ __forceinline__ uint32_t hadd2_(uint32_t a, uint32_t b){
    uint32_t d; asm("add.f16x2 %0,%1,%2;" : "=r"(d) : "r"(a), "r"(b)); return d;
}
__device__ __forceinline__ uint32_t lrelu2_(uint32_t x){
    uint32_t t, d;
    asm("mul.f16x2 %0,%1,%2;" : "=r"(t) : "r"(x), "r"(0x2E662E66u));
    asm("max.f16x2 %0,%1,%2;" : "=r"(d) : "r"(x), "r"(t));
    return d;
}
__device__ __forceinline__ void mma_f16(float& d0, float& d1, float& d2, float& d3,
                                        uint32_t a0, uint32_t a1, uint32_t a2, uint32_t a3,
                                        uint32_t b0, uint32_t b1){
    asm volatile("mma.sync.aligned.m16n8k16.row.col.f32.f16.f16.f32 "
                 "{%0,%1,%2,%3},{%4,%5,%6,%7},{%8,%9},{%0,%1,%2,%3};"
                 : "+f"(d0), "+f"(d1), "+f"(d2), "+f"(d3)
                 : "r"(a0), "r"(a1), "r"(a2), "r"(a3), "r"(b0), "r"(b1));
}

/* ------- 1. prep: coalesced row reads, scatter writes; hw in blocks 0..15 --- */
__global__ void k_prep(const float* __restrict__ conv_w, const float* __restrict__ W1,
                       const float* __restrict__ h){
    __shared__ float hs[HH];
    __shared__ float hp[256];
    int n = blockIdx.x, tid = threadIdx.x;   /* 256 blocks */
    int nt = n >> 3, gg = n & 7;

    /* conv_w row n: contiguous read, scattered fragment write */
    const float* cw = conv_w + n*KC;
    for (int pos = tid; pos < KC; pos += 256){
        int e = pos/3, kk = pos - 3*e;
        int k = kk*512 + e;
        int kt = k >> 4, r = k & 15;
        int c = (r & 7) >> 1;
        int lane = gg*4 + c;
        int hsl = ((r >> 3) << 1) | (r & 1);
        g_whfrag[(((kt*32 + nt)*32 + lane) << 2) + hsl] = __float2half(cw[pos]);
    }
    /* W1T column n: contiguous read of W1 row */
    const float* wr = (n < DM) ? (W1 + n*W1C) : (W1 + (n-DM)*W1C + CP);
    for (int k = tid; k < CP; k += 256)
        g_W1T[k*256 + n] = wr[k];

    /* h-projection for b = blockIdx.x < 16 */
    if (n < BB){
        for (int i = tid; i < HH; i += 256) hs[i] = h[n*HH + i];
        __syncthreads();
        int d = tid & 127, half = tid >> 7;
        const float* w = W1 + d*W1C + 2*CP + half*256;
        float acc = 0.f;
        #pragma unroll 8
        for (int c = 0; c < 256; c++) acc += hs[half*256 + c]*w[c];
        hp[tid] = acc;
        __syncthreads();
        if (tid < 128) g_hw[n*DM + tid] = hp[tid] + hp[tid + 128];
    }
}

/* ------- 2. conv1d fp16 mma GEMM, 160 blocks, fused BN partials (known-good) */
__global__ void __launch_bounds__(256,1) k_conv(const float* __restrict__ x,
                                                const float* __restrict__ conv_b){
    __shared__ uint32_t xh32[18*260];
    __shared__ uint2 wfr[3*32*32];
    int l0 = blockIdx.x*16, b = blockIdx.y;
    int tid = threadIdx.x, w = tid >> 5, t = tid & 31;
    int g = t >> 2, c = t & 3;

    for (int idx = tid; idx < 18*256; idx += 256){
        int r = idx >> 8, i = idx & 255;
        int l = l0 + r - 1;
        uint32_t pv = 0u;
        if (l >= 0 && l < LL){
            const float2 xv = *(const float2*)(x + (l*BB + b)*EE + 2*i);
            pv = h2pack(xv.x, xv.y);
        }
        xh32[r*260 + i] = pv;
    }

    float d[4][4];
    #pragma unroll
    for (int j = 0; j < 4; j++){ d[j][0]=0.f; d[j][1]=0.f; d[j][2]=0.f; d[j][3]=0.f; }

    const uint2* gsrc = (const uint2*)g_whfrag;
    for (int cc = 0; cc < 32; cc++){
        __syncthreads();
        const uint2* src = gsrc + cc*3072;
        #pragma unroll
        for (int q = 0; q < 12; q++) wfr[tid + q*256] = src[tid + q*256];
        __syncthreads();
        #pragma unroll
        for (int kt = 0; kt < 3; kt++){
            int k = cc*48 + kt*16;
            int kk = k >> 9, e2 = (k & 511) >> 1;
            const uint32_t* r0 = xh32 + (g + kk)*260 + e2 + c;
            const uint32_t* r1 = xh32 + (g + 8 + kk)*260 + e2 + c;
            uint32_t a0 = r0[0], a1 = r1[0], a2 = r0[4], a3 = r1[4];
            const uint2* wk = wfr + (kt*32 + w*4)*32 + t;
            #pragma unroll
            for (int j = 0; j < 4; j++){
                uint2 bb = wk[j*32];
                mma_f16(d[j][0], d[j][1], d[j][2], d[j][3], a0, a1, a2, a3, bb.x, bb.y);
            }
        }
    }

    float s[4][2], sq[4][2];
    #pragma unroll
    for (int j = 0; j < 4; j++){ s[j][0]=0.f; s[j][1]=0.f; sq[j][0]=0.f; sq[j][1]=0.f; }
    #pragma unroll
    for (int j = 0; j < 4; j++){
        int n = w*32 + j*8 + 2*c;
        float bx = conv_b[n], by = conv_b[n+1];
        float y0 = lrelu(d[j][0] + bx);
        float y1 = lrelu(d[j][1] + by);
        float y2 = lrelu(d[j][2] + bx);
        float y3 = lrelu(d[j][3] + by);
        int trow = (b*LL + l0 + g)*CC;
        g_y[trow + n]            = y0;
        g_y[trow + n + 1]        = y1;
        g_y[trow + 8*CC + n]     = y2;
        g_y[trow + 8*CC + n + 1] = y3;
        s[j][0]  += y0 + y2;         s[j][1]  += y1 + y3;
        sq[j][0] += y0*y0 + y2*y2;   sq[j][1] += y1*y1 + y3*y3;
    }
    #pragma unroll
    for (int j = 0; j < 4; j++)
        #pragma unroll
        for (int r = 0; r < 2; r++){
            #pragma unroll
            for (int m = 4; m < 32; m <<= 1){
                s[j][r]  += __shfl_xor_sync(0xffffffffu, s[j][r],  m);
                sq[j][r] += __shfl_xor_sync(0xffffffffu, sq[j][r], m);
            }
        }
    if (t < 4){
        int blk = blockIdx.y*10 + blockIdx.x;
        #pragma unroll
        for (int j = 0; j < 4; j++){
            int n = w*32 + j*8 + 2*c;
            g_ssum[blk*256 + n]     = s[j][0];
            g_ssum[blk*256 + n + 1] = s[j][1];
            g_ssq[blk*256 + n]      = sq[j][0];
            g_ssq[blk*256 + n + 1]  = sq[j][1];
        }
    }
}

/* ------- 3. BN finalize: 8 blocks, coalesced ------- */
__global__ void k_stats_fin(const float* __restrict__ bn_g, const float* __restrict__ bn_b){
    __shared__ float sa[256], sqv[256];
    int j = blockIdx.x, tid = threadIdx.x;
    int ch = j*32 + (tid & 31), rg = tid >> 5;
    float a = 0.f, q = 0.f;
    #pragma unroll 4
    for (int r = rg*20; r < rg*20 + 20; r++){
        a += g_ssum[r*256 + ch];
        q += g_ssq[r*256 + ch];
    }
    sa[tid] = a; sqv[tid] = q;
    __syncthreads();
    if (tid < 32){
        float A = 0.f, Q = 0.f;
        #pragma unroll
        for (int r = 0; r < 8; r++){ A += sa[r*32 + tid]; Q += sqv[r*32 + tid]; }
        float mu = A/(float)TOK;
        float var = Q/(float)TOK - mu*mu;
        float sc = bn_g[ch]*rsqrtf(var + 1e-5f);
        g_scale[ch] = sc;
        g_shift[ch] = bn_b[ch] - mu*sc;
    }
}

/* ------- 4. uv projection: 320 blocks x 8 tokens, direct half2 output ------- */
__global__ void __launch_bounds__(256,4) k_uv(){
    __shared__ float xf[8*260];
    __shared__ float scs[256], shs[256];
    int t0 = blockIdx.x*8;
    int b = t0 / LL;
    int tid = threadIdx.x;

    scs[tid] = g_scale[tid];
    shs[tid] = g_shift[tid];
    __syncthreads();
    for (int idx = tid; idx < 8*CC; idx += 256){
        int tok = idx >> 8, c = idx & 255;
        xf[tok*260 + c] = g_y[(t0+tok)*CC + c]*scs[c] + shs[c];
    }
    if (tid < 16){
        int tok = tid >> 1;
        float fi = (float)(t0 + tok - b*LL);
        float sL = sqrtf(160.f);
        float cv = (tid & 1) ? (fmodf(fi, sL) - 2.f)*0.5f : (fi/sL - 2.f)*0.5f;
        xf[tok*260 + 256 + (tid & 1)] = cv;
    }
    __syncthreads();

    int col = tid >> 1, th = tid & 1;      /* col 0..127; th selects token half */
    int q = col & 63;
    int isv = col >> 6;
    int n0 = 2*q + isv*DM;
    int tb = th*4;
    float acc[4][2];
    #pragma unroll
    for (int i = 0; i < 4; i++){ acc[i][0] = 0.f; acc[i][1] = 0.f; }
    #pragma unroll 2
    for (int k = 0; k < CP; k++){
        float w0 = g_W1T[k*256 + n0];
        float w1 = g_W1T[k*256 + n0 + 1];
        #pragma unroll
        for (int tok = 0; tok < 4; tok++){
            float xv = xf[(tb + tok)*260 + k];
            acc[tok][0] += xv*w0;
            acc[tok][1] += xv*w1;
        }
    }
    float hw0 = 0.f, hw1 = 0.f;
    if (isv){ hw0 = g_hw[b*DM + 2*q]; hw1 = g_hw[b*DM + 2*q + 1]; }
    #pragma unroll
    for (int tok = 0; tok < 4; tok++){
        uint32_t p = h2pack(acc[tok][0] + hw0, acc[tok][1] + hw1);
        if (isv) g_vh[(t0 + tb + tok)*64 + q] = p;
        else     g_uh[(t0 + tb + tok)*64 + q] = p;
    }
}

/* ------- 5. pair MLP: uint4 B-frag loads (1 LDS.128 -> 4 mma) -------------- */
#define OFF_WF   0
#define OFF_U2   24576
#define OFF_V2   (OFF_U2 + 16*68)
#define OFF_B12  (OFF_V2 + 16*68)
#define OFF_BI2  (OFF_B12 + 64)
#define OFF_BIF  (OFF_BI2 + 128)
#define SM_TOTU  (OFF_BIF + 128)
#define DYN_SMEM (SM_TOTU*4)

__global__ void __launch_bounds__(256,1) k_pairs_mma(
        const float* __restrict__ W2, const float* __restrict__ W3, const float* __restrict__ W4,
        const float* __restrict__ b1, const float* __restrict__ b2,
        const float* __restrict__ b3, const float* __restrict__ b4){
    extern __shared__ uint32_t smu[];
    uint2*    wfrag   = (uint2*)smu;                 /* [l][kt][h][ntp][lane][e] */
    uint32_t* u2_s    = smu + OFF_U2;
    uint32_t* v2_s    = smu + OFF_V2;
    uint32_t* b12_s   = smu + OFF_B12;
    uint32_t* bias2_s = smu + OFF_BI2;
    float*    biasf_s = (float*)(smu + OFF_BIF);
    float*    part_s  = (float*)(smu + OFF_U2);

    int tid = threadIdx.x, w = tid >> 5, t = tid & 31;
    int g = t >> 2, c = t & 3;

    for (int l = 0; l < 3; l++){
        const float* W = (l == 0) ? W2 : (l == 1) ? W3 : W4;
        for (int idx = tid; idx < 4096; idx += 256){
            int lane = idx & 31, nt = (idx >> 5) & 15, kt = idx >> 9;
            int gg = lane >> 2, cc = lane & 3;
            const float* Wr = W + (nt*8 + gg)*DM + kt*16 + 2*cc;
            uint2 fr;
            fr.x = h2pack(Wr[0], Wr[1]);
            fr.y = h2pack(Wr[8], Wr[9]);
            int h = nt >> 3, ntp = (nt >> 1) & 3, e = nt & 1;
            wfrag[l*4096 + ((kt*2 + h)*4 + ntp)*64 + lane*2 + e] = fr;
        }
    }
    if (tid < 64){
        b12_s[tid]        = h2pack(b1[2*tid], b1[2*tid+1]);
        bias2_s[tid]      = h2pack(b2[2*tid], b2[2*tid+1]);
        bias2_s[64 + tid] = h2pack(b3[2*tid], b3[2*tid+1]);
    }
    if (tid < 128) biasf_s[tid] = b4[tid];

    int cta = blockIdx.x;
    int b = cta / SPB, s = cta % SPB;
    int t0 = s*11 + (s > 0 ? 1 : 0);
    int t1 = t0 + 11 + (s == 0 ? 1 : 0);

    uint32_t a[2][8][4];
    uint32_t an[2][4][4];
    float    d[2][8][4];
    float    acc32[16][2];
    #pragma unroll
    for (int nt = 0; nt < 16; nt++){ acc32[nt][0] = 0.f; acc32[nt][1] = 0.f; }

    for (int tt = t0; tt < t1; tt++){
        int lt0 = (tt / 10)*16, m0 = (tt % 10)*16;
        __syncthreads();
        for (int idx = tid; idx < 1024; idx += 256){
            int mi = idx >> 6, p = idx & 63;
            u2_s[mi*68 + p] = g_uh[(b*LL + m0 + mi)*64 + p];
        }
        for (int idx = tid; idx < 1024; idx += 256){
            int li = idx >> 6, p = idx & 63;
            v2_s[li*68 + p] = g_vh[(b*LL + lt0 + li)*64 + p];
        }
        __syncthreads();

        #pragma unroll
        for (int kt = 0; kt < 8; kt++){
            int i0 = kt*8 + c;
            uint32_t bh0 = b12_s[i0], bh8 = b12_s[i0 + 4];
            #pragma unroll
            for (int f = 0; f < 2; f++){
                const uint32_t* vrow = v2_s + (w + 8*f)*68;
                uint32_t vb0 = hadd2_(vrow[i0], bh0);
                uint32_t vb8 = hadd2_(vrow[i0 + 4], bh8);
                a[f][kt][0] = lrelu2_(hadd2_(u2_s[g*68 + i0], vb0));
                a[f][kt][1] = lrelu2_(hadd2_(u2_s[(g+8)*68 + i0], vb0));
                a[f][kt][2] = lrelu2_(hadd2_(u2_s[g*68 + i0 + 4], vb8));
                a[f][kt][3] = lrelu2_(hadd2_(u2_s[(g+8)*68 + i0 + 4], vb8));
            }
        }

        #pragma unroll 1
        for (int l = 0; l < 3; l++){
            const uint4* wl4 = (const uint4*)wfrag + l*2048;
            #pragma unroll
            for (int h = 0; h < 2; h++){
                #pragma unroll
                for (int ntl = 0; ntl < 8; ntl++){
                    d[0][ntl][0]=0.f; d[0][ntl][1]=0.f; d[0][ntl][2]=0.f; d[0][ntl][3]=0.f;
                    d[1][ntl][0]=0.f; d[1][ntl][1]=0.f; d[1][ntl][2]=0.f; d[1][ntl][3]=0.f;
                }
                const uint4* wh = wl4 + h*128 + t;
                #pragma unroll
                for (int kt = 0; kt < 8; kt++){
                    const uint4* wk = wh + kt*256;
                    #pragma unroll
                    for (int ntp = 0; ntp < 4; ntp++){
                        uint4 bb = wk[ntp*32];    /* one LDS.128 -> 4 mma */
                        mma_f16(d[0][2*ntp][0], d[0][2*ntp][1], d[0][2*ntp][2], d[0][2*ntp][3],
                                a[0][kt][0], a[0][kt][1], a[0][kt][2], a[0][kt][3], bb.x, bb.y);
                        mma_f16(d[1][2*ntp][0], d[1][2*ntp][1], d[1][2*ntp][2], d[1][2*ntp][3],
                                a[1][kt][0], a[1][kt][1], a[1][kt][2], a[1][kt][3], bb.x, bb.y);
                        mma_f16(d[0][2*ntp+1][0], d[0][2*ntp+1][1], d[0][2*ntp+1][2], d[0][2*ntp+1][3],
                                a[0][kt][0], a[0][kt][1], a[0][kt][2], a[0][kt][3], bb.z, bb.w);
                        mma_f16(d[1][2*ntp+1][0], d[1][2*ntp+1][1], d[1][2*ntp+1][2], d[1][2*ntp+1][3],
                                a[1][kt][0], a[1][kt][1], a[1][kt][2], a[1][kt][3], bb.z, bb.w);
                    }
                }
                if (l < 2){
                    const uint32_t* bl2 = bias2_s + l*64;
                    #pragma unroll
                    for (int f = 0; f < 2; f++){
                        #pragma unroll
                        for (int ktl = 0; ktl < 4; ktl++){
                            int i0g = (h*4 + ktl)*8 + c;
                            uint32_t bb0 = bl2[i0g], bb8 = bl2[i0g + 4];
                            uint32_t u0 = lrelu2_(hadd2_(h2pack(d[f][2*ktl][0],   d[f][2*ktl][1]),   bb0));
                            uint32_t u1 = lrelu2_(hadd2_(h2pack(d[f][2*ktl][2],   d[f][2*ktl][3]),   bb0));
                            uint32_t u2 = lrelu2_(hadd2_(h2pack(d[f][2*ktl+1][0], d[f][2*ktl+1][1]), bb8));
                            uint32_t u3 = lrelu2_(hadd2_(h2pack(d[f][2*ktl+1][2], d[f][2*ktl+1][3]), bb8));
                            if (h == 0){
                                an[f][ktl][0]=u0; an[f][ktl][1]=u1; an[f][ktl][2]=u2; an[f][ktl][3]=u3;
                            } else {
                                a[f][4+ktl][0]=u0; a[f][4+ktl][1]=u1; a[f][4+ktl][2]=u2; a[f][4+ktl][3]=u3;
                            }
                        }
                    }
                    if (h == 1){
                        #pragma unroll
                        for (int f = 0; f < 2; f++)
                            #pragma unroll
                            for (int ktl = 0; ktl < 4; ktl++){
                                a[f][ktl][0]=an[f][ktl][0]; a[f][ktl][1]=an[f][ktl][1];
                                a[f][ktl][2]=an[f][ktl][2]; a[f][ktl][3]=an[f][ktl][3];
                            }
                    }
                } else {
                    const float* bl = biasf_s + h*64;
                    #pragma unroll
                    for (int ntl = 0; ntl < 8; ntl++){
                        int nt = 8*h + ntl;
                        float bx = bl[ntl*8 + 2*c], by = bl[ntl*8 + 2*c + 1];
                        acc32[nt][0] += lrelu(d[0][ntl][0] + bx) + lrelu(d[0][ntl][2] + bx)
                                      + lrelu(d[1][ntl][0] + bx) + lrelu(d[1][ntl][2] + bx);
                        acc32[nt][1] += lrelu(d[0][ntl][1] + by) + lrelu(d[0][ntl][3] + by)
                                      + lrelu(d[1][ntl][1] + by) + lrelu(d[1][ntl][3] + by);
                    }
                }
            }
        }
    }

    __syncthreads();   /* fence before part_s aliases u2_s */

    #pragma unroll
    for (int nt = 0; nt < 16; nt++){
        #pragma unroll
        for (int r = 0; r < 2; r++){
            float v = acc32[nt][r];
            v += __shfl_xor_sync(0xffffffffu, v, 4);
            v += __shfl_xor_sync(0xffffffffu, v, 8);
            v += __shfl_xor_sync(0xffffffffu, v, 16);
            acc32[nt][r] = v;
        }
    }
    if (g == 0){
        #pragma unroll
        for (int nt = 0; nt < 16; nt++){
            part_s[w*128 + nt*8 + 2*c]     = acc32[nt][0];
            part_s[w*128 + nt*8 + 2*c + 1] = acc32[nt][1];
        }
    }
    __syncthreads();
    if (tid < 128){
        float r = 0.f;
        #pragma unroll
        for (int ww = 0; ww < 8; ww++) r += part_s[ww*128 + tid];
        g_part[(b*SPB + s)*DM + tid] = r;
    }
}

/* ------- 6. final reduction + 2-layer head ------- */
__global__ void k_tail(const float* __restrict__ W5, const float* __restrict__ b5,
                       const float* __restrict__ W6, const float* __restrict__ b6,
                       float* __restrict__ out){
    __shared__ float s_s[DM], s5[DM];
    int b = blockIdx.x, tid = threadIdx.x;
    if (tid < DM){
        float a = 0.f;
        #pragma unroll
        for (int t = 0; t < SPB; t++) a += g_part[(b*SPB + t)*DM + tid];
        s_s[tid] = a;
    }
    __syncthreads();
    if (tid < DM){
        float a = 0.f;
        const float* w = W5 + tid*DM;
        #pragma unroll 8
        for (int k = 0; k < DM; k++) a += s_s[k]*w[k];
        s5[tid] = lrelu(a + b5[tid]);
    }
    __syncthreads();
    {
        float a = 0.f;
        const float* w = W6 + tid*DM;
        #pragma unroll 8
        for (int k = 0; k < DM; k++) a += s5[k]*w[k];
        out[b*DO + tid] = lrelu(a + b6[tid]);
    }
}

extern "C" void kernel_launch(void* const* d_in, const int* in_sizes, int n_in,
                              void* d_out, int out_size){
    const float* x      = (const float*)d_in[0];
    const float* h      = (const float*)d_in[1];
    const float* conv_w = (const float*)d_in[2];
    const float* conv_b = (const float*)d_in[3];
    const float* bn_g   = (const float*)d_in[4];
    const float* bn_b   = (const float*)d_in[5];
    const float* W1     = (const float*)d_in[6];
    const float* b1     = (const float*)d_in[7];
    const float* W2     = (const float*)d_in[8];
    const float* b2     = (const float*)d_in[9];
    const float* W3     = (const float*)d_in[10];
    const float* b3     = (const float*)d_in[11];
    const float* W4     = (const float*)d_in[12];
    const float* b4     = (const float*)d_in[13];
    const float* W5     = (const float*)d_in[14];
    const float* b5     = (const float*)d_in[15];
    const float* W6     = (const float*)d_in[16];
    const float* b6     = (const float*)d_in[17];
    float* out = (float*)d_out;

    cudaFuncSetAttribute(k_pairs_mma, cudaFuncAttributeMaxDynamicSharedMemorySize, DYN_SMEM);

    k_prep<<<256, 256>>>(conv_w, W1, h);                            /* 1 */
    k_conv<<<dim3(10, BB), 256>>>(x, conv_b);                       /* 2 */
    k_stats_fin<<<8, 256>>>(bn_g, bn_b);                            /* 3 */
    k_uv<<<TOK/8, 256>>>();                                         /* 4: profiled */
    k_pairs_mma<<<GRID_PAIRS, 256, DYN_SMEM>>>(W2, W3, W4, b1, b2, b3, b4);  /* 5 */
    k_tail<<<BB, 512>>>(W5, b5, W6, b6, out);                       /* 6 */
}

// round 13
// speedup vs baseline: 1.1624x; 1.0869x over previous
#include <cuda_runtime.h>
#include <cuda_fp16.h>
#include <math.h>
#include <stdint.h>

#define LL 160
#define BB 16
#define EE 512
#define CC 256
#define HH 512
#define DM 128
#define DO 512
#define TOK (BB*LL)
#define CP 258
#define W1C 1028
#define KC (3*EE)            /* 1536 */
#define SPB 9
#define GRID_PAIRS (BB*SPB)  /* 144 */
#define NKT (KC/16)          /* 96 */
#define NCB 160
#define UVKT 17              /* K=258 padded to 272 -> 17 kt steps */

__device__ __half   g_whfrag[NKT*32*32*4];
__device__ uint2    g_w1frag[UVKT*32*32];   /* uv-proj W fragments */
__device__ float    g_y[TOK*CC];
__device__ float    g_ssum[NCB*256];
__device__ float    g_ssq[NCB*256];
__device__ float    g_scale[CC];
__device__ float    g_shift[CC];
__device__ uint32_t g_uh[TOK*64];
__device__ uint32_t g_vh[TOK*64];
__device__ float    g_hw[BB*DM];
__device__ float    g_part[BB*SPB*DM];

__device__ __forceinline__ float lrelu(float x){ return fmaxf(x, 0.1f*x); }

__device__ __forceinline__ uint32_t h2pack(float lo, float hi){
    __half2 h = __floats2half2_rn(lo, hi);
    return *(uint32_t*)&h;
}
__device__ __forceinline__ uint32_t hadd2_(uint32_t a, uint32_t b){
    uint32_t d; asm("add.f16x2 %0,%1,%2;" : "=r"(d) : "r"(a), "r"(b)); return d;
}
__device__ __forceinline__ uint32_t lrelu2_(uint32_t x){
    uint32_t t, d;
    asm("mul.f16x2 %0,%1,%2;" : "=r"(t) : "r"(x), "r"(0x2E662E66u));
    asm("max.f16x2 %0,%1,%2;" : "=r"(d) : "r"(x), "r"(t));
    return d;
}
__device__ __forceinline__ void mma_f16(float& d0, float& d1, float& d2, float& d3,
                                        uint32_t a0, uint32_t a1, uint32_t a2, uint32_t a3,
                                        uint32_t b0, uint32_t b1){
    asm volatile("mma.sync.aligned.m16n8k16.row.col.f32.f16.f16.f32 "
                 "{%0,%1,%2,%3},{%4,%5,%6,%7},{%8,%9},{%0,%1,%2,%3};"
                 : "+f"(d0), "+f"(d1), "+f"(d2), "+f"(d3)
                 : "r"(a0), "r"(a1), "r"(a2), "r"(a3), "r"(b0), "r"(b1));
}

/* ------- 1. prep: conv frags + uv-proj frags + h-projection ------- */
__global__ void k_prep(const float* __restrict__ conv_w, const float* __restrict__ W1,
                       const float* __restrict__ h){
    __shared__ float hs[HH];
    __shared__ float hp[256];
    int n = blockIdx.x, tid = threadIdx.x;   /* 256 blocks, one output column each */
    int nt = n >> 3, gg = n & 7;

    const float* cw = conv_w + n*KC;
    for (int pos = tid; pos < KC; pos += 256){
        int e = pos/3, kk = pos - 3*e;
        int k = kk*512 + e;
        int kt = k >> 4, r = k & 15;
        int c = (r & 7) >> 1;
        int lane = gg*4 + c;
        int hsl = ((r >> 3) << 1) | (r & 1);
        g_whfrag[(((kt*32 + nt)*32 + lane) << 2) + hsl] = __float2half(cw[pos]);
    }

    /* uv-projection fragments for output column n; K padded to 272 */
    const float* wr = (n < DM) ? (W1 + n*W1C) : (W1 + (n-DM)*W1C + CP);
    if (tid < UVKT*4){
        int kt = tid >> 2, cc = tid & 3;
        int k0 = kt*16 + 2*cc;
        float v0 = (k0   < CP) ? wr[k0]   : 0.f;
        float v1 = (k0+1 < CP) ? wr[k0+1] : 0.f;
        float v8 = (k0+8 < CP) ? wr[k0+8] : 0.f;
        float v9 = (k0+9 < CP) ? wr[k0+9] : 0.f;
        uint2 fr;
        fr.x = h2pack(v0, v1);
        fr.y = h2pack(v8, v9);
        g_w1frag[kt*1024 + nt*32 + gg*4 + cc] = fr;
    }

    if (n < BB){
        for (int i = tid; i < HH; i += 256) hs[i] = h[n*HH + i];
        __syncthreads();
        int d = tid & 127, half = tid >> 7;
        const float* w = W1 + d*W1C + 2*CP + half*256;
        float acc = 0.f;
        #pragma unroll 8
        for (int c = 0; c < 256; c++) acc += hs[half*256 + c]*w[c];
        hp[tid] = acc;
        __syncthreads();
        if (tid < 128) g_hw[n*DM + tid] = hp[tid] + hp[tid + 128];
    }
}

/* ------- 2. conv1d fp16 mma GEMM + fused BN partials (frozen) ------- */
__global__ void __launch_bounds__(256,1) k_conv(const float* __restrict__ x,
                                                const float* __restrict__ conv_b){
    __shared__ uint32_t xh32[18*260];
    __shared__ uint2 wfr[3*32*32];
    int l0 = blockIdx.x*16, b = blockIdx.y;
    int tid = threadIdx.x, w = tid >> 5, t = tid & 31;
    int g = t >> 2, c = t & 3;

    for (int idx = tid; idx < 18*256; idx += 256){
        int r = idx >> 8, i = idx & 255;
        int l = l0 + r - 1;
        uint32_t pv = 0u;
        if (l >= 0 && l < LL){
            const float2 xv = *(const float2*)(x + (l*BB + b)*EE + 2*i);
            pv = h2pack(xv.x, xv.y);
        }
        xh32[r*260 + i] = pv;
    }

    float d[4][4];
    #pragma unroll
    for (int j = 0; j < 4; j++){ d[j][0]=0.f; d[j][1]=0.f; d[j][2]=0.f; d[j][3]=0.f; }

    const uint2* gsrc = (const uint2*)g_whfrag;
    for (int cc = 0; cc < 32; cc++){
        __syncthreads();
        const uint2* src = gsrc + cc*3072;
        #pragma unroll
        for (int q = 0; q < 12; q++) wfr[tid + q*256] = src[tid + q*256];
        __syncthreads();
        #pragma unroll
        for (int kt = 0; kt < 3; kt++){
            int k = cc*48 + kt*16;
            int kk = k >> 9, e2 = (k & 511) >> 1;
            const uint32_t* r0 = xh32 + (g + kk)*260 + e2 + c;
            const uint32_t* r1 = xh32 + (g + 8 + kk)*260 + e2 + c;
            uint32_t a0 = r0[0], a1 = r1[0], a2 = r0[4], a3 = r1[4];
            const uint2* wk = wfr + (kt*32 + w*4)*32 + t;
            #pragma unroll
            for (int j = 0; j < 4; j++){
                uint2 bb = wk[j*32];
                mma_f16(d[j][0], d[j][1], d[j][2], d[j][3], a0, a1, a2, a3, bb.x, bb.y);
            }
        }
    }

    float s[4][2], sq[4][2];
    #pragma unroll
    for (int j = 0; j < 4; j++){ s[j][0]=0.f; s[j][1]=0.f; sq[j][0]=0.f; sq[j][1]=0.f; }
    #pragma unroll
    for (int j = 0; j < 4; j++){
        int n = w*32 + j*8 + 2*c;
        float bx = conv_b[n], by = conv_b[n+1];
        float y0 = lrelu(d[j][0] + bx);
        float y1 = lrelu(d[j][1] + by);
        float y2 = lrelu(d[j][2] + bx);
        float y3 = lrelu(d[j][3] + by);
        int trow = (b*LL + l0 + g)*CC;
        g_y[trow + n]            = y0;
        g_y[trow + n + 1]        = y1;
        g_y[trow + 8*CC + n]     = y2;
        g_y[trow + 8*CC + n + 1] = y3;
        s[j][0]  += y0 + y2;         s[j][1]  += y1 + y3;
        sq[j][0] += y0*y0 + y2*y2;   sq[j][1] += y1*y1 + y3*y3;
    }
    #pragma unroll
    for (int j = 0; j < 4; j++)
        #pragma unroll
        for (int r = 0; r < 2; r++){
            #pragma unroll
            for (int m = 4; m < 32; m <<= 1){
                s[j][r]  += __shfl_xor_sync(0xffffffffu, s[j][r],  m);
                sq[j][r] += __shfl_xor_sync(0xffffffffu, sq[j][r], m);
            }
        }
    if (t < 4){
        int blk = blockIdx.y*10 + blockIdx.x;
        #pragma unroll
        for (int j = 0; j < 4; j++){
            int n = w*32 + j*8 + 2*c;
            g_ssum[blk*256 + n]     = s[j][0];
            g_ssum[blk*256 + n + 1] = s[j][1];
            g_ssq[blk*256 + n]      = sq[j][0];
            g_ssq[blk*256 + n + 1]  = sq[j][1];
        }
    }
}

/* ------- 3. BN finalize (frozen) ------- */
__global__ void k_stats_fin(const float* __restrict__ bn_g, const float* __restrict__ bn_b){
    __shared__ float sa[256], sqv[256];
    int j = blockIdx.x, tid = threadIdx.x;
    int ch = j*32 + (tid & 31), rg = tid >> 5;
    float a = 0.f, q = 0.f;
    #pragma unroll 4
    for (int r = rg*20; r < rg*20 + 20; r++){
        a += g_ssum[r*256 + ch];
        q += g_ssq[r*256 + ch];
    }
    sa[tid] = a; sqv[tid] = q;
    __syncthreads();
    if (tid < 32){
        float A = 0.f, Q = 0.f;
        #pragma unroll
        for (int r = 0; r < 8; r++){ A += sa[r*32 + tid]; Q += sqv[r*32 + tid]; }
        float mu = A/(float)TOK;
        float var = Q/(float)TOK - mu*mu;
        float sc = bn_g[ch]*rsqrtf(var + 1e-5f);
        g_scale[ch] = sc;
        g_shift[ch] = bn_b[ch] - mu*sc;
    }
}

/* ------- 4. uv projection as fp16 mma GEMM ---------------------------------
   block = 16 tokens x 256 outputs, grid 160. Full 139KB W1-fragment buffer
   staged once in smem; xf rows half2 stride 140 (conflict-free A loads).   */
#define UV_XH   (16*140)                       /* u32 words */
#define UV_WF   (UVKT*1024)                    /* uint2 count */
#define DYN_UV  (UV_XH*4 + UV_WF*8)
__global__ void __launch_bounds__(256,1) k_uv(){
    extern __shared__ uint32_t usm[];
    uint32_t* xh2 = usm;                /* [16][140] half2 */
    uint2*    wfr = (uint2*)(usm + UV_XH);
    int tid = threadIdx.x, w = tid >> 5, t = tid & 31;
    int g = t >> 2, c = t & 3;
    int t0 = blockIdx.x*16;
    int b = t0 / LL;
    float sL = sqrtf(160.f);

    /* build xf rows as half2 (K padded to 272) */
    for (int idx = tid; idx < 16*136; idx += 256){
        int tok = idx/136, kk2 = idx - tok*136;
        int k0 = 2*kk2;
        float v0, v1;
        if (k0 < CC){
            int row = (t0+tok)*CC;
            v0 = g_y[row + k0]*g_scale[k0] + g_shift[k0];
            v1 = g_y[row + k0 + 1]*g_scale[k0 + 1] + g_shift[k0 + 1];
        } else if (k0 == 256){
            float fi = (float)(t0 + tok - b*LL);
            v0 = (fi/sL - 2.f)*0.5f;
            v1 = (fmodf(fi, sL) - 2.f)*0.5f;
        } else { v0 = 0.f; v1 = 0.f; }
        xh2[tok*140 + kk2] = h2pack(v0, v1);
    }
    /* stage full W1 fragment buffer */
    {
        const uint4* src = (const uint4*)g_w1frag;
        uint4* dst = (uint4*)wfr;
        for (int i = tid; i < UV_WF/2; i += 256) dst[i] = src[i];
    }
    __syncthreads();

    float d[4][4];
    #pragma unroll
    for (int j = 0; j < 4; j++){ d[j][0]=0.f; d[j][1]=0.f; d[j][2]=0.f; d[j][3]=0.f; }

    #pragma unroll
    for (int kt = 0; kt < UVKT; kt++){
        const uint32_t* r0 = xh2 + g*140 + kt*8 + c;
        const uint32_t* r1 = xh2 + (g+8)*140 + kt*8 + c;
        uint32_t a0 = r0[0], a1 = r1[0], a2 = r0[4], a3 = r1[4];
        const uint2* wk = wfr + (kt*32 + w*4)*32 + t;
        #pragma unroll
        for (int j = 0; j < 4; j++){
            uint2 bb = wk[j*32];
            mma_f16(d[j][0], d[j][1], d[j][2], d[j][3], a0, a1, a2, a3, bb.x, bb.y);
        }
    }

    #pragma unroll
    for (int j = 0; j < 4; j++){
        int n = w*32 + j*8 + 2*c;
        if (n < DM){
            g_uh[(t0 + g)*64 + (n >> 1)]     = h2pack(d[j][0], d[j][1]);
            g_uh[(t0 + g + 8)*64 + (n >> 1)] = h2pack(d[j][2], d[j][3]);
        } else {
            float hw0 = g_hw[b*DM + n - DM];
            float hw1 = g_hw[b*DM + n - DM + 1];
            g_vh[(t0 + g)*64 + ((n - DM) >> 1)]     = h2pack(d[j][0] + hw0, d[j][1] + hw1);
            g_vh[(t0 + g + 8)*64 + ((n - DM) >> 1)] = h2pack(d[j][2] + hw0, d[j][3] + hw1);
        }
    }
}

/* ------- 5. pair MLP (frozen from R12) ------- */
#define OFF_WF   0
#define OFF_U2   24576
#define OFF_V2   (OFF_U2 + 16*68)
#define OFF_B12  (OFF_V2 + 16*68)
#define OFF_BI2  (OFF_B12 + 64)
#define OFF_BIF  (OFF_BI2 + 128)
#define SM_TOTU  (OFF_BIF + 128)
#define DYN_SMEM (SM_TOTU*4)

__global__ void __launch_bounds__(256,1) k_pairs_mma(
        const float* __restrict__ W2, const float* __restrict__ W3, const float* __restrict__ W4,
        const float* __restrict__ b1, const float* __restrict__ b2,
        const float* __restrict__ b3, const float* __restrict__ b4){
    extern __shared__ uint32_t smu[];
    uint2*    wfrag   = (uint2*)smu;
    uint32_t* u2_s    = smu + OFF_U2;
    uint32_t* v2_s    = smu + OFF_V2;
    uint32_t* b12_s   = smu + OFF_B12;
    uint32_t* bias2_s = smu + OFF_BI2;
    float*    biasf_s = (float*)(smu + OFF_BIF);
    float*    part_s  = (float*)(smu + OFF_U2);

    int tid = threadIdx.x, w = tid >> 5, t = tid & 31;
    int g = t >> 2, c = t & 3;

    for (int l = 0; l < 3; l++){
        const float* W = (l == 0) ? W2 : (l == 1) ? W3 : W4;
        for (int idx = tid; idx < 4096; idx += 256){
            int lane = idx & 31, nt = (idx >> 5) & 15, kt = idx >> 9;
            int gg = lane >> 2, cc = lane & 3;
            const float* Wr = W + (nt*8 + gg)*DM + kt*16 + 2*cc;
            uint2 fr;
            fr.x = h2pack(Wr[0], Wr[1]);
            fr.y = h2pack(Wr[8], Wr[9]);
            int h = nt >> 3, ntp = (nt >> 1) & 3, e = nt & 1;
            wfrag[l*4096 + ((kt*2 + h)*4 + ntp)*64 + lane*2 + e] = fr;
        }
    }
    if (tid < 64){
        b12_s[tid]        = h2pack(b1[2*tid], b1[2*tid+1]);
        bias2_s[tid]      = h2pack(b2[2*tid], b2[2*tid+1]);
        bias2_s[64 + tid] = h2pack(b3[2*tid], b3[2*tid+1]);
    }
    if (tid < 128) biasf_s[tid] = b4[tid];

    int cta = blockIdx.x;
    int b = cta / SPB, s = cta % SPB;
    int t0 = s*11 + (s > 0 ? 1 : 0);
    int t1 = t0 + 11 + (s == 0 ? 1 : 0);

    uint32_t a[2][8][4];
    uint32_t an[2][4][4];
    float    d[2][8][4];
    float    acc32[16][2];
    #pragma unroll
    for (int nt = 0; nt < 16; nt++){ acc32[nt][0] = 0.f; acc32[nt][1] = 0.f; }

    for (int tt = t0; tt < t1; tt++){
        int lt0 = (tt / 10)*16, m0 = (tt % 10)*16;
        __syncthreads();
        for (int idx = tid; idx < 1024; idx += 256){
            int mi = idx >> 6, p = idx & 63;
            u2_s[mi*68 + p] = g_uh[(b*LL + m0 + mi)*64 + p];
        }
        for (int idx = tid; idx < 1024; idx += 256){
            int li = idx >> 6, p = idx & 63;
            v2_s[li*68 + p] = g_vh[(b*LL + lt0 + li)*64 + p];
        }
        __syncthreads();

        #pragma unroll
        for (int kt = 0; kt < 8; kt++){
            int i0 = kt*8 + c;
            uint32_t bh0 = b12_s[i0], bh8 = b12_s[i0 + 4];
            #pragma unroll
            for (int f = 0; f < 2; f++){
                const uint32_t* vrow = v2_s + (w + 8*f)*68;
                uint32_t vb0 = hadd2_(vrow[i0], bh0);
                uint32_t vb8 = hadd2_(vrow[i0 + 4], bh8);
                a[f][kt][0] = lrelu2_(hadd2_(u2_s[g*68 + i0], vb0));
                a[f][kt][1] = lrelu2_(hadd2_(u2_s[(g+8)*68 + i0], vb0));
                a[f][kt][2] = lrelu2_(hadd2_(u2_s[g*68 + i0 + 4], vb8));
                a[f][kt][3] = lrelu2_(hadd2_(u2_s[(g+8)*68 + i0 + 4], vb8));
            }
        }

        #pragma unroll 1
        for (int l = 0; l < 3; l++){
            const uint4* wl4 = (const uint4*)wfrag + l*2048;
            #pragma unroll
            for (int h = 0; h < 2; h++){
                #pragma unroll
                for (int ntl = 0; ntl < 8; ntl++){
                    d[0][ntl][0]=0.f; d[0][ntl][1]=0.f; d[0][ntl][2]=0.f; d[0][ntl][3]=0.f;
                    d[1][ntl][0]=0.f; d[1][ntl][1]=0.f; d[1][ntl][2]=0.f; d[1][ntl][3]=0.f;
                }
                const uint4* wh = wl4 + h*128 + t;
                #pragma unroll
                for (int kt = 0; kt < 8; kt++){
                    const uint4* wk = wh + kt*256;
                    #pragma unroll
                    for (int ntp = 0; ntp < 4; ntp++){
                        uint4 bb = wk[ntp*32];
                        mma_f16(d[0][2*ntp][0], d[0][2*ntp][1], d[0][2*ntp][2], d[0][2*ntp][3],
                                a[0][kt][0], a[0][kt][1], a[0][kt][2], a[0][kt][3], bb.x, bb.y);
                        mma_f16(d[1][2*ntp][0], d[1][2*ntp][1], d[1][2*ntp][2], d[1][2*ntp][3],
                                a[1][kt][0], a[1][kt][1], a[1][kt][2], a[1][kt][3], bb.x, bb.y);
                        mma_f16(d[0][2*ntp+1][0], d[0][2*ntp+1][1], d[0][2*ntp+1][2], d[0][2*ntp+1][3],
                                a[0][kt][0], a[0][kt][1], a[0][kt][2], a[0][kt][3], bb.z, bb.w);
                        mma_f16(d[1][2*ntp+1][0], d[1][2*ntp+1][1], d[1][2*ntp+1][2], d[1][2*ntp+1][3],
                                a[1][kt][0], a[1][kt][1], a[1][kt][2], a[1][kt][3], bb.z, bb.w);
                    }
                }
                if (l < 2){
                    const uint32_t* bl2 = bias2_s + l*64;
                    #pragma unroll
                    for (int f = 0; f < 2; f++){
                        #pragma unroll
                        for (int ktl = 0; ktl < 4; ktl++){
                            int i0g = (h*4 + ktl)*8 + c;
                            uint32_t bb0 = bl2[i0g], bb8 = bl2[i0g + 4];
                            uint32_t u0 = lrelu2_(hadd2_(h2pack(d[f][2*ktl][0],   d[f][2*ktl][1]),   bb0));
                            uint32_t u1 = lrelu2_(hadd2_(h2pack(d[f][2*ktl][2],   d[f][2*ktl][3]),   bb0));
                            uint32_t u2 = lrelu2_(hadd2_(h2pack(d[f][2*ktl+1][0], d[f][2*ktl+1][1]), bb8));
                            uint32_t u3 = lrelu2_(hadd2_(h2pack(d[f][2*ktl+1][2], d[f][2*ktl+1][3]), bb8));
                            if (h == 0){
                                an[f][ktl][0]=u0; an[f][ktl][1]=u1; an[f][ktl][2]=u2; an[f][ktl][3]=u3;
                            } else {
                                a[f][4+ktl][0]=u0; a[f][4+ktl][1]=u1; a[f][4+ktl][2]=u2; a[f][4+ktl][3]=u3;
                            }
                        }
                    }
                    if (h == 1){
                        #pragma unroll
                        for (int f = 0; f < 2; f++)
                            #pragma unroll
                            for (int ktl = 0; ktl < 4; ktl++){
                                a[f][ktl][0]=an[f][ktl][0]; a[f][ktl][1]=an[f][ktl][1];
                                a[f][ktl][2]=an[f][ktl][2]; a[f][ktl][3]=an[f][ktl][3];
                            }
                    }
                } else {
                    const float* bl = biasf_s + h*64;
                    #pragma unroll
                    for (int ntl = 0; ntl < 8; ntl++){
                        int nt = 8*h + ntl;
                        float bx = bl[ntl*8 + 2*c], by = bl[ntl*8 + 2*c + 1];
                        acc32[nt][0] += lrelu(d[0][ntl][0] + bx) + lrelu(d[0][ntl][2] + bx)
                                      + lrelu(d[1][ntl][0] + bx) + lrelu(d[1][ntl][2] + bx);
                        acc32[nt][1] += lrelu(d[0][ntl][1] + by) + lrelu(d[0][ntl][3] + by)
                                      + lrelu(d[1][ntl][1] + by) + lrelu(d[1][ntl][3] + by);
                    }
                }
            }
        }
    }

    __syncthreads();

    #pragma unroll
    for (int nt = 0; nt < 16; nt++){
        #pragma unroll
        for (int r = 0; r < 2; r++){
            float v = acc32[nt][r];
            v += __shfl_xor_sync(0xffffffffu, v, 4);
            v += __shfl_xor_sync(0xffffffffu, v, 8);
            v += __shfl_xor_sync(0xffffffffu, v, 16);
            acc32[nt][r] = v;
        }
    }
    if (g == 0){
        #pragma unroll
        for (int nt = 0; nt < 16; nt++){
            part_s[w*128 + nt*8 + 2*c]     = acc32[nt][0];
            part_s[w*128 + nt*8 + 2*c + 1] = acc32[nt][1];
        }
    }
    __syncthreads();
    if (tid < 128){
        float r = 0.f;
        #pragma unroll
        for (int ww = 0; ww < 8; ww++) r += part_s[ww*128 + tid];
        g_part[(b*SPB + s)*DM + tid] = r;
    }
}

/* ------- 6. final reduction + 2-layer head ------- */
__global__ void k_tail(const float* __restrict__ W5, const float* __restrict__ b5,
                       const float* __restrict__ W6, const float* __restrict__ b6,
                       float* __restrict__ out){
    __shared__ float s_s[DM], s5[DM];
    int b = blockIdx.x, tid = threadIdx.x;
    if (tid < DM){
        float a = 0.f;
        #pragma unroll
        for (int t = 0; t < SPB; t++) a += g_part[(b*SPB + t)*DM + tid];
        s_s[tid] = a;
    }
    __syncthreads();
    if (tid < DM){
        float a = 0.f;
        const float* w = W5 + tid*DM;
        #pragma unroll 8
        for (int k = 0; k < DM; k++) a += s_s[k]*w[k];
        s5[tid] = lrelu(a + b5[tid]);
    }
    __syncthreads();
    {
        float a = 0.f;
        const float* w = W6 + tid*DM;
        #pragma unroll 8
        for (int k = 0; k < DM; k++) a += s5[k]*w[k];
        out[b*DO + tid] = lrelu(a + b6[tid]);
    }
}

extern "C" void kernel_launch(void* const* d_in, const int* in_sizes, int n_in,
                              void* d_out, int out_size){
    const float* x      = (const float*)d_in[0];
    const float* h      = (const float*)d_in[1];
    const float* conv_w = (const float*)d_in[2];
    const float* conv_b = (const float*)d_in[3];
    const float* bn_g   = (const float*)d_in[4];
    const float* bn_b   = (const float*)d_in[5];
    const float* W1     = (const float*)d_in[6];
    const float* b1     = (const float*)d_in[7];
    const float* W2     = (const float*)d_in[8];
    const float* b2     = (const float*)d_in[9];
    const float* W3     = (const float*)d_in[10];
    const float* b3     = (const float*)d_in[11];
    const float* W4     = (const float*)d_in[12];
    const float* b4     = (const float*)d_in[13];
    const float* W5     = (const float*)d_in[14];
    const float* b5     = (const float*)d_in[15];
    const float* W6     = (const float*)d_in[16];
    const float* b6     = (const float*)d_in[17];
    float* out = (float*)d_out;

    cudaFuncSetAttribute(k_uv, cudaFuncAttributeMaxDynamicSharedMemorySize, DYN_UV);
    cudaFuncSetAttribute(k_pairs_mma, cudaFuncAttributeMaxDynamicSharedMemorySize, DYN_SMEM);

    k_prep<<<256, 256>>>(conv_w, W1, h);                            /* 1 */
    k_conv<<<dim3(10, BB), 256>>>(x, conv_b);                       /* 2 */
    k_stats_fin<<<8, 256>>>(bn_g, bn_b);                            /* 3 */
    k_uv<<<TOK/16, 256, DYN_UV>>>();                                /* 4: profiled */
    k_pairs_mma<<<GRID_PAIRS, 256, DYN_SMEM>>>(W2, W3, W4, b1, b2, b3, b4);  /* 5 */
    k_tail<<<BB, 512>>>(W5, b5, W6, b6, out);                       /* 6 */
}

// round 14
// speedup vs baseline: 1.1728x; 1.0089x over previous
#include <cuda_runtime.h>
#include <cuda_fp16.h>
#include <math.h>
#include <stdint.h>

#define LL 160
#define BB 16
#define EE 512
#define CC 256
#define HH 512
#define DM 128
#define DO 512
#define TOK (BB*LL)
#define CP 258
#define W1C 1028
#define KC (3*EE)            /* 1536 */
#define SPB 9
#define GRID_PAIRS (BB*SPB)  /* 144 */
#define NKT (KC/16)          /* 96 */
#define NCB 160
#define UVKT 17

__device__ __half   g_whfrag[NKT*32*32*4];
__device__ uint2    g_w1frag[UVKT*32*32];
__device__ float    g_y[TOK*CC];
__device__ float    g_ssum[NCB*256];
__device__ float    g_ssq[NCB*256];
__device__ float    g_scale[CC];
__device__ float    g_shift[CC];
__device__ uint32_t g_uh[TOK*64];
__device__ uint32_t g_vh[TOK*64];
__device__ float    g_hw[BB*DM];
__device__ float    g_part[BB*SPB*DM];

__device__ __forceinline__ float lrelu(float x){ return fmaxf(x, 0.1f*x); }

__device__ __forceinline__ uint32_t h2pack(float lo, float hi){
    __half2 h = __floats2half2_rn(lo, hi);
    return *(uint32_t*)&h;
}
__device__ __forceinline__ uint32_t hadd2_(uint32_t a, uint32_t b){
    uint32_t d; asm("add.f16x2 %0,%1,%2;" : "=r"(d) : "r"(a), "r"(b)); return d;
}
__device__ __forceinline__ uint32_t lrelu2_(uint32_t x){
    uint32_t t, d;
    asm("mul.f16x2 %0,%1,%2;" : "=r"(t) : "r"(x), "r"(0x2E662E66u));
    asm("max.f16x2 %0,%1,%2;" : "=r"(d) : "r"(x), "r"(t));
    return d;
}
__device__ __forceinline__ void mma_f16(float& d0, float& d1, float& d2, float& d3,
                                        uint32_t a0, uint32_t a1, uint32_t a2, uint32_t a3,
                                        uint32_t b0, uint32_t b1){
    asm volatile("mma.sync.aligned.m16n8k16.row.col.f32.f16.f16.f32 "
                 "{%0,%1,%2,%3},{%4,%5,%6,%7},{%8,%9},{%0,%1,%2,%3};"
                 : "+f"(d0), "+f"(d1), "+f"(d2), "+f"(d3)
                 : "r"(a0), "r"(a1), "r"(a2), "r"(a3), "r"(b0), "r"(b1));
}

/* ------- 1. prep (frozen) ------- */
__global__ void k_prep(const float* __restrict__ conv_w, const float* __restrict__ W1,
                       const float* __restrict__ h){
    __shared__ float hs[HH];
    __shared__ float hp[256];
    int n = blockIdx.x, tid = threadIdx.x;
    int nt = n >> 3, gg = n & 7;

    const float* cw = conv_w + n*KC;
    for (int pos = tid; pos < KC; pos += 256){
        int e = pos/3, kk = pos - 3*e;
        int k = kk*512 + e;
        int kt = k >> 4, r = k & 15;
        int c = (r & 7) >> 1;
        int lane = gg*4 + c;
        int hsl = ((r >> 3) << 1) | (r & 1);
        g_whfrag[(((kt*32 + nt)*32 + lane) << 2) + hsl] = __float2half(cw[pos]);
    }

    const float* wr = (n < DM) ? (W1 + n*W1C) : (W1 + (n-DM)*W1C + CP);
    if (tid < UVKT*4){
        int kt = tid >> 2, cc = tid & 3;
        int k0 = kt*16 + 2*cc;
        float v0 = (k0   < CP) ? wr[k0]   : 0.f;
        float v1 = (k0+1 < CP) ? wr[k0+1] : 0.f;
        float v8 = (k0+8 < CP) ? wr[k0+8] : 0.f;
        float v9 = (k0+9 < CP) ? wr[k0+9] : 0.f;
        uint2 fr;
        fr.x = h2pack(v0, v1);
        fr.y = h2pack(v8, v9);
        g_w1frag[kt*1024 + nt*32 + gg*4 + cc] = fr;
    }

    if (n < BB){
        for (int i = tid; i < HH; i += 256) hs[i] = h[n*HH + i];
        __syncthreads();
        int d = tid & 127, half = tid >> 7;
        const float* w = W1 + d*W1C + 2*CP + half*256;
        float acc = 0.f;
        #pragma unroll 8
        for (int c = 0; c < 256; c++) acc += hs[half*256 + c]*w[c];
        hp[tid] = acc;
        __syncthreads();
        if (tid < 128) g_hw[n*DM + tid] = hp[tid] + hp[tid + 128];
    }
}

/* ------- 2. conv1d fp16 mma GEMM: direct-LDG weights, single sync ------- */
__global__ void __launch_bounds__(256) k_conv(const float* __restrict__ x,
                                              const float* __restrict__ conv_b){
    __shared__ uint32_t xh32[18*260];
    int l0 = blockIdx.x*16, b = blockIdx.y;
    int tid = threadIdx.x, w = tid >> 5, t = tid & 31;
    int g = t >> 2, c = t & 3;

    for (int idx = tid; idx < 18*256; idx += 256){
        int r = idx >> 8, i = idx & 255;
        int l = l0 + r - 1;
        uint32_t pv = 0u;
        if (l >= 0 && l < LL){
            const float2 xv = *(const float2*)(x + (l*BB + b)*EE + 2*i);
            pv = h2pack(xv.x, xv.y);
        }
        xh32[r*260 + i] = pv;
    }
    __syncthreads();

    float d[4][4];
    #pragma unroll
    for (int j = 0; j < 4; j++){ d[j][0]=0.f; d[j][1]=0.f; d[j][2]=0.f; d[j][3]=0.f; }

    const uint2* wf = (const uint2*)g_whfrag;
    #pragma unroll 4
    for (int ktg = 0; ktg < NKT; ktg++){
        int k = ktg*16;
        int kk = k >> 9, e2 = (k & 511) >> 1;
        const uint32_t* r0 = xh32 + (g + kk)*260 + e2 + c;
        const uint32_t* r1 = xh32 + (g + 8 + kk)*260 + e2 + c;
        uint32_t a0 = r0[0], a1 = r1[0], a2 = r0[4], a3 = r1[4];
        const uint2* wk = wf + (ktg*32 + w*4)*32 + t;
        #pragma unroll
        for (int j = 0; j < 4; j++){
            uint2 bb = __ldg(wk + j*32);
            mma_f16(d[j][0], d[j][1], d[j][2], d[j][3], a0, a1, a2, a3, bb.x, bb.y);
        }
    }

    float s[4][2], sq[4][2];
    #pragma unroll
    for (int j = 0; j < 4; j++){ s[j][0]=0.f; s[j][1]=0.f; sq[j][0]=0.f; sq[j][1]=0.f; }
    #pragma unroll
    for (int j = 0; j < 4; j++){
        int n = w*32 + j*8 + 2*c;
        float bx = conv_b[n], by = conv_b[n+1];
        float y0 = lrelu(d[j][0] + bx);
        float y1 = lrelu(d[j][1] + by);
        float y2 = lrelu(d[j][2] + bx);
        float y3 = lrelu(d[j][3] + by);
        int trow = (b*LL + l0 + g)*CC;
        g_y[trow + n]            = y0;
        g_y[trow + n + 1]        = y1;
        g_y[trow + 8*CC + n]     = y2;
        g_y[trow + 8*CC + n + 1] = y3;
        s[j][0]  += y0 + y2;         s[j][1]  += y1 + y3;
        sq[j][0] += y0*y0 + y2*y2;   sq[j][1] += y1*y1 + y3*y3;
    }
    #pragma unroll
    for (int j = 0; j < 4; j++)
        #pragma unroll
        for (int r = 0; r < 2; r++){
            #pragma unroll
            for (int m = 4; m < 32; m <<= 1){
                s[j][r]  += __shfl_xor_sync(0xffffffffu, s[j][r],  m);
                sq[j][r] += __shfl_xor_sync(0xffffffffu, sq[j][r], m);
            }
        }
    if (t < 4){
        int blk = blockIdx.y*10 + blockIdx.x;
        #pragma unroll
        for (int j = 0; j < 4; j++){
            int n = w*32 + j*8 + 2*c;
            g_ssum[blk*256 + n]     = s[j][0];
            g_ssum[blk*256 + n + 1] = s[j][1];
            g_ssq[blk*256 + n]      = sq[j][0];
            g_ssq[blk*256 + n + 1]  = sq[j][1];
        }
    }
}

/* ------- 3. BN finalize (frozen) ------- */
__global__ void k_stats_fin(const float* __restrict__ bn_g, const float* __restrict__ bn_b){
    __shared__ float sa[256], sqv[256];
    int j = blockIdx.x, tid = threadIdx.x;
    int ch = j*32 + (tid & 31), rg = tid >> 5;
    float a = 0.f, q = 0.f;
    #pragma unroll 4
    for (int r = rg*20; r < rg*20 + 20; r++){
        a += g_ssum[r*256 + ch];
        q += g_ssq[r*256 + ch];
    }
    sa[tid] = a; sqv[tid] = q;
    __syncthreads();
    if (tid < 32){
        float A = 0.f, Q = 0.f;
        #pragma unroll
        for (int r = 0; r < 8; r++){ A += sa[r*32 + tid]; Q += sqv[r*32 + tid]; }
        float mu = A/(float)TOK;
        float var = Q/(float)TOK - mu*mu;
        float sc = bn_g[ch]*rsqrtf(var + 1e-5f);
        g_scale[ch] = sc;
        g_shift[ch] = bn_b[ch] - mu*sc;
    }
}

/* ------- 4. uv projection fp16 mma: direct-LDG weights ------- */
__global__ void __launch_bounds__(256) k_uv(){
    __shared__ uint32_t xh2[16*140];
    int tid = threadIdx.x, w = tid >> 5, t = tid & 31;
    int g = t >> 2, c = t & 3;
    int t0 = blockIdx.x*16;
    int b = t0 / LL;
    float sL = sqrtf(160.f);

    for (int idx = tid; idx < 16*136; idx += 256){
        int tok = idx/136, kk2 = idx - tok*136;
        int k0 = 2*kk2;
        float v0, v1;
        if (k0 < CC){
            int row = (t0+tok)*CC;
            v0 = g_y[row + k0]*g_scale[k0] + g_shift[k0];
            v1 = g_y[row + k0 + 1]*g_scale[k0 + 1] + g_shift[k0 + 1];
        } else if (k0 == 256){
            float fi = (float)(t0 + tok - b*LL);
            v0 = (fi/sL - 2.f)*0.5f;
            v1 = (fmodf(fi, sL) - 2.f)*0.5f;
        } else { v0 = 0.f; v1 = 0.f; }
        xh2[tok*140 + kk2] = h2pack(v0, v1);
    }
    __syncthreads();

    float d[4][4];
    #pragma unroll
    for (int j = 0; j < 4; j++){ d[j][0]=0.f; d[j][1]=0.f; d[j][2]=0.f; d[j][3]=0.f; }

    #pragma unroll
    for (int kt = 0; kt < UVKT; kt++){
        const uint32_t* r0 = xh2 + g*140 + kt*8 + c;
        const uint32_t* r1 = xh2 + (g+8)*140 + kt*8 + c;
        uint32_t a0 = r0[0], a1 = r1[0], a2 = r0[4], a3 = r1[4];
        const uint2* wk = g_w1frag + (kt*32 + w*4)*32 + t;
        #pragma unroll
        for (int j = 0; j < 4; j++){
            uint2 bb = __ldg(wk + j*32);
            mma_f16(d[j][0], d[j][1], d[j][2], d[j][3], a0, a1, a2, a3, bb.x, bb.y);
        }
    }

    #pragma unroll
    for (int j = 0; j < 4; j++){
        int n = w*32 + j*8 + 2*c;
        if (n < DM){
            g_uh[(t0 + g)*64 + (n >> 1)]     = h2pack(d[j][0], d[j][1]);
            g_uh[(t0 + g + 8)*64 + (n >> 1)] = h2pack(d[j][2], d[j][3]);
        } else {
            float hw0 = g_hw[b*DM + n - DM];
            float hw1 = g_hw[b*DM + n - DM + 1];
            g_vh[(t0 + g)*64 + ((n - DM) >> 1)]     = h2pack(d[j][0] + hw0, d[j][1] + hw1);
            g_vh[(t0 + g + 8)*64 + ((n - DM) >> 1)] = h2pack(d[j][2] + hw0, d[j][3] + hw1);
        }
    }
}

/* ------- 5. pair MLP (frozen from R12/R13) ------- */
#define OFF_WF   0
#define OFF_U2   24576
#define OFF_V2   (OFF_U2 + 16*68)
#define OFF_B12  (OFF_V2 + 16*68)
#define OFF_BI2  (OFF_B12 + 64)
#define OFF_BIF  (OFF_BI2 + 128)
#define SM_TOTU  (OFF_BIF + 128)
#define DYN_SMEM (SM_TOTU*4)

__global__ void __launch_bounds__(256,1) k_pairs_mma(
        const float* __restrict__ W2, const float* __restrict__ W3, const float* __restrict__ W4,
        const float* __restrict__ b1, const float* __restrict__ b2,
        const float* __restrict__ b3, const float* __restrict__ b4){
    extern __shared__ uint32_t smu[];
    uint2*    wfrag   = (uint2*)smu;
    uint32_t* u2_s    = smu + OFF_U2;
    uint32_t* v2_s    = smu + OFF_V2;
    uint32_t* b12_s   = smu + OFF_B12;
    uint32_t* bias2_s = smu + OFF_BI2;
    float*    biasf_s = (float*)(smu + OFF_BIF);
    float*    part_s  = (float*)(smu + OFF_U2);

    int tid = threadIdx.x, w = tid >> 5, t = tid & 31;
    int g = t >> 2, c = t & 3;

    for (int l = 0; l < 3; l++){
        const float* W = (l == 0) ? W2 : (l == 1) ? W3 : W4;
        for (int idx = tid; idx < 4096; idx += 256){
            int lane = idx & 31, nt = (idx >> 5) & 15, kt = idx >> 9;
            int gg = lane >> 2, cc = lane & 3;
            const float* Wr = W + (nt*8 + gg)*DM + kt*16 + 2*cc;
            uint2 fr;
            fr.x = h2pack(Wr[0], Wr[1]);
            fr.y = h2pack(Wr[8], Wr[9]);
            int h = nt >> 3, ntp = (nt >> 1) & 3, e = nt & 1;
            wfrag[l*4096 + ((kt*2 + h)*4 + ntp)*64 + lane*2 + e] = fr;
        }
    }
    if (tid < 64){
        b12_s[tid]        = h2pack(b1[2*tid], b1[2*tid+1]);
        bias2_s[tid]      = h2pack(b2[2*tid], b2[2*tid+1]);
        bias2_s[64 + tid] = h2pack(b3[2*tid], b3[2*tid+1]);
    }
    if (tid < 128) biasf_s[tid] = b4[tid];

    int cta = blockIdx.x;
    int b = cta / SPB, s = cta % SPB;
    int t0 = s*11 + (s > 0 ? 1 : 0);
    int t1 = t0 + 11 + (s == 0 ? 1 : 0);

    uint32_t a[2][8][4];
    uint32_t an[2][4][4];
    float    d[2][8][4];
    float    acc32[16][2];
    #pragma unroll
    for (int nt = 0; nt < 16; nt++){ acc32[nt][0] = 0.f; acc32[nt][1] = 0.f; }

    for (int tt = t0; tt < t1; tt++){
        int lt0 = (tt / 10)*16, m0 = (tt % 10)*16;
        __syncthreads();
        for (int idx = tid; idx < 1024; idx += 256){
            int mi = idx >> 6, p = idx & 63;
            u2_s[mi*68 + p] = g_uh[(b*LL + m0 + mi)*64 + p];
        }
        for (int idx = tid; idx < 1024; idx += 256){
            int li = idx >> 6, p = idx & 63;
            v2_s[li*68 + p] = g_vh[(b*LL + lt0 + li)*64 + p];
        }
        __syncthreads();

        #pragma unroll
        for (int kt = 0; kt < 8; kt++){
            int i0 = kt*8 + c;
            uint32_t bh0 = b12_s[i0], bh8 = b12_s[i0 + 4];
            #pragma unroll
            for (int f = 0; f < 2; f++){
                const uint32_t* vrow = v2_s + (w + 8*f)*68;
                uint32_t vb0 = hadd2_(vrow[i0], bh0);
                uint32_t vb8 = hadd2_(vrow[i0 + 4], bh8);
                a[f][kt][0] = lrelu2_(hadd2_(u2_s[g*68 + i0], vb0));
                a[f][kt][1] = lrelu2_(hadd2_(u2_s[(g+8)*68 + i0], vb0));
                a[f][kt][2] = lrelu2_(hadd2_(u2_s[g*68 + i0 + 4], vb8));
                a[f][kt][3] = lrelu2_(hadd2_(u2_s[(g+8)*68 + i0 + 4], vb8));
            }
        }

        #pragma unroll 1
        for (int l = 0; l < 3; l++){
            const uint4* wl4 = (const uint4*)wfrag + l*2048;
            #pragma unroll
            for (int h = 0; h < 2; h++){
                #pragma unroll
                for (int ntl = 0; ntl < 8; ntl++){
                    d[0][ntl][0]=0.f; d[0][ntl][1]=0.f; d[0][ntl][2]=0.f; d[0][ntl][3]=0.f;
                    d[1][ntl][0]=0.f; d[1][ntl][1]=0.f; d[1][ntl][2]=0.f; d[1][ntl][3]=0.f;
                }
                const uint4* wh = wl4 + h*128 + t;
                #pragma unroll
                for (int kt = 0; kt < 8; kt++){
                    const uint4* wk = wh + kt*256;
                    #pragma unroll
                    for (int ntp = 0; ntp < 4; ntp++){
                        uint4 bb = wk[ntp*32];
                        mma_f16(d[0][2*ntp][0], d[0][2*ntp][1], d[0][2*ntp][2], d[0][2*ntp][3],
                                a[0][kt][0], a[0][kt][1], a[0][kt][2], a[0][kt][3], bb.x, bb.y);
                        mma_f16(d[1][2*ntp][0], d[1][2*ntp][1], d[1][2*ntp][2], d[1][2*ntp][3],
                                a[1][kt][0], a[1][kt][1], a[1][kt][2], a[1][kt][3], bb.x, bb.y);
                        mma_f16(d[0][2*ntp+1][0], d[0][2*ntp+1][1], d[0][2*ntp+1][2], d[0][2*ntp+1][3],
                                a[0][kt][0], a[0][kt][1], a[0][kt][2], a[0][kt][3], bb.z, bb.w);
                        mma_f16(d[1][2*ntp+1][0], d[1][2*ntp+1][1], d[1][2*ntp+1][2], d[1][2*ntp+1][3],
                                a[1][kt][0], a[1][kt][1], a[1][kt][2], a[1][kt][3], bb.z, bb.w);
                    }
                }
                if (l < 2){
                    const uint32_t* bl2 = bias2_s + l*64;
                    #pragma unroll
                    for (int f = 0; f < 2; f++){
                        #pragma unroll
                        for (int ktl = 0; ktl < 4; ktl++){
                            int i0g = (h*4 + ktl)*8 + c;
                            uint32_t bb0 = bl2[i0g], bb8 = bl2[i0g + 4];
                            uint32_t u0 = lrelu2_(hadd2_(h2pack(d[f][2*ktl][0],   d[f][2*ktl][1]),   bb0));
                            uint32_t u1 = lrelu2_(hadd2_(h2pack(d[f][2*ktl][2],   d[f][2*ktl][3]),   bb0));
                            uint32_t u2 = lrelu2_(hadd2_(h2pack(d[f][2*ktl+1][0], d[f][2*ktl+1][1]), bb8));
                            uint32_t u3 = lrelu2_(hadd2_(h2pack(d[f][2*ktl+1][2], d[f][2*ktl+1][3]), bb8));
                            if (h == 0){
                                an[f][ktl][0]=u0; an[f][ktl][1]=u1; an[f][ktl][2]=u2; an[f][ktl][3]=u3;
                            } else {
                                a[f][4+ktl][0]=u0; a[f][4+ktl][1]=u1; a[f][4+ktl][2]=u2; a[f][4+ktl][3]=u3;
                            }
                        }
                    }
                    if (h == 1){
                        #pragma unroll
                        for (int f = 0; f < 2; f++)
                            #pragma unroll
                            for (int ktl = 0; ktl < 4; ktl++){
                                a[f][ktl][0]=an[f][ktl][0]; a[f][ktl][1]=an[f][ktl][1];
                                a[f][ktl][2]=an[f][ktl][2]; a[f][ktl][3]=an[f][ktl][3];
                            }
                    }
                } else {
                    const float* bl = biasf_s + h*64;
                    #pragma unroll
                    for (int ntl = 0; ntl < 8; ntl++){
                        int nt = 8*h + ntl;
                        float bx = bl[ntl*8 + 2*c], by = bl[ntl*8 + 2*c + 1];
                        acc32[nt][0] += lrelu(d[0][ntl][0] + bx) + lrelu(d[0][ntl][2] + bx)
                                      + lrelu(d[1][ntl][0] + bx) + lrelu(d[1][ntl][2] + bx);
                        acc32[nt][1] += lrelu(d[0][ntl][1] + by) + lrelu(d[0][ntl][3] + by)
                                      + lrelu(d[1][ntl][1] + by) + lrelu(d[1][ntl][3] + by);
                    }
                }
            }
        }
    }

    __syncthreads();

    #pragma unroll
    for (int nt = 0; nt < 16; nt++){
        #pragma unroll
        for (int r = 0; r < 2; r++){
            float v = acc32[nt][r];
            v += __shfl_xor_sync(0xffffffffu, v, 4);
            v += __shfl_xor_sync(0xffffffffu, v, 8);
            v += __shfl_xor_sync(0xffffffffu, v, 16);
            acc32[nt][r] = v;
        }
    }
    if (g == 0){
        #pragma unroll
        for (int nt = 0; nt < 16; nt++){
            part_s[w*128 + nt*8 + 2*c]     = acc32[nt][0];
            part_s[w*128 + nt*8 + 2*c + 1] = acc32[nt][1];
        }
    }
    __syncthreads();
    if (tid < 128){
        float r = 0.f;
        #pragma unroll
        for (int ww = 0; ww < 8; ww++) r += part_s[ww*128 + tid];
        g_part[(b*SPB + s)*DM + tid] = r;
    }
}

/* ------- 6. final reduction + 2-layer head (frozen) ------- */
__global__ void k_tail(const float* __restrict__ W5, const float* __restrict__ b5,
                       const float* __restrict__ W6, const float* __restrict__ b6,
                       float* __restrict__ out){
    __shared__ float s_s[DM], s5[DM];
    int b = blockIdx.x, tid = threadIdx.x;
    if (tid < DM){
        float a = 0.f;
        #pragma unroll
        for (int t = 0; t < SPB; t++) a += g_part[(b*SPB + t)*DM + tid];
        s_s[tid] = a;
    }
    __syncthreads();
    if (tid < DM){
        float a = 0.f;
        const float* w = W5 + tid*DM;
        #pragma unroll 8
        for (int k = 0; k < DM; k++) a += s_s[k]*w[k];
        s5[tid] = lrelu(a + b5[tid]);
    }
    __syncthreads();
    {
        float a = 0.f;
        const float* w = W6 + tid*DM;
        #pragma unroll 8
        for (int k = 0; k < DM; k++) a += s5[k]*w[k];
        out[b*DO + tid] = lrelu(a + b6[tid]);
    }
}

extern "C" void kernel_launch(void* const* d_in, const int* in_sizes, int n_in,
                              void* d_out, int out_size){
    const float* x      = (const float*)d_in[0];
    const float* h      = (const float*)d_in[1];
    const float* conv_w = (const float*)d_in[2];
    const float* conv_b = (const float*)d_in[3];
    const float* bn_g   = (const float*)d_in[4];
    const float* bn_b   = (const float*)d_in[5];
    const float* W1     = (const float*)d_in[6];
    const float* b1     = (const float*)d_in[7];
    const float* W2     = (const float*)d_in[8];
    const float* b2     = (const float*)d_in[9];
    const float* W3     = (const float*)d_in[10];
    const float* b3     = (const float*)d_in[11];
    const float* W4     = (const float*)d_in[12];
    const float* b4     = (const float*)d_in[13];
    const float* W5     = (const float*)d_in[14];
    const float* b5     = (const float*)d_in[15];
    const float* W6     = (const float*)d_in[16];
    const float* b6     = (const float*)d_in[17];
    float* out = (float*)d_out;

    cudaFuncSetAttribute(k_pairs_mma, cudaFuncAttributeMaxDynamicSharedMemorySize, DYN_SMEM);

    k_prep<<<256, 256>>>(conv_w, W1, h);                            /* 1 */
    k_conv<<<dim3(10, BB), 256>>>(x, conv_b);                       /* 2 */
    k_stats_fin<<<8, 256>>>(bn_g, bn_b);                            /* 3 */
    k_uv<<<TOK/16, 256>>>();                                        /* 4: profiled */
    k_pairs_mma<<<GRID_PAIRS, 256, DYN_SMEM>>>(W2, W3, W4, b1, b2, b3, b4);  /* 5 */
    k_tail<<<BB, 512>>>(W5, b5, W6, b6, out);                       /* 6 */
}

// round 15
// speedup vs baseline: 1.3391x; 1.1418x over previous
#include <cuda_runtime.h>
#include <cuda_fp16.h>
#include <math.h>
#include <stdint.h>

#define LL 160
#define BB 16
#define EE 512
#define CC 256
#define HH 512
#define DM 128
#define DO 512
#define TOK (BB*LL)
#define CP 258
#define W1C 1028
#define KC (3*EE)            /* 1536 */
#define SPB 9
#define GRID_PAIRS (BB*SPB)  /* 144 */
#define NKT (KC/16)          /* 96 */
#define UVKT 17

__device__ __half   g_whfrag[NKT*32*32*4];
__device__ uint2    g_w1frag[UVKT*32*32];
__device__ float    g_y[TOK*CC];
__device__ float    g_ssum[320*128];
__device__ float    g_ssq[320*128];
__device__ float    g_scale[CC];
__device__ float    g_shift[CC];
__device__ uint32_t g_uh[TOK*64];
__device__ uint32_t g_vh[TOK*64];
__device__ float    g_hw[BB*DM];
__device__ float    g_part[BB*SPB*DM];

__device__ __forceinline__ float lrelu(float x){ return fmaxf(x, 0.1f*x); }

__device__ __forceinline__ uint32_t h2pack(float lo, float hi){
    __half2 h = __floats2half2_rn(lo, hi);
    return *(uint32_t*)&h;
}
__device__ __forceinline__ uint32_t hadd2_(uint32_t a, uint32_t b){
    uint32_t d; asm("add.f16x2 %0,%1,%2;" : "=r"(d) : "r"(a), "r"(b)); return d;
}
__device__ __forceinline__ uint32_t lrelu2_(uint32_t x){
    uint32_t t, d;
    asm("mul.f16x2 %0,%1,%2;" : "=r"(t) : "r"(x), "r"(0x2E662E66u));
    asm("max.f16x2 %0,%1,%2;" : "=r"(d) : "r"(x), "r"(t));
    return d;
}
__device__ __forceinline__ void mma_f16(float& d0, float& d1, float& d2, float& d3,
                                        uint32_t a0, uint32_t a1, uint32_t a2, uint32_t a3,
                                        uint32_t b0, uint32_t b1){
    asm volatile("mma.sync.aligned.m16n8k16.row.col.f32.f16.f16.f32 "
                 "{%0,%1,%2,%3},{%4,%5,%6,%7},{%8,%9},{%0,%1,%2,%3};"
                 : "+f"(d0), "+f"(d1), "+f"(d2), "+f"(d3)
                 : "r"(a0), "r"(a1), "r"(a2), "r"(a3), "r"(b0), "r"(b1));
}

/* ------- 1. prep (frozen) ------- */
__global__ void k_prep(const float* __restrict__ conv_w, const float* __restrict__ W1,
                       const float* __restrict__ h){
    __shared__ float hs[HH];
    __shared__ float hp[256];
    int n = blockIdx.x, tid = threadIdx.x;
    int nt = n >> 3, gg = n & 7;

    const float* cw = conv_w + n*KC;
    for (int pos = tid; pos < KC; pos += 256){
        int e = pos/3, kk = pos - 3*e;
        int k = kk*512 + e;
        int kt = k >> 4, r = k & 15;
        int c = (r & 7) >> 1;
        int lane = gg*4 + c;
        int hsl = ((r >> 3) << 1) | (r & 1);
        g_whfrag[(((kt*32 + nt)*32 + lane) << 2) + hsl] = __float2half(cw[pos]);
    }

    const float* wr = (n < DM) ? (W1 + n*W1C) : (W1 + (n-DM)*W1C + CP);
    if (tid < UVKT*4){
        int kt = tid >> 2, cc = tid & 3;
        int k0 = kt*16 + 2*cc;
        float v0 = (k0   < CP) ? wr[k0]   : 0.f;
        float v1 = (k0+1 < CP) ? wr[k0+1] : 0.f;
        float v8 = (k0+8 < CP) ? wr[k0+8] : 0.f;
        float v9 = (k0+9 < CP) ? wr[k0+9] : 0.f;
        uint2 fr;
        fr.x = h2pack(v0, v1);
        fr.y = h2pack(v8, v9);
        g_w1frag[kt*1024 + nt*32 + gg*4 + cc] = fr;
    }

    if (n < BB){
        for (int i = tid; i < HH; i += 256) hs[i] = h[n*HH + i];
        __syncthreads();
        int d = tid & 127, half = tid >> 7;
        const float* w = W1 + d*W1C + 2*CP + half*256;
        float acc = 0.f;
        #pragma unroll 8
        for (int c = 0; c < 256; c++) acc += hs[half*256 + c]*w[c];
        hp[tid] = acc;
        __syncthreads();
        if (tid < 128) g_hw[n*DM + tid] = hp[tid] + hp[tid + 128];
    }
}

/* ------- 2. conv1d fp16 mma: 320 blocks (16 tok x 128 ch), 2 CTA/SM ------- */
__global__ void __launch_bounds__(256) k_conv(const float* __restrict__ x,
                                              const float* __restrict__ conv_b){
    __shared__ uint32_t xh32[18*260];
    int l0 = blockIdx.x*16, cy = blockIdx.y, b = blockIdx.z;
    int tid = threadIdx.x, w = tid >> 5, t = tid & 31;
    int g = t >> 2, c = t & 3;

    for (int idx = tid; idx < 18*256; idx += 256){
        int r = idx >> 8, i = idx & 255;
        int l = l0 + r - 1;
        uint32_t pv = 0u;
        if (l >= 0 && l < LL){
            const float2 xv = *(const float2*)(x + (l*BB + b)*EE + 2*i);
            pv = h2pack(xv.x, xv.y);
        }
        xh32[r*260 + i] = pv;
    }
    __syncthreads();

    float d[2][4];
    #pragma unroll
    for (int j = 0; j < 2; j++){ d[j][0]=0.f; d[j][1]=0.f; d[j][2]=0.f; d[j][3]=0.f; }

    const uint2* wf = (const uint2*)g_whfrag;
    #pragma unroll 4
    for (int ktg = 0; ktg < NKT; ktg++){
        int k = ktg*16;
        int kk = k >> 9, e2 = (k & 511) >> 1;
        const uint32_t* r0 = xh32 + (g + kk)*260 + e2 + c;
        const uint32_t* r1 = xh32 + (g + 8 + kk)*260 + e2 + c;
        uint32_t a0 = r0[0], a1 = r1[0], a2 = r0[4], a3 = r1[4];
        const uint2* wk = wf + (ktg*32 + cy*16 + w*2)*32 + t;
        #pragma unroll
        for (int j = 0; j < 2; j++){
            uint2 bb = __ldg(wk + j*32);
            mma_f16(d[j][0], d[j][1], d[j][2], d[j][3], a0, a1, a2, a3, bb.x, bb.y);
        }
    }

    float s[2][2], sq[2][2];
    #pragma unroll
    for (int j = 0; j < 2; j++){ s[j][0]=0.f; s[j][1]=0.f; sq[j][0]=0.f; sq[j][1]=0.f; }
    #pragma unroll
    for (int j = 0; j < 2; j++){
        int n = cy*128 + w*16 + j*8 + 2*c;
        float bx = conv_b[n], by = conv_b[n+1];
        float y0 = lrelu(d[j][0] + bx);
        float y1 = lrelu(d[j][1] + by);
        float y2 = lrelu(d[j][2] + bx);
        float y3 = lrelu(d[j][3] + by);
        int trow = (b*LL + l0 + g)*CC;
        g_y[trow + n]            = y0;
        g_y[trow + n + 1]        = y1;
        g_y[trow + 8*CC + n]     = y2;
        g_y[trow + 8*CC + n + 1] = y3;
        s[j][0]  += y0 + y2;         s[j][1]  += y1 + y3;
        sq[j][0] += y0*y0 + y2*y2;   sq[j][1] += y1*y1 + y3*y3;
    }
    #pragma unroll
    for (int j = 0; j < 2; j++)
        #pragma unroll
        for (int r = 0; r < 2; r++){
            #pragma unroll
            for (int m = 4; m < 32; m <<= 1){
                s[j][r]  += __shfl_xor_sync(0xffffffffu, s[j][r],  m);
                sq[j][r] += __shfl_xor_sync(0xffffffffu, sq[j][r], m);
            }
        }
    if (t < 4){
        int blk = (b*10 + blockIdx.x)*2 + cy;     /* 320 rows of 128 */
        #pragma unroll
        for (int j = 0; j < 2; j++){
            int off = w*16 + j*8 + 2*c;
            g_ssum[blk*128 + off]     = s[j][0];
            g_ssum[blk*128 + off + 1] = s[j][1];
            g_ssq[blk*128 + off]      = sq[j][0];
            g_ssq[blk*128 + off + 1]  = sq[j][1];
        }
    }
}

/* ------- 3. BN finalize (adjusted for [320][128] partials) ------- */
__global__ void k_stats_fin(const float* __restrict__ bn_g, const float* __restrict__ bn_b){
    __shared__ float sa[256], sqv[256];
    int j = blockIdx.x, tid = threadIdx.x;
    int ch = j*32 + (tid & 31), rg = tid >> 5;
    int half = ch >> 7, cl = ch & 127;
    float a = 0.f, q = 0.f;
    #pragma unroll 4
    for (int r = rg*20; r < rg*20 + 20; r++){
        a += g_ssum[(r*2 + half)*128 + cl];
        q += g_ssq[(r*2 + half)*128 + cl];
    }
    sa[tid] = a; sqv[tid] = q;
    __syncthreads();
    if (tid < 32){
        float A = 0.f, Q = 0.f;
        #pragma unroll
        for (int r = 0; r < 8; r++){ A += sa[r*32 + tid]; Q += sqv[r*32 + tid]; }
        float mu = A/(float)TOK;
        float var = Q/(float)TOK - mu*mu;
        float sc = bn_g[ch]*rsqrtf(var + 1e-5f);
        g_scale[ch] = sc;
        g_shift[ch] = bn_b[ch] - mu*sc;
    }
}

/* ------- 4. uv projection fp16 mma: direct-LDG weights (frozen) ------- */
__global__ void __launch_bounds__(256) k_uv(){
    __shared__ uint32_t xh2[16*140];
    int tid = threadIdx.x, w = tid >> 5, t = tid & 31;
    int g = t >> 2, c = t & 3;
    int t0 = blockIdx.x*16;
    int b = t0 / LL;
    float sL = sqrtf(160.f);

    for (int idx = tid; idx < 16*136; idx += 256){
        int tok = idx/136, kk2 = idx - tok*136;
        int k0 = 2*kk2;
        float v0, v1;
        if (k0 < CC){
            int row = (t0+tok)*CC;
            v0 = g_y[row + k0]*g_scale[k0] + g_shift[k0];
            v1 = g_y[row + k0 + 1]*g_scale[k0 + 1] + g_shift[k0 + 1];
        } else if (k0 == 256){
            float fi = (float)(t0 + tok - b*LL);
            v0 = (fi/sL - 2.f)*0.5f;
            v1 = (fmodf(fi, sL) - 2.f)*0.5f;
        } else { v0 = 0.f; v1 = 0.f; }
        xh2[tok*140 + kk2] = h2pack(v0, v1);
    }
    __syncthreads();

    float d[4][4];
    #pragma unroll
    for (int j = 0; j < 4; j++){ d[j][0]=0.f; d[j][1]=0.f; d[j][2]=0.f; d[j][3]=0.f; }

    #pragma unroll
    for (int kt = 0; kt < UVKT; kt++){
        const uint32_t* r0 = xh2 + g*140 + kt*8 + c;
        const uint32_t* r1 = xh2 + (g+8)*140 + kt*8 + c;
        uint32_t a0 = r0[0], a1 = r1[0], a2 = r0[4], a3 = r1[4];
        const uint2* wk = g_w1frag + (kt*32 + w*4)*32 + t;
        #pragma unroll
        for (int j = 0; j < 4; j++){
            uint2 bb = __ldg(wk + j*32);
            mma_f16(d[j][0], d[j][1], d[j][2], d[j][3], a0, a1, a2, a3, bb.x, bb.y);
        }
    }

    #pragma unroll
    for (int j = 0; j < 4; j++){
        int n = w*32 + j*8 + 2*c;
        if (n < DM){
            g_uh[(t0 + g)*64 + (n >> 1)]     = h2pack(d[j][0], d[j][1]);
            g_uh[(t0 + g + 8)*64 + (n >> 1)] = h2pack(d[j][2], d[j][3]);
        } else {
            float hw0 = g_hw[b*DM + n - DM];
            float hw1 = g_hw[b*DM + n - DM + 1];
            g_vh[(t0 + g)*64 + ((n - DM) >> 1)]     = h2pack(d[j][0] + hw0, d[j][1] + hw1);
            g_vh[(t0 + g + 8)*64 + ((n - DM) >> 1)] = h2pack(d[j][2] + hw0, d[j][3] + hw1);
        }
    }
}

/* ------- 5. pair MLP: + register prefetch of next tile's u/v ------- */
#define OFF_WF   0
#define OFF_U2   24576
#define OFF_V2   (OFF_U2 + 16*68)
#define OFF_B12  (OFF_V2 + 16*68)
#define OFF_BI2  (OFF_B12 + 64)
#define OFF_BIF  (OFF_BI2 + 128)
#define SM_TOTU  (OFF_BIF + 128)
#define DYN_SMEM (SM_TOTU*4)

__global__ void __launch_bounds__(256,1) k_pairs_mma(
        const float* __restrict__ W2, const float* __restrict__ W3, const float* __restrict__ W4,
        const float* __restrict__ b1, const float* __restrict__ b2,
        const float* __restrict__ b3, const float* __restrict__ b4){
    extern __shared__ uint32_t smu[];
    uint2*    wfrag   = (uint2*)smu;
    uint32_t* u2_s    = smu + OFF_U2;
    uint32_t* v2_s    = smu + OFF_V2;
    uint32_t* b12_s   = smu + OFF_B12;
    uint32_t* bias2_s = smu + OFF_BI2;
    float*    biasf_s = (float*)(smu + OFF_BIF);
    float*    part_s  = (float*)(smu + OFF_U2);

    int tid = threadIdx.x, w = tid >> 5, t = tid & 31;
    int g = t >> 2, c = t & 3;

    for (int l = 0; l < 3; l++){
        const float* W = (l == 0) ? W2 : (l == 1) ? W3 : W4;
        for (int idx = tid; idx < 4096; idx += 256){
            int lane = idx & 31, nt = (idx >> 5) & 15, kt = idx >> 9;
            int gg = lane >> 2, cc = lane & 3;
            const float* Wr = W + (nt*8 + gg)*DM + kt*16 + 2*cc;
            uint2 fr;
            fr.x = h2pack(Wr[0], Wr[1]);
            fr.y = h2pack(Wr[8], Wr[9]);
            int h = nt >> 3, ntp = (nt >> 1) & 3, e = nt & 1;
            wfrag[l*4096 + ((kt*2 + h)*4 + ntp)*64 + lane*2 + e] = fr;
        }
    }
    if (tid < 64){
        b12_s[tid]        = h2pack(b1[2*tid], b1[2*tid+1]);
        bias2_s[tid]      = h2pack(b2[2*tid], b2[2*tid+1]);
        bias2_s[64 + tid] = h2pack(b3[2*tid], b3[2*tid+1]);
    }
    if (tid < 128) biasf_s[tid] = b4[tid];

    int cta = blockIdx.x;
    int b = cta / SPB, s = cta % SPB;
    int t0 = s*11 + (s > 0 ? 1 : 0);
    int t1 = t0 + 11 + (s == 0 ? 1 : 0);

    /* prefetch indices: thread covers u/v words idx = tid + 256*q, q<4 */
    int pmi[4], pp[4];
    #pragma unroll
    for (int q = 0; q < 4; q++){
        int idx = tid + 256*q;
        pmi[q] = idx >> 6;
        pp[q]  = idx & 63;
    }
    uint32_t pu[4], pv[4];
    {   /* prefetch tile t0 */
        int lt0 = (t0 / 10)*16, m0 = (t0 % 10)*16;
        #pragma unroll
        for (int q = 0; q < 4; q++){
            pu[q] = g_uh[(b*LL + m0 + pmi[q])*64 + pp[q]];
            pv[q] = g_vh[(b*LL + lt0 + pmi[q])*64 + pp[q]];
        }
    }

    uint32_t a[2][8][4];
    uint32_t an[2][4][4];
    float    d[2][8][4];
    float    acc32[16][2];
    #pragma unroll
    for (int nt = 0; nt < 16; nt++){ acc32[nt][0] = 0.f; acc32[nt][1] = 0.f; }

    for (int tt = t0; tt < t1; tt++){
        __syncthreads();
        #pragma unroll
        for (int q = 0; q < 4; q++){
            u2_s[pmi[q]*68 + pp[q]] = pu[q];
            v2_s[pmi[q]*68 + pp[q]] = pv[q];
        }
        __syncthreads();
        if (tt + 1 < t1){   /* prefetch next tile; completes under compute */
            int ltn = ((tt+1) / 10)*16, mn = ((tt+1) % 10)*16;
            #pragma unroll
            for (int q = 0; q < 4; q++){
                pu[q] = g_uh[(b*LL + mn + pmi[q])*64 + pp[q]];
                pv[q] = g_vh[(b*LL + ltn + pmi[q])*64 + pp[q]];
            }
        }

        #pragma unroll
        for (int kt = 0; kt < 8; kt++){
            int i0 = kt*8 + c;
            uint32_t bh0 = b12_s[i0], bh8 = b12_s[i0 + 4];
            #pragma unroll
            for (int f = 0; f < 2; f++){
                const uint32_t* vrow = v2_s + (w + 8*f)*68;
                uint32_t vb0 = hadd2_(vrow[i0], bh0);
                uint32_t vb8 = hadd2_(vrow[i0 + 4], bh8);
                a[f][kt][0] = lrelu2_(hadd2_(u2_s[g*68 + i0], vb0));
                a[f][kt][1] = lrelu2_(hadd2_(u2_s[(g+8)*68 + i0], vb0));
                a[f][kt][2] = lrelu2_(hadd2_(u2_s[g*68 + i0 + 4], vb8));
                a[f][kt][3] = lrelu2_(hadd2_(u2_s[(g+8)*68 + i0 + 4], vb8));
            }
        }

        #pragma unroll 1
        for (int l = 0; l < 3; l++){
            const uint4* wl4 = (const uint4*)wfrag + l*2048;
            #pragma unroll
            for (int h = 0; h < 2; h++){
                #pragma unroll
                for (int ntl = 0; ntl < 8; ntl++){
                    d[0][ntl][0]=0.f; d[0][ntl][1]=0.f; d[0][ntl][2]=0.f; d[0][ntl][3]=0.f;
                    d[1][ntl][0]=0.f; d[1][ntl][1]=0.f; d[1][ntl][2]=0.f; d[1][ntl][3]=0.f;
                }
                const uint4* wh = wl4 + h*128 + t;
                #pragma unroll
                for (int kt = 0; kt < 8; kt++){
                    const uint4* wk = wh + kt*256;
                    #pragma unroll
                    for (int ntp = 0; ntp < 4; ntp++){
                        uint4 bb = wk[ntp*32];
                        mma_f16(d[0][2*ntp][0], d[0][2*ntp][1], d[0][2*ntp][2], d[0][2*ntp][3],
                                a[0][kt][0], a[0][kt][1], a[0][kt][2], a[0][kt][3], bb.x, bb.y);
                        mma_f16(d[1][2*ntp][0], d[1][2*ntp][1], d[1][2*ntp][2], d[1][2*ntp][3],
                                a[1][kt][0], a[1][kt][1], a[1][kt][2], a[1][kt][3], bb.x, bb.y);
                        mma_f16(d[0][2*ntp+1][0], d[0][2*ntp+1][1], d[0][2*ntp+1][2], d[0][2*ntp+1][3],
                                a[0][kt][0], a[0][kt][1], a[0][kt][2], a[0][kt][3], bb.z, bb.w);
                        mma_f16(d[1][2*ntp+1][0], d[1][2*ntp+1][1], d[1][2*ntp+1][2], d[1][2*ntp+1][3],
                                a[1][kt][0], a[1][kt][1], a[1][kt][2], a[1][kt][3], bb.z, bb.w);
                    }
                }
                if (l < 2){
                    const uint32_t* bl2 = bias2_s + l*64;
                    #pragma unroll
                    for (int f = 0; f < 2; f++){
                        #pragma unroll
                        for (int ktl = 0; ktl < 4; ktl++){
                            int i0g = (h*4 + ktl)*8 + c;
                            uint32_t bb0 = bl2[i0g], bb8 = bl2[i0g + 4];
                            uint32_t u0 = lrelu2_(hadd2_(h2pack(d[f][2*ktl][0],   d[f][2*ktl][1]),   bb0));
                            uint32_t u1 = lrelu2_(hadd2_(h2pack(d[f][2*ktl][2],   d[f][2*ktl][3]),   bb0));
                            uint32_t u2 = lrelu2_(hadd2_(h2pack(d[f][2*ktl+1][0], d[f][2*ktl+1][1]), bb8));
                            uint32_t u3 = lrelu2_(hadd2_(h2pack(d[f][2*ktl+1][2], d[f][2*ktl+1][3]), bb8));
                            if (h == 0){
                                an[f][ktl][0]=u0; an[f][ktl][1]=u1; an[f][ktl][2]=u2; an[f][ktl][3]=u3;
                            } else {
                                a[f][4+ktl][0]=u0; a[f][4+ktl][1]=u1; a[f][4+ktl][2]=u2; a[f][4+ktl][3]=u3;
                            }
                        }
                    }
                    if (h == 1){
                        #pragma unroll
                        for (int f = 0; f < 2; f++)
                            #pragma unroll
                            for (int ktl = 0; ktl < 4; ktl++){
                                a[f][ktl][0]=an[f][ktl][0]; a[f][ktl][1]=an[f][ktl][1];
                                a[f][ktl][2]=an[f][ktl][2]; a[f][ktl][3]=an[f][ktl][3];
                            }
                    }
                } else {
                    const float* bl = biasf_s + h*64;
                    #pragma unroll
                    for (int ntl = 0; ntl < 8; ntl++){
                        int nt = 8*h + ntl;
                        float bx = bl[ntl*8 + 2*c], by = bl[ntl*8 + 2*c + 1];
                        acc32[nt][0] += lrelu(d[0][ntl][0] + bx) + lrelu(d[0][ntl][2] + bx)
                                      + lrelu(d[1][ntl][0] + bx) + lrelu(d[1][ntl][2] + bx);
                        acc32[nt][1] += lrelu(d[0][ntl][1] + by) + lrelu(d[0][ntl][3] + by)
                                      + lrelu(d[1][ntl][1] + by) + lrelu(d[1][ntl][3] + by);
                    }
                }
            }
        }
    }

    __syncthreads();

    #pragma unroll
    for (int nt = 0; nt < 16; nt++){
        #pragma unroll
        for (int r = 0; r < 2; r++){
            float v = acc32[nt][r];
            v += __shfl_xor_sync(0xffffffffu, v, 4);
            v += __shfl_xor_sync(0xffffffffu, v, 8);
            v += __shfl_xor_sync(0xffffffffu, v, 16);
            acc32[nt][r] = v;
        }
    }
    if (g == 0){
        #pragma unroll
        for (int nt = 0; nt < 16; nt++){
            part_s[w*128 + nt*8 + 2*c]     = acc32[nt][0];
            part_s[w*128 + nt*8 + 2*c + 1] = acc32[nt][1];
        }
    }
    __syncthreads();
    if (tid < 128){
        float r = 0.f;
        #pragma unroll
        for (int ww = 0; ww < 8; ww++) r += part_s[ww*128 + tid];
        g_part[(b*SPB + s)*DM + tid] = r;
    }
}

/* ------- 6. final reduction + 2-layer head (frozen) ------- */
__global__ void k_tail(const float* __restrict__ W5, const float* __restrict__ b5,
                       const float* __restrict__ W6, const float* __restrict__ b6,
                       float* __restrict__ out){
    __shared__ float s_s[DM], s5[DM];
    int b = blockIdx.x, tid = threadIdx.x;
    if (tid < DM){
        float a = 0.f;
        #pragma unroll
        for (int t = 0; t < SPB; t++) a += g_part[(b*SPB + t)*DM + tid];
        s_s[tid] = a;
    }
    __syncthreads();
    if (tid < DM){
        float a = 0.f;
        const float* w = W5 + tid*DM;
        #pragma unroll 8
        for (int k = 0; k < DM; k++) a += s_s[k]*w[k];
        s5[tid] = lrelu(a + b5[tid]);
    }
    __syncthreads();
    {
        float a = 0.f;
        const float* w = W6 + tid*DM;
        #pragma unroll 8
        for (int k = 0; k < DM; k++) a += s5[k]*w[k];
        out[b*DO + tid] = lrelu(a + b6[tid]);
    }
}

extern "C" void kernel_launch(void* const* d_in, const int* in_sizes, int n_in,
                              void* d_out, int out_size){
    const float* x      = (const float*)d_in[0];
    const float* h      = (const float*)d_in[1];
    const float* conv_w = (const float*)d_in[2];
    const float* conv_b = (const float*)d_in[3];
    const float* bn_g   = (const float*)d_in[4];
    const float* bn_b   = (const float*)d_in[5];
    const float* W1     = (const float*)d_in[6];
    const float* b1     = (const float*)d_in[7];
    const float* W2     = (const float*)d_in[8];
    const float* b2     = (const float*)d_in[9];
    const float* W3     = (const float*)d_in[10];
    const float* b3     = (const float*)d_in[11];
    const float* W4     = (const float*)d_in[12];
    const float* b4     = (const float*)d_in[13];
    const float* W5     = (const float*)d_in[14];
    const float* b5     = (const float*)d_in[15];
    const float* W6     = (const float*)d_in[16];
    const float* b6     = (const float*)d_in[17];
    float* out = (float*)d_out;

    cudaFuncSetAttribute(k_pairs_mma, cudaFuncAttributeMaxDynamicSharedMemorySize, DYN_SMEM);

    k_prep<<<256, 256>>>(conv_w, W1, h);                            /* 1 */
    k_conv<<<dim3(10, 2, BB), 256>>>(x, conv_b);                    /* 2 */
    k_stats_fin<<<8, 256>>>(bn_g, bn_b);                            /* 3 */
    k_uv<<<TOK/16, 256>>>();                                        /* 4: profiled */
    k_pairs_mma<<<GRID_PAIRS, 256, DYN_SMEM>>>(W2, W3, W4, b1, b2, b3, b4);  /* 5 */
    k_tail<<<BB, 512>>>(W5, b5, W6, b6, out);                       /* 6 */
}

// round 16
// speedup vs baseline: 1.3636x; 1.0183x over previous
#include <cuda_runtime.h>
#include <cuda_fp16.h>
#include <math.h>
#include <stdint.h>

#define LL 160
#define BB 16
#define EE 512
#define CC 256
#define HH 512
#define DM 128
#define DO 512
#define TOK (BB*LL)
#define CP 258
#define W1C 1028
#define KC (3*EE)            /* 1536 */
#define SPB 9
#define GRID_PAIRS (BB*SPB)  /* 144 */
#define NKT (KC/16)          /* 96 */
#define UVKT 17

__device__ __half   g_whfrag[NKT*32*32*4];
__device__ uint2    g_w1frag[UVKT*32*32];
__device__ float    g_y[TOK*CC];
__device__ float    g_ssum[320*128];
__device__ float    g_ssq[320*128];
__device__ float    g_scale[CC];
__device__ float    g_shift[CC];
__device__ uint32_t g_uh[TOK*64];
__device__ uint32_t g_vh[TOK*64];
__device__ float    g_hw[BB*DM];
__device__ float    g_part[BB*SPB*DM];

__device__ __forceinline__ float lrelu(float x){ return fmaxf(x, 0.1f*x); }

__device__ __forceinline__ uint32_t h2pack(float lo, float hi){
    __half2 h = __floats2half2_rn(lo, hi);
    return *(uint32_t*)&h;
}
__device__ __forceinline__ uint32_t hadd2_(uint32_t a, uint32_t b){
    uint32_t d; asm("add.f16x2 %0,%1,%2;" : "=r"(d) : "r"(a), "r"(b)); return d;
}
__device__ __forceinline__ uint32_t lrelu2_(uint32_t x){
    uint32_t t, d;
    asm("mul.f16x2 %0,%1,%2;" : "=r"(t) : "r"(x), "r"(0x2E662E66u));
    asm("max.f16x2 %0,%1,%2;" : "=r"(d) : "r"(x), "r"(t));
    return d;
}
__device__ __forceinline__ void mma_f16(float& d0, float& d1, float& d2, float& d3,
                                        uint32_t a0, uint32_t a1, uint32_t a2, uint32_t a3,
                                        uint32_t b0, uint32_t b1){
    asm volatile("mma.sync.aligned.m16n8k16.row.col.f32.f16.f16.f32 "
                 "{%0,%1,%2,%3},{%4,%5,%6,%7},{%8,%9},{%0,%1,%2,%3};"
                 : "+f"(d0), "+f"(d1), "+f"(d2), "+f"(d3)
                 : "r"(a0), "r"(a1), "r"(a2), "r"(a3), "r"(b0), "r"(b1));
}

/* ------- 1. prep: uint2 fragment stores, coalesced reads ------- */
__global__ void k_prep(const float* __restrict__ conv_w, const float* __restrict__ W1,
                       const float* __restrict__ h){
    __shared__ float hs[HH];
    __shared__ float hp[256];
    int n = blockIdx.x, tid = threadIdx.x;
    int nt = n >> 3, gg = n & 7;

    /* conv fragments: one uint2 per (kt,c); k = kt*16 + {2c,2c+1,2c+8,2c+9} */
    const float* cw = conv_w + n*KC;
    uint2* wf2 = (uint2*)g_whfrag;
    for (int it = tid; it < NKT*4; it += 256){
        int kt = it >> 2, c = it & 3;
        int k0 = kt*16 + 2*c;
        int k1 = k0 + 1, k2 = k0 + 8, k3 = k0 + 9;
        float f0 = cw[(k0 & 511)*3 + (k0 >> 9)];
        float f1 = cw[(k1 & 511)*3 + (k1 >> 9)];
        float f2 = cw[(k2 & 511)*3 + (k2 >> 9)];
        float f3 = cw[(k3 & 511)*3 + (k3 >> 9)];
        uint2 fr;
        fr.x = h2pack(f0, f1);
        fr.y = h2pack(f2, f3);
        wf2[(kt*32 + nt)*32 + gg*4 + c] = fr;
    }

    const float* wr = (n < DM) ? (W1 + n*W1C) : (W1 + (n-DM)*W1C + CP);
    if (tid < UVKT*4){
        int kt = tid >> 2, cc = tid & 3;
        int k0 = kt*16 + 2*cc;
        float v0 = (k0   < CP) ? wr[k0]   : 0.f;
        float v1 = (k0+1 < CP) ? wr[k0+1] : 0.f;
        float v8 = (k0+8 < CP) ? wr[k0+8] : 0.f;
        float v9 = (k0+9 < CP) ? wr[k0+9] : 0.f;
        uint2 fr;
        fr.x = h2pack(v0, v1);
        fr.y = h2pack(v8, v9);
        g_w1frag[kt*1024 + nt*32 + gg*4 + cc] = fr;
    }

    if (n < BB){
        for (int i = tid; i < HH; i += 256) hs[i] = h[n*HH + i];
        __syncthreads();
        int d = tid & 127, half = tid >> 7;
        const float* w = W1 + d*W1C + 2*CP + half*256;
        float acc = 0.f;
        #pragma unroll 8
        for (int c = 0; c < 256; c++) acc += hs[half*256 + c]*w[c];
        hp[tid] = acc;
        __syncthreads();
        if (tid < 128) g_hw[n*DM + tid] = hp[tid] + hp[tid + 128];
    }
}

/* ------- 2. conv1d fp16 mma: 320 blocks, 2 CTA/SM (frozen from R15) ------- */
__global__ void __launch_bounds__(256) k_conv(const float* __restrict__ x,
                                              const float* __restrict__ conv_b){
    __shared__ uint32_t xh32[18*260];
    int l0 = blockIdx.x*16, cy = blockIdx.y, b = blockIdx.z;
    int tid = threadIdx.x, w = tid >> 5, t = tid & 31;
    int g = t >> 2, c = t & 3;

    for (int idx = tid; idx < 18*256; idx += 256){
        int r = idx >> 8, i = idx & 255;
        int l = l0 + r - 1;
        uint32_t pv = 0u;
        if (l >= 0 && l < LL){
            const float2 xv = *(const float2*)(x + (l*BB + b)*EE + 2*i);
            pv = h2pack(xv.x, xv.y);
        }
        xh32[r*260 + i] = pv;
    }
    __syncthreads();

    float d[2][4];
    #pragma unroll
    for (int j = 0; j < 2; j++){ d[j][0]=0.f; d[j][1]=0.f; d[j][2]=0.f; d[j][3]=0.f; }

    const uint2* wf = (const uint2*)g_whfrag;
    #pragma unroll 4
    for (int ktg = 0; ktg < NKT; ktg++){
        int k = ktg*16;
        int kk = k >> 9, e2 = (k & 511) >> 1;
        const uint32_t* r0 = xh32 + (g + kk)*260 + e2 + c;
        const uint32_t* r1 = xh32 + (g + 8 + kk)*260 + e2 + c;
        uint32_t a0 = r0[0], a1 = r1[0], a2 = r0[4], a3 = r1[4];
        const uint2* wk = wf + (ktg*32 + cy*16 + w*2)*32 + t;
        #pragma unroll
        for (int j = 0; j < 2; j++){
            uint2 bb = __ldg(wk + j*32);
            mma_f16(d[j][0], d[j][1], d[j][2], d[j][3], a0, a1, a2, a3, bb.x, bb.y);
        }
    }

    float s[2][2], sq[2][2];
    #pragma unroll
    for (int j = 0; j < 2; j++){ s[j][0]=0.f; s[j][1]=0.f; sq[j][0]=0.f; sq[j][1]=0.f; }
    #pragma unroll
    for (int j = 0; j < 2; j++){
        int n = cy*128 + w*16 + j*8 + 2*c;
        float bx = conv_b[n], by = conv_b[n+1];
        float y0 = lrelu(d[j][0] + bx);
        float y1 = lrelu(d[j][1] + by);
        float y2 = lrelu(d[j][2] + bx);
        float y3 = lrelu(d[j][3] + by);
        int trow = (b*LL + l0 + g)*CC;
        g_y[trow + n]            = y0;
        g_y[trow + n + 1]        = y1;
        g_y[trow + 8*CC + n]     = y2;
        g_y[trow + 8*CC + n + 1] = y3;
        s[j][0]  += y0 + y2;         s[j][1]  += y1 + y3;
        sq[j][0] += y0*y0 + y2*y2;   sq[j][1] += y1*y1 + y3*y3;
    }
    #pragma unroll
    for (int j = 0; j < 2; j++)
        #pragma unroll
        for (int r = 0; r < 2; r++){
            #pragma unroll
            for (int m = 4; m < 32; m <<= 1){
                s[j][r]  += __shfl_xor_sync(0xffffffffu, s[j][r],  m);
                sq[j][r] += __shfl_xor_sync(0xffffffffu, sq[j][r], m);
            }
        }
    if (t < 4){
        int blk = (b*10 + blockIdx.x)*2 + cy;
        #pragma unroll
        for (int j = 0; j < 2; j++){
            int off = w*16 + j*8 + 2*c;
            g_ssum[blk*128 + off]     = s[j][0];
            g_ssum[blk*128 + off + 1] = s[j][1];
            g_ssq[blk*128 + off]      = sq[j][0];
            g_ssq[blk*128 + off + 1]  = sq[j][1];
        }
    }
}

/* ------- 3. BN finalize (frozen) ------- */
__global__ void k_stats_fin(const float* __restrict__ bn_g, const float* __restrict__ bn_b){
    __shared__ float sa[256], sqv[256];
    int j = blockIdx.x, tid = threadIdx.x;
    int ch = j*32 + (tid & 31), rg = tid >> 5;
    int half = ch >> 7, cl = ch & 127;
    float a = 0.f, q = 0.f;
    #pragma unroll 4
    for (int r = rg*20; r < rg*20 + 20; r++){
        a += g_ssum[(r*2 + half)*128 + cl];
        q += g_ssq[(r*2 + half)*128 + cl];
    }
    sa[tid] = a; sqv[tid] = q;
    __syncthreads();
    if (tid < 32){
        float A = 0.f, Q = 0.f;
        #pragma unroll
        for (int r = 0; r < 8; r++){ A += sa[r*32 + tid]; Q += sqv[r*32 + tid]; }
        float mu = A/(float)TOK;
        float var = Q/(float)TOK - mu*mu;
        float sc = bn_g[ch]*rsqrtf(var + 1e-5f);
        g_scale[ch] = sc;
        g_shift[ch] = bn_b[ch] - mu*sc;
    }
}

/* ------- 4. uv projection: n-split x2 (16 tok x 128 out per block) ------- */
__global__ void __launch_bounds__(256) k_uv(){
    __shared__ uint32_t xh2[16*140];
    int tid = threadIdx.x, w = tid >> 5, t = tid & 31;
    int g = t >> 2, c = t & 3;
    int t0 = blockIdx.x*16;
    int cy = blockIdx.y;               /* 0 = u half, 1 = v half */
    int b = t0 / LL;
    float sL = sqrtf(160.f);

    for (int idx = tid; idx < 16*136; idx += 256){
        int tok = idx/136, kk2 = idx - tok*136;
        int k0 = 2*kk2;
        float v0, v1;
        if (k0 < CC){
            int row = (t0+tok)*CC;
            v0 = g_y[row + k0]*g_scale[k0] + g_shift[k0];
            v1 = g_y[row + k0 + 1]*g_scale[k0 + 1] + g_shift[k0 + 1];
        } else if (k0 == 256){
            float fi = (float)(t0 + tok - b*LL);
            v0 = (fi/sL - 2.f)*0.5f;
            v1 = (fmodf(fi, sL) - 2.f)*0.5f;
        } else { v0 = 0.f; v1 = 0.f; }
        xh2[tok*140 + kk2] = h2pack(v0, v1);
    }
    __syncthreads();

    float d[2][4];
    #pragma unroll
    for (int j = 0; j < 2; j++){ d[j][0]=0.f; d[j][1]=0.f; d[j][2]=0.f; d[j][3]=0.f; }

    #pragma unroll
    for (int kt = 0; kt < UVKT; kt++){
        const uint32_t* r0 = xh2 + g*140 + kt*8 + c;
        const uint32_t* r1 = xh2 + (g+8)*140 + kt*8 + c;
        uint32_t a0 = r0[0], a1 = r1[0], a2 = r0[4], a3 = r1[4];
        const uint2* wk = g_w1frag + (kt*32 + cy*16 + w*2)*32 + t;
        #pragma unroll
        for (int j = 0; j < 2; j++){
            uint2 bb = __ldg(wk + j*32);
            mma_f16(d[j][0], d[j][1], d[j][2], d[j][3], a0, a1, a2, a3, bb.x, bb.y);
        }
    }

    #pragma unroll
    for (int j = 0; j < 2; j++){
        int nl = w*16 + j*8 + 2*c;            /* local output index 0..127 */
        int q = nl >> 1;
        if (cy == 0){
            g_uh[(t0 + g)*64 + q]     = h2pack(d[j][0], d[j][1]);
            g_uh[(t0 + g + 8)*64 + q] = h2pack(d[j][2], d[j][3]);
        } else {
            float hw0 = g_hw[b*DM + nl];
            float hw1 = g_hw[b*DM + nl + 1];
            g_vh[(t0 + g)*64 + q]     = h2pack(d[j][0] + hw0, d[j][1] + hw1);
            g_vh[(t0 + g + 8)*64 + q] = h2pack(d[j][2] + hw0, d[j][3] + hw1);
        }
    }
}

/* ------- 5. pair MLP (frozen from R15, incl. register prefetch) ------- */
#define OFF_WF   0
#define OFF_U2   24576
#define OFF_V2   (OFF_U2 + 16*68)
#define OFF_B12  (OFF_V2 + 16*68)
#define OFF_BI2  (OFF_B12 + 64)
#define OFF_BIF  (OFF_BI2 + 128)
#define SM_TOTU  (OFF_BIF + 128)
#define DYN_SMEM (SM_TOTU*4)

__global__ void __launch_bounds__(256,1) k_pairs_mma(
        const float* __restrict__ W2, const float* __restrict__ W3, const float* __restrict__ W4,
        const float* __restrict__ b1, const float* __restrict__ b2,
        const float* __restrict__ b3, const float* __restrict__ b4){
    extern __shared__ uint32_t smu[];
    uint2*    wfrag   = (uint2*)smu;
    uint32_t* u2_s    = smu + OFF_U2;
    uint32_t* v2_s    = smu + OFF_V2;
    uint32_t* b12_s   = smu + OFF_B12;
    uint32_t* bias2_s = smu + OFF_BI2;
    float*    biasf_s = (float*)(smu + OFF_BIF);
    float*    part_s  = (float*)(smu + OFF_U2);

    int tid = threadIdx.x, w = tid >> 5, t = tid & 31;
    int g = t >> 2, c = t & 3;

    for (int l = 0; l < 3; l++){
        const float* W = (l == 0) ? W2 : (l == 1) ? W3 : W4;
        for (int idx = tid; idx < 4096; idx += 256){
            int lane = idx & 31, nt = (idx >> 5) & 15, kt = idx >> 9;
            int gg = lane >> 2, cc = lane & 3;
            const float* Wr = W + (nt*8 + gg)*DM + kt*16 + 2*cc;
            uint2 fr;
            fr.x = h2pack(Wr[0], Wr[1]);
            fr.y = h2pack(Wr[8], Wr[9]);
            int h = nt >> 3, ntp = (nt >> 1) & 3, e = nt & 1;
            wfrag[l*4096 + ((kt*2 + h)*4 + ntp)*64 + lane*2 + e] = fr;
        }
    }
    if (tid < 64){
        b12_s[tid]        = h2pack(b1[2*tid], b1[2*tid+1]);
        bias2_s[tid]      = h2pack(b2[2*tid], b2[2*tid+1]);
        bias2_s[64 + tid] = h2pack(b3[2*tid], b3[2*tid+1]);
    }
    if (tid < 128) biasf_s[tid] = b4[tid];

    int cta = blockIdx.x;
    int b = cta / SPB, s = cta % SPB;
    int t0 = s*11 + (s > 0 ? 1 : 0);
    int t1 = t0 + 11 + (s == 0 ? 1 : 0);

    int pmi[4], pp[4];
    #pragma unroll
    for (int q = 0; q < 4; q++){
        int idx = tid + 256*q;
        pmi[q] = idx >> 6;
        pp[q]  = idx & 63;
    }
    uint32_t pu[4], pv[4];
    {
        int lt0 = (t0 / 10)*16, m0 = (t0 % 10)*16;
        #pragma unroll
        for (int q = 0; q < 4; q++){
            pu[q] = g_uh[(b*LL + m0 + pmi[q])*64 + pp[q]];
            pv[q] = g_vh[(b*LL + lt0 + pmi[q])*64 + pp[q]];
        }
    }

    uint32_t a[2][8][4];
    uint32_t an[2][4][4];
    float    d[2][8][4];
    float    acc32[16][2];
    #pragma unroll
    for (int nt = 0; nt < 16; nt++){ acc32[nt][0] = 0.f; acc32[nt][1] = 0.f; }

    for (int tt = t0; tt < t1; tt++){
        __syncthreads();
        #pragma unroll
        for (int q = 0; q < 4; q++){
            u2_s[pmi[q]*68 + pp[q]] = pu[q];
            v2_s[pmi[q]*68 + pp[q]] = pv[q];
        }
        __syncthreads();
        if (tt + 1 < t1){
            int ltn = ((tt+1) / 10)*16, mn = ((tt+1) % 10)*16;
            #pragma unroll
            for (int q = 0; q < 4; q++){
                pu[q] = g_uh[(b*LL + mn + pmi[q])*64 + pp[q]];
                pv[q] = g_vh[(b*LL + ltn + pmi[q])*64 + pp[q]];
            }
        }

        #pragma unroll
        for (int kt = 0; kt < 8; kt++){
            int i0 = kt*8 + c;
            uint32_t bh0 = b12_s[i0], bh8 = b12_s[i0 + 4];
            #pragma unroll
            for (int f = 0; f < 2; f++){
                const uint32_t* vrow = v2_s + (w + 8*f)*68;
                uint32_t vb0 = hadd2_(vrow[i0], bh0);
                uint32_t vb8 = hadd2_(vrow[i0 + 4], bh8);
                a[f][kt][0] = lrelu2_(hadd2_(u2_s[g*68 + i0], vb0));
                a[f][kt][1] = lrelu2_(hadd2_(u2_s[(g+8)*68 + i0], vb0));
                a[f][kt][2] = lrelu2_(hadd2_(u2_s[g*68 + i0 + 4], vb8));
                a[f][kt][3] = lrelu2_(hadd2_(u2_s[(g+8)*68 + i0 + 4], vb8));
            }
        }

        #pragma unroll 1
        for (int l = 0; l < 3; l++){
            const uint4* wl4 = (const uint4*)wfrag + l*2048;
            #pragma unroll
            for (int h = 0; h < 2; h++){
                #pragma unroll
                for (int ntl = 0; ntl < 8; ntl++){
                    d[0][ntl][0]=0.f; d[0][ntl][1]=0.f; d[0][ntl][2]=0.f; d[0][ntl][3]=0.f;
                    d[1][ntl][0]=0.f; d[1][ntl][1]=0.f; d[1][ntl][2]=0.f; d[1][ntl][3]=0.f;
                }
                const uint4* wh = wl4 + h*128 + t;
                #pragma unroll
                for (int kt = 0; kt < 8; kt++){
                    const uint4* wk = wh + kt*256;
                    #pragma unroll
                    for (int ntp = 0; ntp < 4; ntp++){
                        uint4 bb = wk[ntp*32];
                        mma_f16(d[0][2*ntp][0], d[0][2*ntp][1], d[0][2*ntp][2], d[0][2*ntp][3],
                                a[0][kt][0], a[0][kt][1], a[0][kt][2], a[0][kt][3], bb.x, bb.y);
                        mma_f16(d[1][2*ntp][0], d[1][2*ntp][1], d[1][2*ntp][2], d[1][2*ntp][3],
                                a[1][kt][0], a[1][kt][1], a[1][kt][2], a[1][kt][3], bb.x, bb.y);
                        mma_f16(d[0][2*ntp+1][0], d[0][2*ntp+1][1], d[0][2*ntp+1][2], d[0][2*ntp+1][3],
                                a[0][kt][0], a[0][kt][1], a[0][kt][2], a[0][kt][3], bb.z, bb.w);
                        mma_f16(d[1][2*ntp+1][0], d[1][2*ntp+1][1], d[1][2*ntp+1][2], d[1][2*ntp+1][3],
                                a[1][kt][0], a[1][kt][1], a[1][kt][2], a[1][kt][3], bb.z, bb.w);
                    }
                }
                if (l < 2){
                    const uint32_t* bl2 = bias2_s + l*64;
                    #pragma unroll
                    for (int f = 0; f < 2; f++){
                        #pragma unroll
                        for (int ktl = 0; ktl < 4; ktl++){
                            int i0g = (h*4 + ktl)*8 + c;
                            uint32_t bb0 = bl2[i0g], bb8 = bl2[i0g + 4];
                            uint32_t u0 = lrelu2_(hadd2_(h2pack(d[f][2*ktl][0],   d[f][2*ktl][1]),   bb0));
                            uint32_t u1 = lrelu2_(hadd2_(h2pack(d[f][2*ktl][2],   d[f][2*ktl][3]),   bb0));
                            uint32_t u2 = lrelu2_(hadd2_(h2pack(d[f][2*ktl+1][0], d[f][2*ktl+1][1]), bb8));
                            uint32_t u3 = lrelu2_(hadd2_(h2pack(d[f][2*ktl+1][2], d[f][2*ktl+1][3]), bb8));
                            if (h == 0){
                                an[f][ktl][0]=u0; an[f][ktl][1]=u1; an[f][ktl][2]=u2; an[f][ktl][3]=u3;
                            } else {
                                a[f][4+ktl][0]=u0; a[f][4+ktl][1]=u1; a[f][4+ktl][2]=u2; a[f][4+ktl][3]=u3;
                            }
                        }
                    }
                    if (h == 1){
                        #pragma unroll
                        for (int f = 0; f < 2; f++)
                            #pragma unroll
                            for (int ktl = 0; ktl < 4; ktl++){
                                a[f][ktl][0]=an[f][ktl][0]; a[f][ktl][1]=an[f][ktl][1];
                                a[f][ktl][2]=an[f][ktl][2]; a[f][ktl][3]=an[f][ktl][3];
                            }
                    }
                } else {
                    const float* bl = biasf_s + h*64;
                    #pragma unroll
                    for (int ntl = 0; ntl < 8; ntl++){
                        int nt = 8*h + ntl;
                        float bx = bl[ntl*8 + 2*c], by = bl[ntl*8 + 2*c + 1];
                        acc32[nt][0] += lrelu(d[0][ntl][0] + bx) + lrelu(d[0][ntl][2] + bx)
                                      + lrelu(d[1][ntl][0] + bx) + lrelu(d[1][ntl][2] + bx);
                        acc32[nt][1] += lrelu(d[0][ntl][1] + by) + lrelu(d[0][ntl][3] + by)
                                      + lrelu(d[1][ntl][1] + by) + lrelu(d[1][ntl][3] + by);
                    }
                }
            }
        }
    }

    __syncthreads();

    #pragma unroll
    for (int nt = 0; nt < 16; nt++){
        #pragma unroll
        for (int r = 0; r < 2; r++){
            float v = acc32[nt][r];
            v += __shfl_xor_sync(0xffffffffu, v, 4);
            v += __shfl_xor_sync(0xffffffffu, v, 8);
            v += __shfl_xor_sync(0xffffffffu, v, 16);
            acc32[nt][r] = v;
        }
    }
    if (g == 0){
        #pragma unroll
        for (int nt = 0; nt < 16; nt++){
            part_s[w*128 + nt*8 + 2*c]     = acc32[nt][0];
            part_s[w*128 + nt*8 + 2*c + 1] = acc32[nt][1];
        }
    }
    __syncthreads();
    if (tid < 128){
        float r = 0.f;
        #pragma unroll
        for (int ww = 0; ww < 8; ww++) r += part_s[ww*128 + tid];
        g_part[(b*SPB + s)*DM + tid] = r;
    }
}

/* ------- 6. final reduction + 2-layer head (frozen) ------- */
__global__ void k_tail(const float* __restrict__ W5, const float* __restrict__ b5,
                       const float* __restrict__ W6, const float* __restrict__ b6,
                       float* __restrict__ out){
    __shared__ float s_s[DM], s5[DM];
    int b = blockIdx.x, tid = threadIdx.x;
    if (tid < DM){
        float a = 0.f;
        #pragma unroll
        for (int t = 0; t < SPB; t++) a += g_part[(b*SPB + t)*DM + tid];
        s_s[tid] = a;
    }
    __syncthreads();
    if (tid < DM){
        float a = 0.f;
        const float* w = W5 + tid*DM;
        #pragma unroll 8
        for (int k = 0; k < DM; k++) a += s_s[k]*w[k];
        s5[tid] = lrelu(a + b5[tid]);
    }
    __syncthreads();
    {
        float a = 0.f;
        const float* w = W6 + tid*DM;
        #pragma unroll 8
        for (int k = 0; k < DM; k++) a += s5[k]*w[k];
        out[b*DO + tid] = lrelu(a + b6[tid]);
    }
}

extern "C" void kernel_launch(void* const* d_in, const int* in_sizes, int n_in,
                              void* d_out, int out_size){
    const float* x      = (const float*)d_in[0];
    const float* h      = (const float*)d_in[1];
    const float* conv_w = (const float*)d_in[2];
    const float* conv_b = (const float*)d_in[3];
    const float* bn_g   = (const float*)d_in[4];
    const float* bn_b   = (const float*)d_in[5];
    const float* W1     = (const float*)d_in[6];
    const float* b1     = (const float*)d_in[7];
    const float* W2     = (const float*)d_in[8];
    const float* b2     = (const float*)d_in[9];
    const float* W3     = (const float*)d_in[10];
    const float* b3     = (const float*)d_in[11];
    const float* W4     = (const float*)d_in[12];
    const float* b4     = (const float*)d_in[13];
    const float* W5     = (const float*)d_in[14];
    const float* b5     = (const float*)d_in[15];
    const float* W6     = (const float*)d_in[16];
    const float* b6     = (const float*)d_in[17];
    float* out = (float*)d_out;

    cudaFuncSetAttribute(k_pairs_mma, cudaFuncAttributeMaxDynamicSharedMemorySize, DYN_SMEM);

    k_prep<<<256, 256>>>(conv_w, W1, h);                            /* 1 */
    k_conv<<<dim3(10, 2, BB), 256>>>(x, conv_b);                    /* 2 */
    k_stats_fin<<<8, 256>>>(bn_g, bn_b);                            /* 3 */
    k_uv<<<dim3(TOK/16, 2), 256>>>();                               /* 4: profiled */
    k_pairs_mma<<<GRID_PAIRS, 256, DYN_SMEM>>>(W2, W3, W4, b1, b2, b3, b4);  /* 5 */
    k_tail<<<BB, 512>>>(W5, b5, W6, b6, out);                       /* 6 */
}

// round 17
// speedup vs baseline: 1.3774x; 1.0101x over previous
#include <cuda_runtime.h>
#include <cuda_fp16.h>
#include <math.h>
#include <stdint.h>

#define LL 160
#define BB 16
#define EE 512
#define CC 256
#define HH 512
#define DM 128
#define DO 512
#define TOK (BB*LL)
#define CP 258
#define W1C 1028
#define KC (3*EE)            /* 1536 */
#define SPB 9
#define GRID_PAIRS (BB*SPB)  /* 144 */
#define NKT (KC/16)          /* 96 */
#define UVKT 17

__device__ __half   g_whfrag[NKT*32*32*4];
__device__ uint2    g_w1frag[UVKT*32*32];
__device__ float    g_y[TOK*CC];
__device__ float    g_ssum[160*128];
__device__ float    g_ssq[160*128];
__device__ float    g_scale[CC];
__device__ float    g_shift[CC];
__device__ uint32_t g_uh[TOK*64];
__device__ uint32_t g_vh[TOK*64];
__device__ float    g_hw[BB*DM];
__device__ float    g_part[BB*SPB*DM];

__device__ __forceinline__ float lrelu(float x){ return fmaxf(x, 0.1f*x); }

__device__ __forceinline__ uint32_t h2pack(float lo, float hi){
    __half2 h = __floats2half2_rn(lo, hi);
    return *(uint32_t*)&h;
}
__device__ __forceinline__ uint32_t hadd2_(uint32_t a, uint32_t b){
    uint32_t d; asm("add.f16x2 %0,%1,%2;" : "=r"(d) : "r"(a), "r"(b)); return d;
}
__device__ __forceinline__ uint32_t lrelu2_(uint32_t x){
    uint32_t t, d;
    asm("mul.f16x2 %0,%1,%2;" : "=r"(t) : "r"(x), "r"(0x2E662E66u));
    asm("max.f16x2 %0,%1,%2;" : "=r"(d) : "r"(x), "r"(t));
    return d;
}
__device__ __forceinline__ void mma_f16(float& d0, float& d1, float& d2, float& d3,
                                        uint32_t a0, uint32_t a1, uint32_t a2, uint32_t a3,
                                        uint32_t b0, uint32_t b1){
    asm volatile("mma.sync.aligned.m16n8k16.row.col.f32.f16.f16.f32 "
                 "{%0,%1,%2,%3},{%4,%5,%6,%7},{%8,%9},{%0,%1,%2,%3};"
                 : "+f"(d0), "+f"(d1), "+f"(d2), "+f"(d3)
                 : "r"(a0), "r"(a1), "r"(a2), "r"(a3), "r"(b0), "r"(b1));
}
__device__ __forceinline__ void mma_h16(uint32_t& d0, uint32_t& d1,
                                        uint32_t a0, uint32_t a1, uint32_t a2, uint32_t a3,
                                        uint32_t b0, uint32_t b1){
    asm volatile("mma.sync.aligned.m16n8k16.row.col.f16.f16.f16.f16 "
                 "{%0,%1},{%2,%3,%4,%5},{%6,%7},{%0,%1};"
                 : "+r"(d0), "+r"(d1)
                 : "r"(a0), "r"(a1), "r"(a2), "r"(a3), "r"(b0), "r"(b1));
}

/* ------- 1. prep (frozen) ------- */
__global__ void k_prep(const float* __restrict__ conv_w, const float* __restrict__ W1,
                       const float* __restrict__ h){
    __shared__ float hs[HH];
    __shared__ float hp[256];
    int n = blockIdx.x, tid = threadIdx.x;
    int nt = n >> 3, gg = n & 7;

    const float* cw = conv_w + n*KC;
    uint2* wf2 = (uint2*)g_whfrag;
    for (int it = tid; it < NKT*4; it += 256){
        int kt = it >> 2, c = it & 3;
        int k0 = kt*16 + 2*c;
        int k1 = k0 + 1, k2 = k0 + 8, k3 = k0 + 9;
        float f0 = cw[(k0 & 511)*3 + (k0 >> 9)];
        float f1 = cw[(k1 & 511)*3 + (k1 >> 9)];
        float f2 = cw[(k2 & 511)*3 + (k2 >> 9)];
        float f3 = cw[(k3 & 511)*3 + (k3 >> 9)];
        uint2 fr;
        fr.x = h2pack(f0, f1);
        fr.y = h2pack(f2, f3);
        wf2[(kt*32 + nt)*32 + gg*4 + c] = fr;
    }

    const float* wr = (n < DM) ? (W1 + n*W1C) : (W1 + (n-DM)*W1C + CP);
    if (tid < UVKT*4){
        int kt = tid >> 2, cc = tid & 3;
        int k0 = kt*16 + 2*cc;
        float v0 = (k0   < CP) ? wr[k0]   : 0.f;
        float v1 = (k0+1 < CP) ? wr[k0+1] : 0.f;
        float v8 = (k0+8 < CP) ? wr[k0+8] : 0.f;
        float v9 = (k0+9 < CP) ? wr[k0+9] : 0.f;
        uint2 fr;
        fr.x = h2pack(v0, v1);
        fr.y = h2pack(v8, v9);
        g_w1frag[kt*1024 + nt*32 + gg*4 + cc] = fr;
    }

    if (n < BB){
        for (int i = tid; i < HH; i += 256) hs[i] = h[n*HH + i];
        __syncthreads();
        int d = tid & 127, half = tid >> 7;
        const float* w = W1 + d*W1C + 2*CP + half*256;
        float acc = 0.f;
        #pragma unroll 8
        for (int c = 0; c < 256; c++) acc += hs[half*256 + c]*w[c];
        hp[tid] = acc;
        __syncthreads();
        if (tid < 128) g_hw[n*DM + tid] = hp[tid] + hp[tid + 128];
    }
}

/* ------- 2. conv1d fp16 mma: M=32 tokens, n-split x2 (grid 5x2x16) ------- */
__global__ void __launch_bounds__(256) k_conv(const float* __restrict__ x,
                                              const float* __restrict__ conv_b){
    __shared__ uint32_t xh32[34*260];
    int l0 = blockIdx.x*32, cy = blockIdx.y, b = blockIdx.z;
    int tid = threadIdx.x, w = tid >> 5, t = tid & 31;
    int g = t >> 2, c = t & 3;

    for (int idx = tid; idx < 34*256; idx += 256){
        int r = idx >> 8, i = idx & 255;
        int l = l0 + r - 1;
        uint32_t pv = 0u;
        if (l >= 0 && l < LL){
            const float2 xv = *(const float2*)(x + (l*BB + b)*EE + 2*i);
            pv = h2pack(xv.x, xv.y);
        }
        xh32[r*260 + i] = pv;
    }
    __syncthreads();

    float d[2][2][4];
    #pragma unroll
    for (int mt = 0; mt < 2; mt++)
        #pragma unroll
        for (int j = 0; j < 2; j++){
            d[mt][j][0]=0.f; d[mt][j][1]=0.f; d[mt][j][2]=0.f; d[mt][j][3]=0.f;
        }

    const uint2* wf = (const uint2*)g_whfrag;
    #pragma unroll 4
    for (int ktg = 0; ktg < NKT; ktg++){
        int k = ktg*16;
        int kk = k >> 9, e2 = (k & 511) >> 1;
        uint32_t am[2][4];
        #pragma unroll
        for (int mt = 0; mt < 2; mt++){
            const uint32_t* r0 = xh32 + (mt*16 + g + kk)*260 + e2 + c;
            const uint32_t* r1 = xh32 + (mt*16 + g + 8 + kk)*260 + e2 + c;
            am[mt][0] = r0[0]; am[mt][1] = r1[0]; am[mt][2] = r0[4]; am[mt][3] = r1[4];
        }
        const uint2* wk = wf + (ktg*32 + cy*16 + w*2)*32 + t;
        #pragma unroll
        for (int j = 0; j < 2; j++){
            uint2 bb = __ldg(wk + j*32);
            mma_f16(d[0][j][0], d[0][j][1], d[0][j][2], d[0][j][3],
                    am[0][0], am[0][1], am[0][2], am[0][3], bb.x, bb.y);
            mma_f16(d[1][j][0], d[1][j][1], d[1][j][2], d[1][j][3],
                    am[1][0], am[1][1], am[1][2], am[1][3], bb.x, bb.y);
        }
    }

    float s[2][2], sq[2][2];
    #pragma unroll
    for (int j = 0; j < 2; j++){ s[j][0]=0.f; s[j][1]=0.f; sq[j][0]=0.f; sq[j][1]=0.f; }
    #pragma unroll
    for (int mt = 0; mt < 2; mt++){
        #pragma unroll
        for (int j = 0; j < 2; j++){
            int n = cy*128 + w*16 + j*8 + 2*c;
            float bx = conv_b[n], by = conv_b[n+1];
            float y0 = lrelu(d[mt][j][0] + bx);
            float y1 = lrelu(d[mt][j][1] + by);
            float y2 = lrelu(d[mt][j][2] + bx);
            float y3 = lrelu(d[mt][j][3] + by);
            int trow = (b*LL + l0 + mt*16 + g)*CC;
            g_y[trow + n]            = y0;
            g_y[trow + n + 1]        = y1;
            g_y[trow + 8*CC + n]     = y2;
            g_y[trow + 8*CC + n + 1] = y3;
            s[j][0]  += y0 + y2;         s[j][1]  += y1 + y3;
            sq[j][0] += y0*y0 + y2*y2;   sq[j][1] += y1*y1 + y3*y3;
        }
    }
    #pragma unroll
    for (int j = 0; j < 2; j++)
        #pragma unroll
        for (int r = 0; r < 2; r++){
            #pragma unroll
            for (int m = 4; m < 32; m <<= 1){
                s[j][r]  += __shfl_xor_sync(0xffffffffu, s[j][r],  m);
                sq[j][r] += __shfl_xor_sync(0xffffffffu, sq[j][r], m);
            }
        }
    if (t < 4){
        int blk = (b*5 + blockIdx.x)*2 + cy;     /* 160 rows of 128 */
        #pragma unroll
        for (int j = 0; j < 2; j++){
            int off = w*16 + j*8 + 2*c;
            g_ssum[blk*128 + off]     = s[j][0];
            g_ssum[blk*128 + off + 1] = s[j][1];
            g_ssq[blk*128 + off]      = sq[j][0];
            g_ssq[blk*128 + off + 1]  = sq[j][1];
        }
    }
}

/* ------- 3. BN finalize ([160][128] partials) ------- */
__global__ void k_stats_fin(const float* __restrict__ bn_g, const float* __restrict__ bn_b){
    __shared__ float sa[256], sqv[256];
    int j = blockIdx.x, tid = threadIdx.x;
    int ch = j*32 + (tid & 31), rg = tid >> 5;
    int half = ch >> 7, cl = ch & 127;
    float a = 0.f, q = 0.f;
    #pragma unroll 2
    for (int r = rg*10; r < rg*10 + 10; r++){
        a += g_ssum[(r*2 + half)*128 + cl];
        q += g_ssq[(r*2 + half)*128 + cl];
    }
    sa[tid] = a; sqv[tid] = q;
    __syncthreads();
    if (tid < 32){
        float A = 0.f, Q = 0.f;
        #pragma unroll
        for (int r = 0; r < 8; r++){ A += sa[r*32 + tid]; Q += sqv[r*32 + tid]; }
        float mu = A/(float)TOK;
        float var = Q/(float)TOK - mu*mu;
        float sc = bn_g[ch]*rsqrtf(var + 1e-5f);
        g_scale[ch] = sc;
        g_shift[ch] = bn_b[ch] - mu*sc;
    }
}

/* ------- 4. uv projection: n-split x2 (frozen from R16) ------- */
__global__ void __launch_bounds__(256) k_uv(){
    __shared__ uint32_t xh2[16*140];
    int tid = threadIdx.x, w = tid >> 5, t = tid & 31;
    int g = t >> 2, c = t & 3;
    int t0 = blockIdx.x*16;
    int cy = blockIdx.y;
    int b = t0 / LL;
    float sL = sqrtf(160.f);

    for (int idx = tid; idx < 16*136; idx += 256){
        int tok = idx/136, kk2 = idx - tok*136;
        int k0 = 2*kk2;
        float v0, v1;
        if (k0 < CC){
            int row = (t0+tok)*CC;
            v0 = g_y[row + k0]*g_scale[k0] + g_shift[k0];
            v1 = g_y[row + k0 + 1]*g_scale[k0 + 1] + g_shift[k0 + 1];
        } else if (k0 == 256){
            float fi = (float)(t0 + tok - b*LL);
            v0 = (fi/sL - 2.f)*0.5f;
            v1 = (fmodf(fi, sL) - 2.f)*0.5f;
        } else { v0 = 0.f; v1 = 0.f; }
        xh2[tok*140 + kk2] = h2pack(v0, v1);
    }
    __syncthreads();

    float d[2][4];
    #pragma unroll
    for (int j = 0; j < 2; j++){ d[j][0]=0.f; d[j][1]=0.f; d[j][2]=0.f; d[j][3]=0.f; }

    #pragma unroll
    for (int kt = 0; kt < UVKT; kt++){
        const uint32_t* r0 = xh2 + g*140 + kt*8 + c;
        const uint32_t* r1 = xh2 + (g+8)*140 + kt*8 + c;
        uint32_t a0 = r0[0], a1 = r1[0], a2 = r0[4], a3 = r1[4];
        const uint2* wk = g_w1frag + (kt*32 + cy*16 + w*2)*32 + t;
        #pragma unroll
        for (int j = 0; j < 2; j++){
            uint2 bb = __ldg(wk + j*32);
            mma_f16(d[j][0], d[j][1], d[j][2], d[j][3], a0, a1, a2, a3, bb.x, bb.y);
        }
    }

    #pragma unroll
    for (int j = 0; j < 2; j++){
        int nl = w*16 + j*8 + 2*c;
        int q = nl >> 1;
        if (cy == 0){
            g_uh[(t0 + g)*64 + q]     = h2pack(d[j][0], d[j][1]);
            g_uh[(t0 + g + 8)*64 + q] = h2pack(d[j][2], d[j][3]);
        } else {
            float hw0 = g_hw[b*DM + nl];
            float hw1 = g_hw[b*DM + nl + 1];
            g_vh[(t0 + g)*64 + q]     = h2pack(d[j][0] + hw0, d[j][1] + hw1);
            g_vh[(t0 + g + 8)*64 + q] = h2pack(d[j][2] + hw0, d[j][3] + hw1);
        }
    }
}

/* ------- 5. pair MLP: f16-acc mma for layers 0-1, fp32 acc final ------- */
#define OFF_WF   0
#define OFF_U2   24576
#define OFF_V2   (OFF_U2 + 16*68)
#define OFF_B12  (OFF_V2 + 16*68)
#define OFF_BI2  (OFF_B12 + 64)
#define OFF_BIF  (OFF_BI2 + 128)
#define SM_TOTU  (OFF_BIF + 128)
#define DYN_SMEM (SM_TOTU*4)

__global__ void __launch_bounds__(256,1) k_pairs_mma(
        const float* __restrict__ W2, const float* __restrict__ W3, const float* __restrict__ W4,
        const float* __restrict__ b1, const float* __restrict__ b2,
        const float* __restrict__ b3, const float* __restrict__ b4){
    extern __shared__ uint32_t smu[];
    uint2*    wfrag   = (uint2*)smu;
    uint32_t* u2_s    = smu + OFF_U2;
    uint32_t* v2_s    = smu + OFF_V2;
    uint32_t* b12_s   = smu + OFF_B12;
    uint32_t* bias2_s = smu + OFF_BI2;
    float*    biasf_s = (float*)(smu + OFF_BIF);
    float*    part_s  = (float*)(smu + OFF_U2);

    int tid = threadIdx.x, w = tid >> 5, t = tid & 31;
    int g = t >> 2, c = t & 3;

    for (int l = 0; l < 3; l++){
        const float* W = (l == 0) ? W2 : (l == 1) ? W3 : W4;
        for (int idx = tid; idx < 4096; idx += 256){
            int lane = idx & 31, nt = (idx >> 5) & 15, kt = idx >> 9;
            int gg = lane >> 2, cc = lane & 3;
            const float* Wr = W + (nt*8 + gg)*DM + kt*16 + 2*cc;
            uint2 fr;
            fr.x = h2pack(Wr[0], Wr[1]);
            fr.y = h2pack(Wr[8], Wr[9]);
            int h = nt >> 3, ntp = (nt >> 1) & 3, e = nt & 1;
            wfrag[l*4096 + ((kt*2 + h)*4 + ntp)*64 + lane*2 + e] = fr;
        }
    }
    if (tid < 64){
        b12_s[tid]        = h2pack(b1[2*tid], b1[2*tid+1]);
        bias2_s[tid]      = h2pack(b2[2*tid], b2[2*tid+1]);
        bias2_s[64 + tid] = h2pack(b3[2*tid], b3[2*tid+1]);
    }
    if (tid < 128) biasf_s[tid] = b4[tid];

    int cta = blockIdx.x;
    int b = cta / SPB, s = cta % SPB;
    int t0 = s*11 + (s > 0 ? 1 : 0);
    int t1 = t0 + 11 + (s == 0 ? 1 : 0);

    int pmi[4], pp[4];
    #pragma unroll
    for (int q = 0; q < 4; q++){
        int idx = tid + 256*q;
        pmi[q] = idx >> 6;
        pp[q]  = idx & 63;
    }
    uint32_t pu[4], pv[4];
    {
        int lt0 = (t0 / 10)*16, m0 = (t0 % 10)*16;
        #pragma unroll
        for (int q = 0; q < 4; q++){
            pu[q] = g_uh[(b*LL + m0 + pmi[q])*64 + pp[q]];
            pv[q] = g_vh[(b*LL + lt0 + pmi[q])*64 + pp[q]];
        }
    }

    uint32_t a[2][8][4];
    uint32_t an[2][4][4];
    float    acc32[16][2];
    #pragma unroll
    for (int nt = 0; nt < 16; nt++){ acc32[nt][0] = 0.f; acc32[nt][1] = 0.f; }

    for (int tt = t0; tt < t1; tt++){
        __syncthreads();
        #pragma unroll
        for (int q = 0; q < 4; q++){
            u2_s[pmi[q]*68 + pp[q]] = pu[q];
            v2_s[pmi[q]*68 + pp[q]] = pv[q];
        }
        __syncthreads();
        if (tt + 1 < t1){
            int ltn = ((tt+1) / 10)*16, mn = ((tt+1) % 10)*16;
            #pragma unroll
            for (int q = 0; q < 4; q++){
                pu[q] = g_uh[(b*LL + mn + pmi[q])*64 + pp[q]];
                pv[q] = g_vh[(b*LL + ltn + pmi[q])*64 + pp[q]];
            }
        }

        #pragma unroll
        for (int kt = 0; kt < 8; kt++){
            int i0 = kt*8 + c;
            uint32_t bh0 = b12_s[i0], bh8 = b12_s[i0 + 4];
            #pragma unroll
            for (int f = 0; f < 2; f++){
                const uint32_t* vrow = v2_s + (w + 8*f)*68;
                uint32_t vb0 = hadd2_(vrow[i0], bh0);
                uint32_t vb8 = hadd2_(vrow[i0 + 4], bh8);
                a[f][kt][0] = lrelu2_(hadd2_(u2_s[g*68 + i0], vb0));
                a[f][kt][1] = lrelu2_(hadd2_(u2_s[(g+8)*68 + i0], vb0));
                a[f][kt][2] = lrelu2_(hadd2_(u2_s[g*68 + i0 + 4], vb8));
                a[f][kt][3] = lrelu2_(hadd2_(u2_s[(g+8)*68 + i0 + 4], vb8));
            }
        }

        /* layers 0-1: fp16-accumulate mma; D is already next-layer A layout */
        #pragma unroll 1
        for (int l = 0; l < 2; l++){
            const uint4* wl4 = (const uint4*)wfrag + l*2048;
            #pragma unroll
            for (int h = 0; h < 2; h++){
                uint32_t d16[2][8][2];
                #pragma unroll
                for (int ntl = 0; ntl < 8; ntl++){
                    d16[0][ntl][0]=0u; d16[0][ntl][1]=0u;
                    d16[1][ntl][0]=0u; d16[1][ntl][1]=0u;
                }
                const uint4* wh = wl4 + h*128 + t;
                #pragma unroll
                for (int kt = 0; kt < 8; kt++){
                    const uint4* wk = wh + kt*256;
                    #pragma unroll
                    for (int ntp = 0; ntp < 4; ntp++){
                        uint4 bb = wk[ntp*32];
                        mma_h16(d16[0][2*ntp][0], d16[0][2*ntp][1],
                                a[0][kt][0], a[0][kt][1], a[0][kt][2], a[0][kt][3], bb.x, bb.y);
                        mma_h16(d16[1][2*ntp][0], d16[1][2*ntp][1],
                                a[1][kt][0], a[1][kt][1], a[1][kt][2], a[1][kt][3], bb.x, bb.y);
                        mma_h16(d16[0][2*ntp+1][0], d16[0][2*ntp+1][1],
                                a[0][kt][0], a[0][kt][1], a[0][kt][2], a[0][kt][3], bb.z, bb.w);
                        mma_h16(d16[1][2*ntp+1][0], d16[1][2*ntp+1][1],
                                a[1][kt][0], a[1][kt][1], a[1][kt][2], a[1][kt][3], bb.z, bb.w);
                    }
                }
                const uint32_t* bl2 = bias2_s + l*64;
                #pragma unroll
                for (int f = 0; f < 2; f++){
                    #pragma unroll
                    for (int ktl = 0; ktl < 4; ktl++){
                        int i0g = (h*4 + ktl)*8 + c;
                        uint32_t bb0 = bl2[i0g], bb8 = bl2[i0g + 4];
                        uint32_t u0 = lrelu2_(hadd2_(d16[f][2*ktl][0],   bb0));
                        uint32_t u1 = lrelu2_(hadd2_(d16[f][2*ktl][1],   bb0));
                        uint32_t u2 = lrelu2_(hadd2_(d16[f][2*ktl+1][0], bb8));
                        uint32_t u3 = lrelu2_(hadd2_(d16[f][2*ktl+1][1], bb8));
                        if (h == 0){
                            an[f][ktl][0]=u0; an[f][ktl][1]=u1; an[f][ktl][2]=u2; an[f][ktl][3]=u3;
                        } else {
                            a[f][4+ktl][0]=u0; a[f][4+ktl][1]=u1; a[f][4+ktl][2]=u2; a[f][4+ktl][3]=u3;
                        }
                    }
                }
                if (h == 1){
                    #pragma unroll
                    for (int f = 0; f < 2; f++)
                        #pragma unroll
                        for (int ktl = 0; ktl < 4; ktl++){
                            a[f][ktl][0]=an[f][ktl][0]; a[f][ktl][1]=an[f][ktl][1];
                            a[f][ktl][2]=an[f][ktl][2]; a[f][ktl][3]=an[f][ktl][3];
                        }
                }
            }
        }

        /* layer 2: fp32 accumulate, feeds the big sum */
        {
            const uint4* wl4 = (const uint4*)wfrag + 2*2048;
            #pragma unroll
            for (int h = 0; h < 2; h++){
                float d[2][8][4];
                #pragma unroll
                for (int ntl = 0; ntl < 8; ntl++){
                    d[0][ntl][0]=0.f; d[0][ntl][1]=0.f; d[0][ntl][2]=0.f; d[0][ntl][3]=0.f;
                    d[1][ntl][0]=0.f; d[1][ntl][1]=0.f; d[1][ntl][2]=0.f; d[1][ntl][3]=0.f;
                }
                const uint4* wh = wl4 + h*128 + t;
                #pragma unroll
                for (int kt = 0; kt < 8; kt++){
                    const uint4* wk = wh + kt*256;
                    #pragma unroll
                    for (int ntp = 0; ntp < 4; ntp++){
                        uint4 bb = wk[ntp*32];
                        mma_f16(d[0][2*ntp][0], d[0][2*ntp][1], d[0][2*ntp][2], d[0][2*ntp][3],
                                a[0][kt][0], a[0][kt][1], a[0][kt][2], a[0][kt][3], bb.x, bb.y);
                        mma_f16(d[1][2*ntp][0], d[1][2*ntp][1], d[1][2*ntp][2], d[1][2*ntp][3],
                                a[1][kt][0], a[1][kt][1], a[1][kt][2], a[1][kt][3], bb.x, bb.y);
                        mma_f16(d[0][2*ntp+1][0], d[0][2*ntp+1][1], d[0][2*ntp+1][2], d[0][2*ntp+1][3],
                                a[0][kt][0], a[0][kt][1], a[0][kt][2], a[0][kt][3], bb.z, bb.w);
                        mma_f16(d[1][2*ntp+1][0], d[1][2*ntp+1][1], d[1][2*ntp+1][2], d[1][2*ntp+1][3],
                                a[1][kt][0], a[1][kt][1], a[1][kt][2], a[1][kt][3], bb.z, bb.w);
                    }
                }
                const float* bl = biasf_s + h*64;
                #pragma unroll
                for (int ntl = 0; ntl < 8; ntl++){
                    int nt = 8*h + ntl;
                    float bx = bl[ntl*8 + 2*c], by = bl[ntl*8 + 2*c + 1];
                    acc32[nt][0] += lrelu(d[0][ntl][0] + bx) + lrelu(d[0][ntl][2] + bx)
                                  + lrelu(d[1][ntl][0] + bx) + lrelu(d[1][ntl][2] + bx);
                    acc32[nt][1] += lrelu(d[0][ntl][1] + by) + lrelu(d[0][ntl][3] + by)
                                  + lrelu(d[1][ntl][1] + by) + lrelu(d[1][ntl][3] + by);
                }
            }
        }
    }

    __syncthreads();

    #pragma unroll
    for (int nt = 0; nt < 16; nt++){
        #pragma unroll
        for (int r = 0; r < 2; r++){
            float v = acc32[nt][r];
            v += __shfl_xor_sync(0xffffffffu, v, 4);
            v += __shfl_xor_sync(0xffffffffu, v, 8);
            v += __shfl_xor_sync(0xffffffffu, v, 16);
            acc32[nt][r] = v;
        }
    }
    if (g == 0){
        #pragma unroll
        for (int nt = 0; nt < 16; nt++){
            part_s[w*128 + nt*8 + 2*c]     = acc32[nt][0];
            part_s[w*128 + nt*8 + 2*c + 1] = acc32[nt][1];
        }
    }
    __syncthreads();
    if (tid < 128){
        float r = 0.f;
        #pragma unroll
        for (int ww = 0; ww < 8; ww++) r += part_s[ww*128 + tid];
        g_part[(b*SPB + s)*DM + tid] = r;
    }
}

/* ------- 6. final reduction + 2-layer head (frozen) ------- */
__global__ void k_tail(const float* __restrict__ W5, const float* __restrict__ b5,
                       const float* __restrict__ W6, const float* __restrict__ b6,
                       float* __restrict__ out){
    __shared__ float s_s[DM], s5[DM];
    int b = blockIdx.x, tid = threadIdx.x;
    if (tid < DM){
        float a = 0.f;
        #pragma unroll
        for (int t = 0; t < SPB; t++) a += g_part[(b*SPB + t)*DM + tid];
        s_s[tid] = a;
    }
    __syncthreads();
    if (tid < DM){
        float a = 0.f;
        const float* w = W5 + tid*DM;
        #pragma unroll 8
        for (int k = 0; k < DM; k++) a += s_s[k]*w[k];
        s5[tid] = lrelu(a + b5[tid]);
    }
    __syncthreads();
    {
        float a = 0.f;
        const float* w = W6 + tid*DM;
        #pragma unroll 8
        for (int k = 0; k < DM; k++) a += s5[k]*w[k];
        out[b*DO + tid] = lrelu(a + b6[tid]);
    }
}

extern "C" void kernel_launch(void* const* d_in, const int* in_sizes, int n_in,
                              void* d_out, int out_size){
    const float* x      = (const float*)d_in[0];
    const float* h      = (const float*)d_in[1];
    const float* conv_w = (const float*)d_in[2];
    const float* conv_b = (const float*)d_in[3];
    const float* bn_g   = (const float*)d_in[4];
    const float* bn_b   = (const float*)d_in[5];
    const float* W1     = (const float*)d_in[6];
    const float* b1     = (const float*)d_in[7];
    const float* W2     = (const float*)d_in[8];
    const float* b2     = (const float*)d_in[9];
    const float* W3     = (const float*)d_in[10];
    const float* b3     = (const float*)d_in[11];
    const float* W4     = (const float*)d_in[12];
    const float* b4     = (const float*)d_in[13];
    const float* W5     = (const float*)d_in[14];
    const float* b5     = (const float*)d_in[15];
    const float* W6     = (const float*)d_in[16];
    const float* b6     = (const float*)d_in[17];
    float* out = (float*)d_out;

    cudaFuncSetAttribute(k_pairs_mma, cudaFuncAttributeMaxDynamicSharedMemorySize, DYN_SMEM);

    k_prep<<<256, 256>>>(conv_w, W1, h);                            /* 1 */
    k_conv<<<dim3(5, 2, BB), 256>>>(x, conv_b);                     /* 2 */
    k_stats_fin<<<8, 256>>>(bn_g, bn_b);                            /* 3 */
    k_uv<<<dim3(TOK/16, 2), 256>>>();                               /* 4: profiled */
    k_pairs_mma<<<GRID_PAIRS, 256, DYN_SMEM>>>(W2, W3, W4, b1, b2, b3, b4);  /* 5 */
    k_tail<<<BB, 512>>>(W5, b5, W6, b6, out);                       /* 6 */
}